// round 1
// baseline (speedup 1.0000x reference)
#include <cuda_runtime.h>
#include <math.h>

#define B_TOT   32768
#define OWN_DIM 3
#define N_INTR  32
#define INT_DIM 7
#define D       128
#define OBS_DIM 227
#define HID     256

#define R1      16      // rows per block, kernel 1
#define NC      8       // interactors per chunk
#define NCHUNK  (N_INTR / NC)
#define TILE    (R1 * NC)   // 128 GEMM rows per chunk
#define IE_STR  132

#define R2      64      // rows per block, kernel 2
#define X_STR   260

// ---- smem layout (floats), kernel 1 ----
#define OFF_W     0
#define OFF_IE    (D * D)                       // 16384
#define OFF_OBS   (OFF_IE + TILE * IE_STR)      // 33280
#define OFF_OWNE  (OFF_OBS + R1 * OBS_DIM)      // 36912
#define OFF_Q     (OFF_OWNE + R1 * D)           // 38960
#define OFF_CTX   (OFF_Q + R1 * D)              // 41008
#define OFF_SC    (OFF_CTX + R1 * D)            // 43056
#define OFF_AL    (OFF_SC + R1 * N_INTR)        // 43568
#define OFF_INTW  (OFF_AL + R1 * N_INTR)        // 44080
#define OFF_OWNW  (OFF_INTW + INT_DIM * D)      // 44976
#define OFF_INTB  (OFF_OWNW + OWN_DIM * D)      // 45360
#define OFF_VATT  (OFF_INTB + D)                // 45488
#define SMEM1_FLOATS (OFF_VATT + D)             // 45616 -> 182464 B

// ---- smem layout, kernel 2 ----
#define OFF_X2    0
#define OFF_W2    (R2 * X_STR)                  // 16640
#define SMEM2_FLOATS (OFF_W2 + 64 * HID)        // 33024 -> 132096 B

// scratch: x = [own_e | attn_vec], (B, 256) fp32
__device__ float g_x[(size_t)B_TOT * 256];

__device__ __forceinline__ float lrelu(float x) { return fmaxf(x, 0.2f * x); }

// =====================================================================
// Kernel 1: own_e, q, scores (k), softmax, ctx (v), attn_vec -> g_x
// =====================================================================
__global__ void __launch_bounds__(256, 1)
k_attn(const float* __restrict__ obs,
       const float* __restrict__ ownW, const float* __restrict__ ownB,
       const float* __restrict__ intW, const float* __restrict__ intB,
       const float* __restrict__ Wq,   const float* __restrict__ Wk,
       const float* __restrict__ Wv,   const float* __restrict__ vatt,
       const float* __restrict__ projW,const float* __restrict__ projB)
{
    extern __shared__ float sm[];
    float* sW    = sm + OFF_W;
    float* sIE   = sm + OFF_IE;
    float* sObs  = sm + OFF_OBS;
    float* sOwnE = sm + OFF_OWNE;
    float* sQ    = sm + OFF_Q;
    float* sCtx  = sm + OFF_CTX;
    float* sSc   = sm + OFF_SC;
    float* sAl   = sm + OFF_AL;
    float* sIntW = sm + OFF_INTW;
    float* sOwnW = sm + OFF_OWNW;
    float* sIntB = sm + OFF_INTB;
    float* sVatt = sm + OFF_VATT;

    const int tid = threadIdx.x;
    const int tx  = tid & 15;     // 16 column groups
    const int ty  = tid >> 4;     // 16 row groups
    const int b0  = blockIdx.x * R1;
    const float NEG_INF = __int_as_float(0xff800000u);

    // ---- stage obs tile + small weights; Wq into sW ----
    for (int i = tid; i < R1 * OBS_DIM; i += 256) sObs[i] = obs[(size_t)b0 * OBS_DIM + i];
    for (int i = tid; i < INT_DIM * D; i += 256)  sIntW[i] = intW[i];
    for (int i = tid; i < OWN_DIM * D; i += 256)  sOwnW[i] = ownW[i];
    if (tid < D) { sIntB[tid] = intB[tid]; sVatt[tid] = vatt[tid]; }
    for (int i = tid; i < D * D / 4; i += 256)
        ((float4*)sW)[i] = ((const float4*)Wq)[i];
    __syncthreads();

    // ---- own_e (also written to g_x[:,0:128]); zero ctx; pad mask -> score init ----
    for (int i = tid; i < R1 * D; i += 256) {
        int r = i >> 7, d = i & 127;
        const float* o = &sObs[r * OBS_DIM];
        float a = ownB[d] + o[0] * sOwnW[d] + o[1] * sOwnW[D + d] + o[2] * sOwnW[2 * D + d];
        a = lrelu(a);
        sOwnE[i] = a;
        g_x[(size_t)(b0 + r) * 256 + d] = a;
        sCtx[i] = 0.f;
    }
    for (int i = tid; i < R1 * N_INTR; i += 256) {
        int r = i >> 5, n = i & 31;
        const float* p = &sObs[r * OBS_DIM + OWN_DIM + n * INT_DIM];
        float s = 0.f;
        #pragma unroll
        for (int j = 0; j < INT_DIM; j++) s += fabsf(p[j]);
        sSc[i] = (s < 1e-6f) ? NEG_INF : 0.f;
    }
    __syncthreads();

    // ---- q = own_e @ Wq  (16 x 128, K = 128) ----
    {
        float a0[4] = {0.f,0.f,0.f,0.f}, a1[4] = {0.f,0.f,0.f,0.f};
        const float* ae = &sOwnE[ty * D];
        #pragma unroll 4
        for (int e = 0; e < D; e++) {
            float a = ae[e];
            float4 w0 = *(const float4*)&sW[e * D + 4 * tx];
            float4 w1 = *(const float4*)&sW[e * D + 64 + 4 * tx];
            a0[0] += a * w0.x; a0[1] += a * w0.y; a0[2] += a * w0.z; a0[3] += a * w0.w;
            a1[0] += a * w1.x; a1[1] += a * w1.y; a1[2] += a * w1.z; a1[3] += a * w1.w;
        }
        #pragma unroll
        for (int j = 0; j < 4; j++) {
            sQ[ty * D + 4 * tx + j]      = a0[j];
            sQ[ty * D + 64 + 4 * tx + j] = a1[j];
        }
    }
    __syncthreads();

    // ---- Wk into sW ----
    for (int i = tid; i < D * D / 4; i += 256)
        ((float4*)sW)[i] = ((const float4*)Wk)[i];
    __syncthreads();

    // ================= PASS 1: k -> scores =================
    for (int cc = 0; cc < NCHUNK; cc++) {
        // int_e chunk: rows (r, n = cc*NC + nn), 128 x 128
        for (int i = tid; i < TILE * D; i += 256) {
            int row = i >> 7, d = i & 127;
            int r = row >> 3, nn = row & 7;
            const float* p = &sObs[r * OBS_DIM + OWN_DIM + (cc * NC + nn) * INT_DIM];
            float acc = sIntB[d];
            #pragma unroll
            for (int j = 0; j < INT_DIM; j++) acc += p[j] * sIntW[j * D + d];
            sIE[row * IE_STR + d] = lrelu(acc);
        }
        __syncthreads();

        float acc[2][2][4][4];
        #pragma unroll
        for (int a = 0; a < 2; a++)
        #pragma unroll
        for (int b = 0; b < 2; b++)
        #pragma unroll
        for (int c = 0; c < 4; c++)
        #pragma unroll
        for (int d = 0; d < 4; d++) acc[a][b][c][d] = 0.f;

        const float* iA0 = &sIE[(4 * ty) * IE_STR];
        const float* iA1 = &sIE[(64 + 4 * ty) * IE_STR];
        #pragma unroll 4
        for (int e = 0; e < D; e++) {
            float a0[4], a1[4];
            #pragma unroll
            for (int i = 0; i < 4; i++) { a0[i] = iA0[i * IE_STR + e]; a1[i] = iA1[i * IE_STR + e]; }
            float4 w0 = *(const float4*)&sW[e * D + 4 * tx];
            float4 w1 = *(const float4*)&sW[e * D + 64 + 4 * tx];
            float wb0[4] = {w0.x, w0.y, w0.z, w0.w};
            float wb1[4] = {w1.x, w1.y, w1.z, w1.w};
            #pragma unroll
            for (int i = 0; i < 4; i++)
            #pragma unroll
            for (int j = 0; j < 4; j++) {
                acc[0][0][i][j] += a0[i] * wb0[j];
                acc[0][1][i][j] += a0[i] * wb1[j];
                acc[1][0][i][j] += a1[i] * wb0[j];
                acc[1][1][i][j] += a1[i] * wb1[j];
            }
        }

        // scores: sum_d tanh(q + k) * v_att
        #pragma unroll
        for (int rh = 0; rh < 2; rh++)
        #pragma unroll
        for (int i = 0; i < 4; i++) {
            int row = rh * 64 + 4 * ty + i;
            int r = row >> 3, nn = row & 7;
            const float* qr = &sQ[r * D];
            float s = 0.f;
            #pragma unroll
            for (int ch = 0; ch < 2; ch++)
            #pragma unroll
            for (int j = 0; j < 4; j++) {
                int col = ch * 64 + 4 * tx + j;
                s += tanhf(qr[col] + acc[rh][ch][i][j]) * sVatt[col];
            }
            atomicAdd(&sSc[r * N_INTR + cc * NC + nn], s);
        }
        __syncthreads();
    }

    // ---- softmax over 32 interactors per row (8 warps x 2 rows) ----
    {
        int w = tid >> 5, lane = tid & 31;
        for (int r = w; r < R1; r += 8) {
            float s = sSc[r * N_INTR + lane];
            float m = s;
            #pragma unroll
            for (int o = 16; o > 0; o >>= 1) m = fmaxf(m, __shfl_xor_sync(0xffffffffu, m, o));
            float e = (m == NEG_INF) ? 0.f : expf(s - m);
            float sum = e;
            #pragma unroll
            for (int o = 16; o > 0; o >>= 1) sum += __shfl_xor_sync(0xffffffffu, sum, o);
            sAl[r * N_INTR + lane] = (sum > 0.f) ? (e / sum) : 0.f;
        }
    }
    __syncthreads();

    // ---- Wv into sW ----
    for (int i = tid; i < D * D / 4; i += 256)
        ((float4*)sW)[i] = ((const float4*)Wv)[i];
    __syncthreads();

    // ================= PASS 2: v -> ctx =================
    float ctxa[2][2][4];
    #pragma unroll
    for (int a = 0; a < 2; a++)
    #pragma unroll
    for (int b = 0; b < 2; b++)
    #pragma unroll
    for (int c = 0; c < 4; c++) ctxa[a][b][c] = 0.f;

    for (int cc = 0; cc < NCHUNK; cc++) {
        for (int i = tid; i < TILE * D; i += 256) {
            int row = i >> 7, d = i & 127;
            int r = row >> 3, nn = row & 7;
            const float* p = &sObs[r * OBS_DIM + OWN_DIM + (cc * NC + nn) * INT_DIM];
            float acc = sIntB[d];
            #pragma unroll
            for (int j = 0; j < INT_DIM; j++) acc += p[j] * sIntW[j * D + d];
            sIE[row * IE_STR + d] = lrelu(acc);
        }
        __syncthreads();

        float acc[2][2][4][4];
        #pragma unroll
        for (int a = 0; a < 2; a++)
        #pragma unroll
        for (int b = 0; b < 2; b++)
        #pragma unroll
        for (int c = 0; c < 4; c++)
        #pragma unroll
        for (int d = 0; d < 4; d++) acc[a][b][c][d] = 0.f;

        const float* iA0 = &sIE[(4 * ty) * IE_STR];
        const float* iA1 = &sIE[(64 + 4 * ty) * IE_STR];
        #pragma unroll 4
        for (int e = 0; e < D; e++) {
            float a0[4], a1[4];
            #pragma unroll
            for (int i = 0; i < 4; i++) { a0[i] = iA0[i * IE_STR + e]; a1[i] = iA1[i * IE_STR + e]; }
            float4 w0 = *(const float4*)&sW[e * D + 4 * tx];
            float4 w1 = *(const float4*)&sW[e * D + 64 + 4 * tx];
            float wb0[4] = {w0.x, w0.y, w0.z, w0.w};
            float wb1[4] = {w1.x, w1.y, w1.z, w1.w};
            #pragma unroll
            for (int i = 0; i < 4; i++)
            #pragma unroll
            for (int j = 0; j < 4; j++) {
                acc[0][0][i][j] += a0[i] * wb0[j];
                acc[0][1][i][j] += a0[i] * wb1[j];
                acc[1][0][i][j] += a1[i] * wb0[j];
                acc[1][1][i][j] += a1[i] * wb1[j];
            }
        }

        // ctx partial: each thread's 4-row group shares a single r
        #pragma unroll
        for (int rh = 0; rh < 2; rh++)
        #pragma unroll
        for (int i = 0; i < 4; i++) {
            int row = rh * 64 + 4 * ty + i;
            int r = row >> 3, nn = row & 7;
            float al = sAl[r * N_INTR + cc * NC + nn];
            #pragma unroll
            for (int ch = 0; ch < 2; ch++)
            #pragma unroll
            for (int j = 0; j < 4; j++)
                ctxa[rh][ch][j] += al * acc[rh][ch][i][j];
        }
        __syncthreads();
    }

    // reduce ctx partials into sCtx
    #pragma unroll
    for (int rh = 0; rh < 2; rh++)
    #pragma unroll
    for (int ch = 0; ch < 2; ch++)
    #pragma unroll
    for (int j = 0; j < 4; j++) {
        int r = rh * 8 + (ty >> 1);
        int col = ch * 64 + 4 * tx + j;
        atomicAdd(&sCtx[r * D + col], ctxa[rh][ch][j]);
    }
    __syncthreads();

    // ---- proj into sW; attn_vec = tanh(ctx @ proj + b) -> g_x[:,128:256] ----
    for (int i = tid; i < D * D / 4; i += 256)
        ((float4*)sW)[i] = ((const float4*)projW)[i];
    __syncthreads();
    {
        float a0[4] = {0.f,0.f,0.f,0.f}, a1[4] = {0.f,0.f,0.f,0.f};
        const float* ce = &sCtx[ty * D];
        #pragma unroll 4
        for (int e = 0; e < D; e++) {
            float a = ce[e];
            float4 w0 = *(const float4*)&sW[e * D + 4 * tx];
            float4 w1 = *(const float4*)&sW[e * D + 64 + 4 * tx];
            a0[0] += a * w0.x; a0[1] += a * w0.y; a0[2] += a * w0.z; a0[3] += a * w0.w;
            a1[0] += a * w1.x; a1[1] += a * w1.y; a1[2] += a * w1.z; a1[3] += a * w1.w;
        }
        size_t base = (size_t)(b0 + ty) * 256 + 128;
        #pragma unroll
        for (int j = 0; j < 4; j++) {
            int c0 = 4 * tx + j, c1 = 64 + 4 * tx + j;
            g_x[base + c0] = tanhf(a0[j] + projB[c0]);
            g_x[base + c1] = tanhf(a1[j] + projB[c1]);
        }
    }
}

// =====================================================================
// Kernel 2: x(B,256) -> lrelu(h1) -> lrelu(h2) -> out(B,2)
// =====================================================================
__global__ void __launch_bounds__(256, 1)
k_mlp(const float* __restrict__ W1, const float* __restrict__ b1,
      const float* __restrict__ W2, const float* __restrict__ b2,
      const float* __restrict__ Wo, const float* __restrict__ bo,
      float* __restrict__ out)
{
    extern __shared__ float sm[];
    float* sX  = sm + OFF_X2;   // [64][260]
    float* sWt = sm + OFF_W2;   // [64][256] K-tile of weights

    const int tid = threadIdx.x;
    const int tx  = tid & 31;   // 32 column groups
    const int ty  = tid >> 5;   // 8 row groups
    const int b0  = blockIdx.x * R2;

    for (int i = tid; i < R2 * HID; i += 256) {
        int r = i >> 8, e = i & 255;
        sX[r * X_STR + e] = g_x[(size_t)b0 * HID + i];
    }
    __syncthreads();

    for (int layer = 0; layer < 2; layer++) {
        const float* W    = layer ? W2 : W1;
        const float* bias = layer ? b2 : b1;

        float acc[2][2][4][4];
        #pragma unroll
        for (int a = 0; a < 2; a++)
        #pragma unroll
        for (int b = 0; b < 2; b++)
        #pragma unroll
        for (int c = 0; c < 4; c++)
        #pragma unroll
        for (int d = 0; d < 4; d++) acc[a][b][c][d] = 0.f;

        for (int kk = 0; kk < 4; kk++) {
            for (int i = tid; i < 64 * HID / 4; i += 256)
                ((float4*)sWt)[i] = ((const float4*)W)[kk * (64 * HID / 4) + i];
            __syncthreads();

            const float* x0 = &sX[(4 * ty) * X_STR + kk * 64];
            const float* x1 = &sX[(32 + 4 * ty) * X_STR + kk * 64];
            #pragma unroll 4
            for (int el = 0; el < 64; el++) {
                float a0[4], a1[4];
                #pragma unroll
                for (int i = 0; i < 4; i++) { a0[i] = x0[i * X_STR + el]; a1[i] = x1[i * X_STR + el]; }
                float4 w0 = *(const float4*)&sWt[el * HID + 4 * tx];
                float4 w1 = *(const float4*)&sWt[el * HID + 128 + 4 * tx];
                float wb0[4] = {w0.x, w0.y, w0.z, w0.w};
                float wb1[4] = {w1.x, w1.y, w1.z, w1.w};
                #pragma unroll
                for (int i = 0; i < 4; i++)
                #pragma unroll
                for (int j = 0; j < 4; j++) {
                    acc[0][0][i][j] += a0[i] * wb0[j];
                    acc[0][1][i][j] += a0[i] * wb1[j];
                    acc[1][0][i][j] += a1[i] * wb0[j];
                    acc[1][1][i][j] += a1[i] * wb1[j];
                }
            }
            __syncthreads();
        }

        // activation + write back in place
        #pragma unroll
        for (int rh = 0; rh < 2; rh++)
        #pragma unroll
        for (int i = 0; i < 4; i++)
        #pragma unroll
        for (int ch = 0; ch < 2; ch++)
        #pragma unroll
        for (int j = 0; j < 4; j++) {
            int row = rh * 32 + 4 * ty + i;
            int col = ch * 128 + 4 * tx + j;
            sX[row * X_STR + col] = lrelu(acc[rh][ch][i][j] + bias[col]);
        }
        __syncthreads();
    }

    // out layer: 256 -> 2
    if (tid < R2) {
        int r = tid;
        float a0 = bo[0], a1 = bo[1];
        const float* xr = &sX[r * X_STR];
        #pragma unroll 4
        for (int e = 0; e < HID; e++) {
            float2 w = ((const float2*)Wo)[e];
            a0 += xr[e] * w.x;
            a1 += xr[e] * w.y;
        }
        out[(size_t)(b0 + r) * 2 + 0] = a0;
        out[(size_t)(b0 + r) * 2 + 1] = a1;
    }
}

extern "C" void kernel_launch(void* const* d_in, const int* in_sizes, int n_in,
                              void* d_out, int out_size)
{
    const float* obs   = (const float*)d_in[0];
    const float* ownW  = (const float*)d_in[1];
    const float* ownB  = (const float*)d_in[2];
    const float* intW  = (const float*)d_in[3];
    const float* intB  = (const float*)d_in[4];
    const float* Wq    = (const float*)d_in[5];
    const float* Wk    = (const float*)d_in[6];
    const float* Wv    = (const float*)d_in[7];
    const float* vatt  = (const float*)d_in[8];
    const float* projW = (const float*)d_in[9];
    const float* projB = (const float*)d_in[10];
    const float* W1    = (const float*)d_in[11];
    const float* b1    = (const float*)d_in[12];
    const float* W2    = (const float*)d_in[13];
    const float* b2    = (const float*)d_in[14];
    const float* Wo    = (const float*)d_in[15];
    const float* bo    = (const float*)d_in[16];
    float* out = (float*)d_out;

    cudaFuncSetAttribute(k_attn, cudaFuncAttributeMaxDynamicSharedMemorySize, SMEM1_FLOATS * 4);
    cudaFuncSetAttribute(k_mlp,  cudaFuncAttributeMaxDynamicSharedMemorySize, SMEM2_FLOATS * 4);

    k_attn<<<B_TOT / R1, 256, SMEM1_FLOATS * 4>>>(obs, ownW, ownB, intW, intB,
                                                  Wq, Wk, Wv, vatt, projW, projB);
    k_mlp<<<B_TOT / R2, 256, SMEM2_FLOATS * 4>>>(W1, b1, W2, b2, Wo, bo, out);
}

// round 2
// speedup vs baseline: 1.7428x; 1.7428x over previous
#include <cuda_runtime.h>
#include <math.h>

#define B_TOT   32768
#define OWN_DIM 3
#define N_INTR  32
#define INT_DIM 7
#define D       128
#define OBS_DIM 227
#define HID     256

#define R1      16      // rows per block, kernel 1
#define NC      8       // interactors per chunk
#define NCHUNK  (N_INTR / NC)
#define TILE    (R1 * NC)   // 128 GEMM rows per chunk
#define IE_STR  132

#define R2      64      // rows per block, kernel 2
#define X_STR   260

// ---- smem layout (floats), kernel 1 ----
#define OFF_W     0
#define OFF_IE    (D * D)                       // 16384
#define OFF_OBS   (OFF_IE + TILE * IE_STR)      // 33280
#define OFF_OWNE  (OFF_OBS + R1 * OBS_DIM)      // 36912
#define OFF_Q     (OFF_OWNE + R1 * D)           // 38960
#define OFF_CTX   (OFF_Q + R1 * D)              // 41008
#define OFF_SC    (OFF_CTX + R1 * D)            // 43056
#define OFF_AL    (OFF_SC + R1 * N_INTR)        // 43568
#define OFF_INTW  (OFF_AL + R1 * N_INTR)        // 44080
#define OFF_OWNW  (OFF_INTW + INT_DIM * D)      // 44976
#define OFF_INTB  (OFF_OWNW + OWN_DIM * D)      // 45360
#define OFF_VATT  (OFF_INTB + D)                // 45488
#define SMEM1_FLOATS (OFF_VATT + D)             // 45616 -> 182464 B

// ---- smem layout, kernel 2 ----
#define OFF_X2    0
#define OFF_W2    (R2 * X_STR)                  // 16640
#define SMEM2_FLOATS (OFF_W2 + 64 * HID)        // 33024 -> 132096 B

// scratch: x = [own_e | attn_vec], (B, 256) fp32
__device__ float g_x[(size_t)B_TOT * 256];

typedef unsigned long long u64;

__device__ __forceinline__ float lrelu(float x) { return fmaxf(x, 0.2f * x); }

__device__ __forceinline__ float tanh_ap(float x) {
    float y; asm("tanh.approx.f32 %0, %1;" : "=f"(y) : "f"(x)); return y;
}
__device__ __forceinline__ u64 dup2(float a) {
    u64 d; asm("mov.b64 %0, {%1, %1};" : "=l"(d) : "f"(a)); return d;
}
__device__ __forceinline__ void fma2(u64& d, u64 a, u64 b) {
    asm("fma.rn.f32x2 %0, %1, %2, %0;" : "+l"(d) : "l"(a), "l"(b));
}
__device__ __forceinline__ float2 unpack2(u64 v) {
    float2 f; asm("mov.b64 {%0, %1}, %2;" : "=f"(f.x), "=f"(f.y) : "l"(v)); return f;
}

// =====================================================================
// Kernel 1: own_e, q, scores (k), softmax, wsum = alpha@int_e,
//           ctx = wsum@Wv, attn_vec -> g_x
// =====================================================================
__global__ void __launch_bounds__(256, 1)
k_attn(const float* __restrict__ obs,
       const float* __restrict__ ownW, const float* __restrict__ ownB,
       const float* __restrict__ intW, const float* __restrict__ intB,
       const float* __restrict__ Wq,   const float* __restrict__ Wk,
       const float* __restrict__ Wv,   const float* __restrict__ vatt,
       const float* __restrict__ projW,const float* __restrict__ projB)
{
    extern __shared__ float sm[];
    float* sW    = sm + OFF_W;
    float* sIE   = sm + OFF_IE;
    float* sObs  = sm + OFF_OBS;
    float* sOwnE = sm + OFF_OWNE;
    float* sQ    = sm + OFF_Q;
    float* sCtx  = sm + OFF_CTX;
    float* sSc   = sm + OFF_SC;
    float* sAl   = sm + OFF_AL;
    float* sIntW = sm + OFF_INTW;
    float* sOwnW = sm + OFF_OWNW;
    float* sIntB = sm + OFF_INTB;
    float* sVatt = sm + OFF_VATT;

    const int tid = threadIdx.x;
    const int tx  = tid & 15;     // 16 column groups
    const int ty  = tid >> 4;     // 16 row groups
    const int b0  = blockIdx.x * R1;
    const float NEG_INF = __int_as_float(0xff800000u);

    // ---- stage obs tile + small weights; Wq into sW ----
    for (int i = tid; i < R1 * OBS_DIM; i += 256) sObs[i] = obs[(size_t)b0 * OBS_DIM + i];
    for (int i = tid; i < INT_DIM * D; i += 256)  sIntW[i] = intW[i];
    for (int i = tid; i < OWN_DIM * D; i += 256)  sOwnW[i] = ownW[i];
    if (tid < D) { sIntB[tid] = intB[tid]; sVatt[tid] = vatt[tid]; }
    for (int i = tid; i < D * D / 4; i += 256)
        ((float4*)sW)[i] = ((const float4*)Wq)[i];
    __syncthreads();

    // ---- own_e (also to g_x[:,0:128]); pad mask -> score init ----
    for (int i = tid; i < R1 * D; i += 256) {
        int r = i >> 7, d = i & 127;
        const float* o = &sObs[r * OBS_DIM];
        float a = ownB[d] + o[0] * sOwnW[d] + o[1] * sOwnW[D + d] + o[2] * sOwnW[2 * D + d];
        a = lrelu(a);
        sOwnE[i] = a;
        g_x[(size_t)(b0 + r) * 256 + d] = a;
    }
    for (int i = tid; i < R1 * N_INTR; i += 256) {
        int r = i >> 5, n = i & 31;
        const float* p = &sObs[r * OBS_DIM + OWN_DIM + n * INT_DIM];
        float s = 0.f;
        #pragma unroll
        for (int j = 0; j < INT_DIM; j++) s += fabsf(p[j]);
        sSc[i] = (s < 1e-6f) ? NEG_INF : 0.f;
    }
    __syncthreads();

    // ---- q = own_e @ Wq  (16 x 128, K = 128) ----
    {
        float a0[4] = {0.f,0.f,0.f,0.f}, a1[4] = {0.f,0.f,0.f,0.f};
        const float* ae = &sOwnE[ty * D];
        #pragma unroll 4
        for (int e = 0; e < D; e++) {
            float a = ae[e];
            float4 w0 = *(const float4*)&sW[e * D + 4 * tx];
            float4 w1 = *(const float4*)&sW[e * D + 64 + 4 * tx];
            a0[0] += a * w0.x; a0[1] += a * w0.y; a0[2] += a * w0.z; a0[3] += a * w0.w;
            a1[0] += a * w1.x; a1[1] += a * w1.y; a1[2] += a * w1.z; a1[3] += a * w1.w;
        }
        #pragma unroll
        for (int j = 0; j < 4; j++) {
            sQ[ty * D + 4 * tx + j]      = a0[j];
            sQ[ty * D + 64 + 4 * tx + j] = a1[j];
        }
    }
    __syncthreads();

    // ---- Wk into sW ----
    for (int i = tid; i < D * D / 4; i += 256)
        ((float4*)sW)[i] = ((const float4*)Wk)[i];
    __syncthreads();

    // ================= PASS 1: k -> scores (f32x2 GEMM) =================
    for (int cc = 0; cc < NCHUNK; cc++) {
        // int_e chunk: rows (r, n = cc*NC + nn), 128 x 128
        for (int i = tid; i < TILE * D; i += 256) {
            int row = i >> 7, d = i & 127;
            int r = row >> 3, nn = row & 7;
            const float* p = &sObs[r * OBS_DIM + OWN_DIM + (cc * NC + nn) * INT_DIM];
            float acc = sIntB[d];
            #pragma unroll
            for (int j = 0; j < INT_DIM; j++) acc += p[j] * sIntW[j * D + d];
            sIE[row * IE_STR + d] = lrelu(acc);
        }
        __syncthreads();

        u64 acc2[2][2][4][2];
        #pragma unroll
        for (int a = 0; a < 2; a++)
        #pragma unroll
        for (int b = 0; b < 2; b++)
        #pragma unroll
        for (int c = 0; c < 4; c++)
        #pragma unroll
        for (int d = 0; d < 2; d++) acc2[a][b][c][d] = 0ull;

        const float* iA0 = &sIE[(4 * ty) * IE_STR];
        const float* iA1 = &sIE[(64 + 4 * ty) * IE_STR];
        #pragma unroll 4
        for (int e = 0; e < D; e++) {
            u64 d0[4], d1[4];
            #pragma unroll
            for (int i = 0; i < 4; i++) {
                d0[i] = dup2(iA0[i * IE_STR + e]);
                d1[i] = dup2(iA1[i * IE_STR + e]);
            }
            ulonglong2 w0 = *(const ulonglong2*)&sW[e * D + 4 * tx];
            ulonglong2 w1 = *(const ulonglong2*)&sW[e * D + 64 + 4 * tx];
            #pragma unroll
            for (int i = 0; i < 4; i++) {
                fma2(acc2[0][0][i][0], d0[i], w0.x);
                fma2(acc2[0][0][i][1], d0[i], w0.y);
                fma2(acc2[0][1][i][0], d0[i], w1.x);
                fma2(acc2[0][1][i][1], d0[i], w1.y);
                fma2(acc2[1][0][i][0], d1[i], w0.x);
                fma2(acc2[1][0][i][1], d1[i], w0.y);
                fma2(acc2[1][1][i][0], d1[i], w1.x);
                fma2(acc2[1][1][i][1], d1[i], w1.y);
            }
        }

        // scores: sum_d tanh(q + k) * v_att, 16-lane shuffle reduce over tx
        #pragma unroll
        for (int rh = 0; rh < 2; rh++)
        #pragma unroll
        for (int i = 0; i < 4; i++) {
            int row = rh * 64 + 4 * ty + i;
            int r = row >> 3, nn = row & 7;
            const float* qr = &sQ[r * D];
            float s = 0.f;
            #pragma unroll
            for (int ch = 0; ch < 2; ch++) {
                int colb = ch * 64 + 4 * tx;
                #pragma unroll
                for (int jp = 0; jp < 2; jp++) {
                    float2 kv = unpack2(acc2[rh][ch][i][jp]);
                    int c0 = colb + 2 * jp;
                    s += tanh_ap(qr[c0]     + kv.x) * sVatt[c0];
                    s += tanh_ap(qr[c0 + 1] + kv.y) * sVatt[c0 + 1];
                }
            }
            #pragma unroll
            for (int o = 8; o > 0; o >>= 1) s += __shfl_xor_sync(0xffffffffu, s, o);
            if (tx == 0) sSc[r * N_INTR + cc * NC + nn] += s;
        }
        __syncthreads();
    }

    // ---- softmax over 32 interactors per row (8 warps x 2 rows) ----
    {
        int w = tid >> 5, lane = tid & 31;
        for (int r = w; r < R1; r += 8) {
            float s = sSc[r * N_INTR + lane];
            float m = s;
            #pragma unroll
            for (int o = 16; o > 0; o >>= 1) m = fmaxf(m, __shfl_xor_sync(0xffffffffu, m, o));
            float e = (m == NEG_INF) ? 0.f : __expf(s - m);
            float sum = e;
            #pragma unroll
            for (int o = 16; o > 0; o >>= 1) sum += __shfl_xor_sync(0xffffffffu, sum, o);
            sAl[r * N_INTR + lane] = (sum > 0.f) ? (e / sum) : 0.f;
        }
    }
    __syncthreads();

    // ================= PASS 2 (light): wsum = alpha @ int_e =================
    // thread (ty, tx) owns row ty, cols [8*tx, 8*tx+8)
    {
        float wIW[INT_DIM][8];
        float wB[8];
        #pragma unroll
        for (int c = 0; c < 8; c++) {
            wB[c] = sIntB[8 * tx + c];
            #pragma unroll
            for (int j = 0; j < INT_DIM; j++) wIW[j][c] = sIntW[j * D + 8 * tx + c];
        }
        float ws[8] = {0.f,0.f,0.f,0.f,0.f,0.f,0.f,0.f};
        for (int n = 0; n < N_INTR; n++) {
            float al = sAl[ty * N_INTR + n];
            if (al != 0.f) {
                const float* p = &sObs[ty * OBS_DIM + OWN_DIM + n * INT_DIM];
                float pj[INT_DIM];
                #pragma unroll
                for (int j = 0; j < INT_DIM; j++) pj[j] = p[j];
                #pragma unroll
                for (int c = 0; c < 8; c++) {
                    float pre = wB[c];
                    #pragma unroll
                    for (int j = 0; j < INT_DIM; j++) pre += pj[j] * wIW[j][c];
                    ws[c] += al * lrelu(pre);
                }
            }
        }
        #pragma unroll
        for (int c = 0; c < 8; c++) sCtx[ty * D + 8 * tx + c] = ws[c];
    }
    __syncthreads();

    // ---- Wv into sW; ctx = wsum @ Wv (16x128, K=128) -> sQ (reuse) ----
    for (int i = tid; i < D * D / 4; i += 256)
        ((float4*)sW)[i] = ((const float4*)Wv)[i];
    __syncthreads();
    {
        float a0[4] = {0.f,0.f,0.f,0.f}, a1[4] = {0.f,0.f,0.f,0.f};
        const float* ce = &sCtx[ty * D];
        #pragma unroll 4
        for (int e = 0; e < D; e++) {
            float a = ce[e];
            float4 w0 = *(const float4*)&sW[e * D + 4 * tx];
            float4 w1 = *(const float4*)&sW[e * D + 64 + 4 * tx];
            a0[0] += a * w0.x; a0[1] += a * w0.y; a0[2] += a * w0.z; a0[3] += a * w0.w;
            a1[0] += a * w1.x; a1[1] += a * w1.y; a1[2] += a * w1.z; a1[3] += a * w1.w;
        }
        __syncthreads();
        #pragma unroll
        for (int j = 0; j < 4; j++) {
            sQ[ty * D + 4 * tx + j]      = a0[j];
            sQ[ty * D + 64 + 4 * tx + j] = a1[j];
        }
    }
    __syncthreads();

    // ---- proj into sW; attn_vec = tanh(ctx @ proj + b) -> g_x[:,128:256] ----
    for (int i = tid; i < D * D / 4; i += 256)
        ((float4*)sW)[i] = ((const float4*)projW)[i];
    __syncthreads();
    {
        float a0[4] = {0.f,0.f,0.f,0.f}, a1[4] = {0.f,0.f,0.f,0.f};
        const float* ce = &sQ[ty * D];
        #pragma unroll 4
        for (int e = 0; e < D; e++) {
            float a = ce[e];
            float4 w0 = *(const float4*)&sW[e * D + 4 * tx];
            float4 w1 = *(const float4*)&sW[e * D + 64 + 4 * tx];
            a0[0] += a * w0.x; a0[1] += a * w0.y; a0[2] += a * w0.z; a0[3] += a * w0.w;
            a1[0] += a * w1.x; a1[1] += a * w1.y; a1[2] += a * w1.z; a1[3] += a * w1.w;
        }
        size_t base = (size_t)(b0 + ty) * 256 + 128;
        #pragma unroll
        for (int j = 0; j < 4; j++) {
            int c0 = 4 * tx + j, c1 = 64 + 4 * tx + j;
            g_x[base + c0] = tanhf(a0[j] + projB[c0]);
            g_x[base + c1] = tanhf(a1[j] + projB[c1]);
        }
    }
}

// =====================================================================
// Kernel 2: x(B,256) -> lrelu(h1) -> lrelu(h2) -> out(B,2)  (f32x2)
// =====================================================================
__global__ void __launch_bounds__(256, 1)
k_mlp(const float* __restrict__ W1, const float* __restrict__ b1,
      const float* __restrict__ W2, const float* __restrict__ b2,
      const float* __restrict__ Wo, const float* __restrict__ bo,
      float* __restrict__ out)
{
    extern __shared__ float sm[];
    float* sX  = sm + OFF_X2;   // [64][260]
    float* sWt = sm + OFF_W2;   // [64][256] K-tile of weights

    const int tid = threadIdx.x;
    const int tx  = tid & 31;   // 32 column groups
    const int ty  = tid >> 5;   // 8 row groups
    const int b0  = blockIdx.x * R2;

    for (int i = tid; i < R2 * HID; i += 256) {
        int r = i >> 8, e = i & 255;
        sX[r * X_STR + e] = g_x[(size_t)b0 * HID + i];
    }
    __syncthreads();

    for (int layer = 0; layer < 2; layer++) {
        const float* W    = layer ? W2 : W1;
        const float* bias = layer ? b2 : b1;

        u64 acc2[2][2][4][2];
        #pragma unroll
        for (int a = 0; a < 2; a++)
        #pragma unroll
        for (int b = 0; b < 2; b++)
        #pragma unroll
        for (int c = 0; c < 4; c++)
        #pragma unroll
        for (int d = 0; d < 2; d++) acc2[a][b][c][d] = 0ull;

        for (int kk = 0; kk < 4; kk++) {
            for (int i = tid; i < 64 * HID / 4; i += 256)
                ((float4*)sWt)[i] = ((const float4*)W)[kk * (64 * HID / 4) + i];
            __syncthreads();

            const float* x0 = &sX[(4 * ty) * X_STR + kk * 64];
            const float* x1 = &sX[(32 + 4 * ty) * X_STR + kk * 64];
            #pragma unroll 4
            for (int el = 0; el < 64; el++) {
                u64 d0[4], d1[4];
                #pragma unroll
                for (int i = 0; i < 4; i++) {
                    d0[i] = dup2(x0[i * X_STR + el]);
                    d1[i] = dup2(x1[i * X_STR + el]);
                }
                ulonglong2 w0 = *(const ulonglong2*)&sWt[el * HID + 4 * tx];
                ulonglong2 w1 = *(const ulonglong2*)&sWt[el * HID + 128 + 4 * tx];
                #pragma unroll
                for (int i = 0; i < 4; i++) {
                    fma2(acc2[0][0][i][0], d0[i], w0.x);
                    fma2(acc2[0][0][i][1], d0[i], w0.y);
                    fma2(acc2[0][1][i][0], d0[i], w1.x);
                    fma2(acc2[0][1][i][1], d0[i], w1.y);
                    fma2(acc2[1][0][i][0], d1[i], w0.x);
                    fma2(acc2[1][0][i][1], d1[i], w0.y);
                    fma2(acc2[1][1][i][0], d1[i], w1.x);
                    fma2(acc2[1][1][i][1], d1[i], w1.y);
                }
            }
            __syncthreads();
        }

        // activation + write back in place
        #pragma unroll
        for (int rh = 0; rh < 2; rh++)
        #pragma unroll
        for (int i = 0; i < 4; i++)
        #pragma unroll
        for (int ch = 0; ch < 2; ch++)
        #pragma unroll
        for (int jp = 0; jp < 2; jp++) {
            int row = rh * 32 + 4 * ty + i;
            int col = ch * 128 + 4 * tx + 2 * jp;
            float2 v = unpack2(acc2[rh][ch][i][jp]);
            sX[row * X_STR + col]     = lrelu(v.x + bias[col]);
            sX[row * X_STR + col + 1] = lrelu(v.y + bias[col + 1]);
        }
        __syncthreads();
    }

    // out layer: 256 -> 2
    if (tid < R2) {
        int r = tid;
        float a0 = bo[0], a1 = bo[1];
        const float* xr = &sX[r * X_STR];
        #pragma unroll 4
        for (int e = 0; e < HID; e++) {
            float2 w = ((const float2*)Wo)[e];
            a0 += xr[e] * w.x;
            a1 += xr[e] * w.y;
        }
        out[(size_t)(b0 + r) * 2 + 0] = a0;
        out[(size_t)(b0 + r) * 2 + 1] = a1;
    }
}

extern "C" void kernel_launch(void* const* d_in, const int* in_sizes, int n_in,
                              void* d_out, int out_size)
{
    const float* obs   = (const float*)d_in[0];
    const float* ownW  = (const float*)d_in[1];
    const float* ownB  = (const float*)d_in[2];
    const float* intW  = (const float*)d_in[3];
    const float* intB  = (const float*)d_in[4];
    const float* Wq    = (const float*)d_in[5];
    const float* Wk    = (const float*)d_in[6];
    const float* Wv    = (const float*)d_in[7];
    const float* vatt  = (const float*)d_in[8];
    const float* projW = (const float*)d_in[9];
    const float* projB = (const float*)d_in[10];
    const float* W1    = (const float*)d_in[11];
    const float* b1    = (const float*)d_in[12];
    const float* W2    = (const float*)d_in[13];
    const float* b2    = (const float*)d_in[14];
    const float* Wo    = (const float*)d_in[15];
    const float* bo    = (const float*)d_in[16];
    float* out = (float*)d_out;

    cudaFuncSetAttribute(k_attn, cudaFuncAttributeMaxDynamicSharedMemorySize, SMEM1_FLOATS * 4);
    cudaFuncSetAttribute(k_mlp,  cudaFuncAttributeMaxDynamicSharedMemorySize, SMEM2_FLOATS * 4);

    k_attn<<<B_TOT / R1, 256, SMEM1_FLOATS * 4>>>(obs, ownW, ownB, intW, intB,
                                                  Wq, Wk, Wv, vatt, projW, projB);
    k_mlp<<<B_TOT / R2, 256, SMEM2_FLOATS * 4>>>(W1, b1, W2, b2, Wo, bo, out);
}

// round 3
// speedup vs baseline: 1.9334x; 1.1094x over previous
#include <cuda_runtime.h>
#include <math.h>

#define B_TOT   32768
#define OWN_DIM 3
#define N_INTR  32
#define INT_DIM 7
#define D       128
#define OBS_DIM 227
#define HID     256

#define R1      16      // rows per block, kernel 1
#define NC      8       // interactors per chunk
#define NCHUNK  (N_INTR / NC)
#define TILE    (R1 * NC)   // 128 GEMM rows per chunk
#define IE_STR  132

#define R2      64      // rows per block, kernel 2
#define X_STR   260

#define NT      512     // threads per block (16 warps = 4/SMSP)

// ---- smem layout (floats), kernel 1 ----
#define OFF_W     0
#define OFF_IE    (D * D)                       // 16384
#define OFF_OBS   (OFF_IE + TILE * IE_STR)      // 33280
#define OFF_OWNE  (OFF_OBS + R1 * OBS_DIM)      // 36912
#define OFF_Q     (OFF_OWNE + R1 * D)           // 38960
#define OFF_CTX   (OFF_Q + R1 * D)              // 41008
#define OFF_SC    (OFF_CTX + R1 * D)            // 43056
#define OFF_AL    (OFF_SC + R1 * N_INTR)        // 43568
#define OFF_INTW  (OFF_AL + R1 * N_INTR)        // 44080
#define OFF_OWNW  (OFF_INTW + INT_DIM * D)      // 44976
#define OFF_INTB  (OFF_OWNW + OWN_DIM * D)      // 45360
#define OFF_VATT  (OFF_INTB + D)                // 45488
#define SMEM1_FLOATS (OFF_VATT + D)             // 45616 -> 182464 B

// ---- smem layout, kernel 2 ----
#define OFF_X2    0
#define OFF_W2    (R2 * X_STR)                  // 16640
#define SMEM2_FLOATS (OFF_W2 + 64 * HID)        // 33024 -> 132096 B

// scratch: x = [own_e | attn_vec], (B, 256) fp32
__device__ float g_x[(size_t)B_TOT * 256];

typedef unsigned long long u64;

__device__ __forceinline__ float lrelu(float x) { return fmaxf(x, 0.2f * x); }

__device__ __forceinline__ float tanh_ap(float x) {
    float y; asm("tanh.approx.f32 %0, %1;" : "=f"(y) : "f"(x)); return y;
}
__device__ __forceinline__ u64 dup2(float a) {
    u64 d; asm("mov.b64 %0, {%1, %1};" : "=l"(d) : "f"(a)); return d;
}
__device__ __forceinline__ void fma2(u64& d, u64 a, u64 b) {
    asm("fma.rn.f32x2 %0, %1, %2, %0;" : "+l"(d) : "l"(a), "l"(b));
}
__device__ __forceinline__ float2 unpack2(u64 v) {
    float2 f; asm("mov.b64 {%0, %1}, %2;" : "=f"(f.x), "=f"(f.y) : "l"(v)); return f;
}

// =====================================================================
// Kernel 1: own_e, q, scores (k), softmax, wsum = alpha@int_e,
//           ctx = wsum@Wv, attn_vec -> g_x
// =====================================================================
__global__ void __launch_bounds__(NT, 1)
k_attn(const float* __restrict__ obs,
       const float* __restrict__ ownW, const float* __restrict__ ownB,
       const float* __restrict__ intW, const float* __restrict__ intB,
       const float* __restrict__ Wq,   const float* __restrict__ Wk,
       const float* __restrict__ Wv,   const float* __restrict__ vatt,
       const float* __restrict__ projW,const float* __restrict__ projB)
{
    extern __shared__ float sm[];
    float* sW    = sm + OFF_W;
    float* sIE   = sm + OFF_IE;
    float* sObs  = sm + OFF_OBS;
    float* sOwnE = sm + OFF_OWNE;
    float* sQ    = sm + OFF_Q;
    float* sCtx  = sm + OFF_CTX;
    float* sSc   = sm + OFF_SC;
    float* sAl   = sm + OFF_AL;
    float* sIntW = sm + OFF_INTW;
    float* sOwnW = sm + OFF_OWNW;
    float* sIntB = sm + OFF_INTB;
    float* sVatt = sm + OFF_VATT;

    const int tid = threadIdx.x;
    const int tx  = tid & 15;     // 16 col groups (main GEMM)
    const int tyg = tid >> 4;     // 32 row groups of 4 rows
    const int tx5 = tid & 31;     // 32 col groups (small GEMMs)
    const int ty5 = tid >> 5;     // 16 rows
    const int b0  = blockIdx.x * R1;
    const float NEG_INF = __int_as_float(0xff800000u);

    // ---- stage obs tile + small weights; Wq into sW ----
    for (int i = tid; i < R1 * OBS_DIM; i += NT) sObs[i] = obs[(size_t)b0 * OBS_DIM + i];
    for (int i = tid; i < INT_DIM * D; i += NT)  sIntW[i] = intW[i];
    for (int i = tid; i < OWN_DIM * D; i += NT)  sOwnW[i] = ownW[i];
    if (tid < D) { sIntB[tid] = intB[tid]; sVatt[tid] = vatt[tid]; }
    for (int i = tid; i < D * D / 4; i += NT)
        ((float4*)sW)[i] = ((const float4*)Wq)[i];
    __syncthreads();

    // ---- own_e (also to g_x[:,0:128]); pad mask -> score init ----
    for (int i = tid; i < R1 * D; i += NT) {
        int r = i >> 7, d = i & 127;
        const float* o = &sObs[r * OBS_DIM];
        float a = ownB[d] + o[0] * sOwnW[d] + o[1] * sOwnW[D + d] + o[2] * sOwnW[2 * D + d];
        a = lrelu(a);
        sOwnE[i] = a;
        g_x[(size_t)(b0 + r) * 256 + d] = a;
    }
    if (tid < R1 * N_INTR) {
        int r = tid >> 5, n = tid & 31;
        const float* p = &sObs[r * OBS_DIM + OWN_DIM + n * INT_DIM];
        float s = 0.f;
        #pragma unroll
        for (int j = 0; j < INT_DIM; j++) s += fabsf(p[j]);
        sSc[tid] = (s < 1e-6f) ? NEG_INF : 0.f;
    }
    __syncthreads();

    // ---- q = own_e @ Wq  (16 x 128, K=128): 1 row x 4 cols per thread ----
    {
        float a0[4] = {0.f,0.f,0.f,0.f};
        const float* ae = &sOwnE[ty5 * D];
        #pragma unroll 4
        for (int e = 0; e < D; e++) {
            float a = ae[e];
            float4 w = *(const float4*)&sW[e * D + 4 * tx5];
            a0[0] += a * w.x; a0[1] += a * w.y; a0[2] += a * w.z; a0[3] += a * w.w;
        }
        #pragma unroll
        for (int j = 0; j < 4; j++) sQ[ty5 * D + 4 * tx5 + j] = a0[j];
    }
    __syncthreads();

    // ---- Wk into sW ----
    for (int i = tid; i < D * D / 4; i += NT)
        ((float4*)sW)[i] = ((const float4*)Wk)[i];
    __syncthreads();

    // ================= PASS 1: k -> scores (f32x2 GEMM) =================
    for (int cc = 0; cc < NCHUNK; cc++) {
        // int_e chunk: rows (r, n = cc*NC + nn), 128 x 128
        for (int i = tid; i < TILE * D; i += NT) {
            int row = i >> 7, d = i & 127;
            int r = row >> 3, nn = row & 7;
            const float* p = &sObs[r * OBS_DIM + OWN_DIM + (cc * NC + nn) * INT_DIM];
            float acc = sIntB[d];
            #pragma unroll
            for (int j = 0; j < INT_DIM; j++) acc += p[j] * sIntW[j * D + d];
            sIE[row * IE_STR + d] = lrelu(acc);
        }
        __syncthreads();

        // thread tile: 4 rows (4*tyg..+3) x 8 cols (4*tx, 64+4*tx)
        u64 acc2[4][2][2];
        #pragma unroll
        for (int i = 0; i < 4; i++)
        #pragma unroll
        for (int c = 0; c < 2; c++)
        #pragma unroll
        for (int d = 0; d < 2; d++) acc2[i][c][d] = 0ull;

        const float* iA = &sIE[(4 * tyg) * IE_STR];
        #pragma unroll 4
        for (int e = 0; e < D; e++) {
            u64 dv[4];
            #pragma unroll
            for (int i = 0; i < 4; i++) dv[i] = dup2(iA[i * IE_STR + e]);
            ulonglong2 w0 = *(const ulonglong2*)&sW[e * D + 4 * tx];
            ulonglong2 w1 = *(const ulonglong2*)&sW[e * D + 64 + 4 * tx];
            #pragma unroll
            for (int i = 0; i < 4; i++) {
                fma2(acc2[i][0][0], dv[i], w0.x);
                fma2(acc2[i][0][1], dv[i], w0.y);
                fma2(acc2[i][1][0], dv[i], w1.x);
                fma2(acc2[i][1][1], dv[i], w1.y);
            }
        }

        // scores: sum_d tanh(q + k) * v_att, 16-lane shuffle reduce over tx
        #pragma unroll
        for (int i = 0; i < 4; i++) {
            int row = 4 * tyg + i;
            int r = row >> 3, nn = row & 7;
            const float* qr = &sQ[r * D];
            float s = 0.f;
            #pragma unroll
            for (int ch = 0; ch < 2; ch++) {
                int colb = ch * 64 + 4 * tx;
                #pragma unroll
                for (int jp = 0; jp < 2; jp++) {
                    float2 kv = unpack2(acc2[i][ch][jp]);
                    int c0 = colb + 2 * jp;
                    s += tanh_ap(qr[c0]     + kv.x) * sVatt[c0];
                    s += tanh_ap(qr[c0 + 1] + kv.y) * sVatt[c0 + 1];
                }
            }
            #pragma unroll
            for (int o = 8; o > 0; o >>= 1) s += __shfl_xor_sync(0xffffffffu, s, o);
            if (tx == 0) sSc[r * N_INTR + cc * NC + nn] += s;
        }
        __syncthreads();
    }

    // ---- softmax over 32 interactors per row (16 warps, 1 row each) ----
    {
        int w = tid >> 5, lane = tid & 31;
        float s = sSc[w * N_INTR + lane];
        float m = s;
        #pragma unroll
        for (int o = 16; o > 0; o >>= 1) m = fmaxf(m, __shfl_xor_sync(0xffffffffu, m, o));
        float e = (m == NEG_INF) ? 0.f : __expf(s - m);
        float sum = e;
        #pragma unroll
        for (int o = 16; o > 0; o >>= 1) sum += __shfl_xor_sync(0xffffffffu, sum, o);
        sAl[w * N_INTR + lane] = (sum > 0.f) ? (e / sum) : 0.f;
    }
    __syncthreads();

    // ================= PASS 2 (light): wsum = alpha @ int_e =================
    // thread (ty5, tx5) owns row ty5, cols [4*tx5, 4*tx5+4)
    {
        float wIW[INT_DIM][4];
        float wB[4];
        #pragma unroll
        for (int c = 0; c < 4; c++) {
            wB[c] = sIntB[4 * tx5 + c];
            #pragma unroll
            for (int j = 0; j < INT_DIM; j++) wIW[j][c] = sIntW[j * D + 4 * tx5 + c];
        }
        float ws[4] = {0.f,0.f,0.f,0.f};
        for (int n = 0; n < N_INTR; n++) {
            float al = sAl[ty5 * N_INTR + n];
            if (al != 0.f) {
                const float* p = &sObs[ty5 * OBS_DIM + OWN_DIM + n * INT_DIM];
                float pj[INT_DIM];
                #pragma unroll
                for (int j = 0; j < INT_DIM; j++) pj[j] = p[j];
                #pragma unroll
                for (int c = 0; c < 4; c++) {
                    float pre = wB[c];
                    #pragma unroll
                    for (int j = 0; j < INT_DIM; j++) pre += pj[j] * wIW[j][c];
                    ws[c] += al * lrelu(pre);
                }
            }
        }
        #pragma unroll
        for (int c = 0; c < 4; c++) sCtx[ty5 * D + 4 * tx5 + c] = ws[c];
    }
    __syncthreads();

    // ---- Wv into sW; ctx = wsum @ Wv (16x128, K=128) -> sQ (reuse) ----
    for (int i = tid; i < D * D / 4; i += NT)
        ((float4*)sW)[i] = ((const float4*)Wv)[i];
    __syncthreads();
    {
        float a0[4] = {0.f,0.f,0.f,0.f};
        const float* ce = &sCtx[ty5 * D];
        #pragma unroll 4
        for (int e = 0; e < D; e++) {
            float a = ce[e];
            float4 w = *(const float4*)&sW[e * D + 4 * tx5];
            a0[0] += a * w.x; a0[1] += a * w.y; a0[2] += a * w.z; a0[3] += a * w.w;
        }
        __syncthreads();
        #pragma unroll
        for (int j = 0; j < 4; j++) sQ[ty5 * D + 4 * tx5 + j] = a0[j];
    }
    __syncthreads();

    // ---- proj into sW; attn_vec = tanh(ctx @ proj + b) -> g_x[:,128:256] ----
    for (int i = tid; i < D * D / 4; i += NT)
        ((float4*)sW)[i] = ((const float4*)projW)[i];
    __syncthreads();
    {
        float a0[4] = {0.f,0.f,0.f,0.f};
        const float* ce = &sQ[ty5 * D];
        #pragma unroll 4
        for (int e = 0; e < D; e++) {
            float a = ce[e];
            float4 w = *(const float4*)&sW[e * D + 4 * tx5];
            a0[0] += a * w.x; a0[1] += a * w.y; a0[2] += a * w.z; a0[3] += a * w.w;
        }
        size_t base = (size_t)(b0 + ty5) * 256 + 128;
        #pragma unroll
        for (int j = 0; j < 4; j++) {
            int c0 = 4 * tx5 + j;
            g_x[base + c0] = tanhf(a0[j] + projB[c0]);
        }
    }
}

// =====================================================================
// Kernel 2: x(B,256) -> lrelu(h1) -> lrelu(h2) -> out(B,2)  (f32x2)
// =====================================================================
__global__ void __launch_bounds__(NT, 1)
k_mlp(const float* __restrict__ W1, const float* __restrict__ b1,
      const float* __restrict__ W2, const float* __restrict__ b2,
      const float* __restrict__ Wo, const float* __restrict__ bo,
      float* __restrict__ out)
{
    extern __shared__ float sm[];
    float* sX  = sm + OFF_X2;   // [64][260]
    float* sWt = sm + OFF_W2;   // [64][256] K-tile of weights

    const int tid = threadIdx.x;
    const int tx  = tid & 31;   // 32 col groups
    const int tyg = tid >> 5;   // 16 row groups of 4 rows
    const int b0  = blockIdx.x * R2;

    for (int i = tid; i < R2 * HID; i += NT) {
        int r = i >> 8, e = i & 255;
        sX[r * X_STR + e] = g_x[(size_t)b0 * HID + i];
    }
    __syncthreads();

    for (int layer = 0; layer < 2; layer++) {
        const float* W    = layer ? W2 : W1;
        const float* bias = layer ? b2 : b1;

        // thread tile: 4 rows (4*tyg..+3) x 8 cols (4*tx, 128+4*tx)
        u64 acc2[4][2][2];
        #pragma unroll
        for (int i = 0; i < 4; i++)
        #pragma unroll
        for (int c = 0; c < 2; c++)
        #pragma unroll
        for (int d = 0; d < 2; d++) acc2[i][c][d] = 0ull;

        for (int kk = 0; kk < 4; kk++) {
            for (int i = tid; i < 64 * HID / 4; i += NT)
                ((float4*)sWt)[i] = ((const float4*)W)[kk * (64 * HID / 4) + i];
            __syncthreads();

            const float* x0 = &sX[(4 * tyg) * X_STR + kk * 64];
            #pragma unroll 4
            for (int el = 0; el < 64; el++) {
                u64 dv[4];
                #pragma unroll
                for (int i = 0; i < 4; i++) dv[i] = dup2(x0[i * X_STR + el]);
                ulonglong2 w0 = *(const ulonglong2*)&sWt[el * HID + 4 * tx];
                ulonglong2 w1 = *(const ulonglong2*)&sWt[el * HID + 128 + 4 * tx];
                #pragma unroll
                for (int i = 0; i < 4; i++) {
                    fma2(acc2[i][0][0], dv[i], w0.x);
                    fma2(acc2[i][0][1], dv[i], w0.y);
                    fma2(acc2[i][1][0], dv[i], w1.x);
                    fma2(acc2[i][1][1], dv[i], w1.y);
                }
            }
            __syncthreads();
        }

        // activation + write back in place
        #pragma unroll
        for (int i = 0; i < 4; i++)
        #pragma unroll
        for (int ch = 0; ch < 2; ch++)
        #pragma unroll
        for (int jp = 0; jp < 2; jp++) {
            int row = 4 * tyg + i;
            int col = ch * 128 + 4 * tx + 2 * jp;
            float2 v = unpack2(acc2[i][ch][jp]);
            sX[row * X_STR + col]     = lrelu(v.x + bias[col]);
            sX[row * X_STR + col + 1] = lrelu(v.y + bias[col + 1]);
        }
        __syncthreads();
    }

    // out layer: 256 -> 2
    if (tid < R2) {
        int r = tid;
        float a0 = bo[0], a1 = bo[1];
        const float* xr = &sX[r * X_STR];
        #pragma unroll 4
        for (int e = 0; e < HID; e++) {
            float2 w = ((const float2*)Wo)[e];
            a0 += xr[e] * w.x;
            a1 += xr[e] * w.y;
        }
        out[(size_t)(b0 + r) * 2 + 0] = a0;
        out[(size_t)(b0 + r) * 2 + 1] = a1;
    }
}

extern "C" void kernel_launch(void* const* d_in, const int* in_sizes, int n_in,
                              void* d_out, int out_size)
{
    const float* obs   = (const float*)d_in[0];
    const float* ownW  = (const float*)d_in[1];
    const float* ownB  = (const float*)d_in[2];
    const float* intW  = (const float*)d_in[3];
    const float* intB  = (const float*)d_in[4];
    const float* Wq    = (const float*)d_in[5];
    const float* Wk    = (const float*)d_in[6];
    const float* Wv    = (const float*)d_in[7];
    const float* vatt  = (const float*)d_in[8];
    const float* projW = (const float*)d_in[9];
    const float* projB = (const float*)d_in[10];
    const float* W1    = (const float*)d_in[11];
    const float* b1    = (const float*)d_in[12];
    const float* W2    = (const float*)d_in[13];
    const float* b2    = (const float*)d_in[14];
    const float* Wo    = (const float*)d_in[15];
    const float* bo    = (const float*)d_in[16];
    float* out = (float*)d_out;

    cudaFuncSetAttribute(k_attn, cudaFuncAttributeMaxDynamicSharedMemorySize, SMEM1_FLOATS * 4);
    cudaFuncSetAttribute(k_mlp,  cudaFuncAttributeMaxDynamicSharedMemorySize, SMEM2_FLOATS * 4);

    k_attn<<<B_TOT / R1, NT, SMEM1_FLOATS * 4>>>(obs, ownW, ownB, intW, intB,
                                                 Wq, Wk, Wv, vatt, projW, projB);
    k_mlp<<<B_TOT / R2, NT, SMEM2_FLOATS * 4>>>(W1, b1, W2, b2, Wo, bo, out);
}

// round 5
// speedup vs baseline: 2.6717x; 1.3819x over previous
#include <cuda_runtime.h>
#include <cuda_bf16.h>
#include <math.h>
#include <stdint.h>

#define B_TOT   32768
#define OWN_DIM 3
#define N_INTR  32
#define INT_DIM 7
#define D       128
#define OBS_DIM 227
#define HID     256

#define R1      16
#define NC      8
#define NCHUNK  (N_INTR / NC)
#define TILE    (R1 * NC)       // 128 GEMM rows per chunk

#define R2      64
#define X_STR   260
#define NT      512

#define ASTR    272             // bf16 tile row stride in bytes (17 x 16B, odd -> conflict-free ldmatrix)
#define TILE_BYTES (128 * ASTR) // 34816

// ---- k_attn smem (byte offsets) ----
#define BY_AHI    1024
#define BY_ALO    (BY_AHI + TILE_BYTES)
#define BY_BHI    (BY_ALO + TILE_BYTES)
#define BY_BLO    (BY_BHI + TILE_BYTES)
#define BY_F32    (BY_BLO + TILE_BYTES)          // 140288
// fp32 region (float indices)
#define F_OBS   (BY_F32 / 4)
#define F_OWNE  (F_OBS  + R1 * OBS_DIM)
#define F_Q     (F_OWNE + R1 * D)
#define F_CTX   (F_Q    + R1 * D)
#define F_SC    (F_CTX  + R1 * D)
#define F_AL    (F_SC   + R1 * N_INTR)
#define F_INTW  (F_AL   + R1 * N_INTR)
#define F_OWNW  (F_INTW + INT_DIM * D)
#define F_INTB  (F_OWNW + OWN_DIM * D)
#define F_VATT  (F_INTB + D)
#define SMEM1_BYTES ((F_VATT + D) * 4)           // ~189.6 KB

// ---- k_mlp smem ----
#define OFF_X2    0
#define OFF_W2    (R2 * X_STR)
#define SMEM2_FLOATS (OFF_W2 + 64 * HID)

__device__ float g_x[(size_t)B_TOT * 256];

typedef unsigned long long u64;

__device__ __forceinline__ float lrelu(float x) { return fmaxf(x, 0.2f * x); }
__device__ __forceinline__ float tanh_ap(float x) {
    float y; asm("tanh.approx.f32 %0, %1;" : "=f"(y) : "f"(x)); return y;
}
__device__ __forceinline__ u64 dup2(float a) {
    u64 d; asm("mov.b64 %0, {%1, %1};" : "=l"(d) : "f"(a)); return d;
}
__device__ __forceinline__ void fma2(u64& d, u64 a, u64 b) {
    asm("fma.rn.f32x2 %0, %1, %2, %0;" : "+l"(d) : "l"(a), "l"(b));
}
__device__ __forceinline__ float2 unpack2(u64 v) {
    float2 f; asm("mov.b64 {%0, %1}, %2;" : "=f"(f.x), "=f"(f.y) : "l"(v)); return f;
}
__device__ __forceinline__ uint32_t smem_u32(const void* p) {
    uint32_t a;
    asm("{ .reg .u64 t; cvta.to.shared.u64 t, %1; cvt.u32.u64 %0, t; }" : "=r"(a) : "l"(p));
    return a;
}
__device__ __forceinline__ uint32_t bf16pair(float a, float b) {
    __nv_bfloat162 t = __floats2bfloat162_rn(a, b);
    return *(uint32_t*)&t;
}

#define LDSM_X4(r0, r1, r2, r3, addr) \
    asm volatile("ldmatrix.sync.aligned.m8n8.x4.shared.b16 {%0,%1,%2,%3}, [%4];" \
                 : "=r"(r0), "=r"(r1), "=r"(r2), "=r"(r3) : "r"(addr))

__device__ __forceinline__ void mma_bf16(float* c, const uint32_t* a, const uint32_t* b) {
    asm volatile(
        "mma.sync.aligned.m16n8k16.row.col.f32.bf16.bf16.f32 "
        "{%0,%1,%2,%3}, {%4,%5,%6,%7}, {%8,%9}, {%0,%1,%2,%3};"
        : "+f"(c[0]), "+f"(c[1]), "+f"(c[2]), "+f"(c[3])
        : "r"(a[0]), "r"(a[1]), "r"(a[2]), "r"(a[3]), "r"(b[0]), "r"(b[1]));
}

// =====================================================================
// Kernel 1
// =====================================================================
__global__ void __launch_bounds__(NT, 1)
k_attn(const float* __restrict__ obs,
       const float* __restrict__ ownW, const float* __restrict__ ownB,
       const float* __restrict__ intW, const float* __restrict__ intB,
       const float* __restrict__ Wq,   const float* __restrict__ Wk,
       const float* __restrict__ Wv,   const float* __restrict__ vatt,
       const float* __restrict__ projW,const float* __restrict__ projB)
{
    extern __shared__ float sm[];
    char* smc = (char*)sm;
    const uint32_t smb = smem_u32(sm);

    float* sW    = (float*)(smc + BY_AHI);   // 64KB fp32 overlay over A hi+lo (Wq / Wv / proj)
    float* sObs  = sm + F_OBS;
    float* sOwnE = sm + F_OWNE;
    float* sQ    = sm + F_Q;
    float* sCtx  = sm + F_CTX;
    float* sSc   = sm + F_SC;
    float* sAl   = sm + F_AL;
    float* sIntW = sm + F_INTW;
    float* sOwnW = sm + F_OWNW;
    float* sIntB = sm + F_INTB;
    float* sVatt = sm + F_VATT;

    const int tid  = threadIdx.x;
    const int wid  = tid >> 5;
    const int lane = tid & 31;
    const int tx5  = tid & 31;
    const int ty5  = tid >> 5;
    const int b0   = blockIdx.x * R1;
    const float NEG_INF = __int_as_float(0xff800000u);

    // stage obs + small weights; Wq into overlay
    for (int i = tid; i < R1 * OBS_DIM; i += NT) sObs[i] = obs[(size_t)b0 * OBS_DIM + i];
    for (int i = tid; i < INT_DIM * D; i += NT)  sIntW[i] = intW[i];
    for (int i = tid; i < OWN_DIM * D; i += NT)  sOwnW[i] = ownW[i];
    if (tid < D) { sIntB[tid] = intB[tid]; sVatt[tid] = vatt[tid]; }
    for (int i = tid; i < D * D / 4; i += NT)
        ((float4*)sW)[i] = ((const float4*)Wq)[i];
    __syncthreads();

    // own_e -> sOwnE + g_x[:,0:128]; pad mask -> score init
    for (int i = tid; i < R1 * D; i += NT) {
        int r = i >> 7, d = i & 127;
        const float* o = &sObs[r * OBS_DIM];
        float a = ownB[d] + o[0] * sOwnW[d] + o[1] * sOwnW[D + d] + o[2] * sOwnW[2 * D + d];
        a = lrelu(a);
        sOwnE[i] = a;
        g_x[(size_t)(b0 + r) * 256 + d] = a;
    }
    {
        int r = tid >> 5, n = tid & 31;   // NT == R1*N_INTR
        const float* p = &sObs[r * OBS_DIM + OWN_DIM + n * INT_DIM];
        float s = 0.f;
        #pragma unroll
        for (int j = 0; j < INT_DIM; j++) s += fabsf(p[j]);
        sSc[tid] = (s < 1e-6f) ? NEG_INF : 0.f;
    }
    __syncthreads();

    // q = own_e @ Wq
    {
        float a0[4] = {0.f,0.f,0.f,0.f};
        const float* ae = &sOwnE[ty5 * D];
        #pragma unroll 4
        for (int e = 0; e < D; e++) {
            float a = ae[e];
            float4 w = *(const float4*)&sW[e * D + 4 * tx5];
            a0[0] += a * w.x; a0[1] += a * w.y; a0[2] += a * w.z; a0[3] += a * w.w;
        }
        #pragma unroll
        for (int j = 0; j < 4; j++) sQ[ty5 * D + 4 * tx5 + j] = a0[j];
    }
    __syncthreads();   // q done before overlay reuse; B region untouched by overlay

    // B tile: Bn[n][e] = Wk[e][n], bf16 hi/lo, row stride ASTR
    for (int i = tid; i < 64 * D; i += NT) {
        int ep = i >> 7, n = i & 127;      // gmem reads coalesced over n
        int e0 = 2 * ep;
        float w0 = Wk[e0 * D + n], w1 = Wk[(e0 + 1) * D + n];
        float h0 = __bfloat162float(__float2bfloat16(w0));
        float h1 = __bfloat162float(__float2bfloat16(w1));
        uint32_t off = (uint32_t)n * ASTR + (uint32_t)e0 * 2;
        *(uint32_t*)(smc + BY_BHI + off) = bf16pair(h0, h1);
        *(uint32_t*)(smc + BY_BLO + off) = bf16pair(w0 - h0, w1 - h1);
    }

    // warp tile coords: 4x4 warps, each 32x32 of C
    const int wr = wid >> 2, wc = wid & 3;
    // ldmatrix lane addressing
    const int lt = lane >> 3, lw = lane & 7;
    // A frag rows: R0 + (lt&1)*8 + lw, khalf = lt>>1
    const uint32_t aoff = (uint32_t)(((lt & 1) * 8 + lw) * ASTR + (lt >> 1) * 16);
    // B frag: n = N0 + (lt>>1)*8 + lw, khalf = lt&1
    const uint32_t boff = (uint32_t)((((lt >> 1) * 8 + lw) + 32 * wc) * ASTR + (lt & 1) * 16);
    const uint32_t aBase0 = smb + BY_AHI + (uint32_t)(32 * wr) * ASTR + aoff;
    const uint32_t aBase1 = aBase0 + 16 * ASTR;
    const uint32_t alBase0 = aBase0 + TILE_BYTES;
    const uint32_t alBase1 = aBase1 + TILE_BYTES;
    const uint32_t bBase0 = smb + BY_BHI + boff;
    const uint32_t bBase1 = bBase0 + 16 * ASTR;
    const uint32_t blBase0 = bBase0 + TILE_BYTES;
    const uint32_t blBase1 = bBase1 + TILE_BYTES;

    // ================= chunk loop: k GEMM on HMMA =================
    for (int cc = 0; cc < NCHUNK; cc++) {
        // A = int_e (bf16 hi/lo), rows = 8r+nn, cols = d
        for (int i = tid; i < 64 * TILE; i += NT) {
            int row = i >> 6, dp = i & 63;
            int d0 = 2 * dp;
            int r = row >> 3, nn = row & 7;
            const float* p = &sObs[r * OBS_DIM + OWN_DIM + (cc * NC + nn) * INT_DIM];
            float2 acc = *(const float2*)&sIntB[d0];
            #pragma unroll
            for (int j = 0; j < INT_DIM; j++) {
                float2 w = *(const float2*)&sIntW[j * D + d0];
                acc.x += p[j] * w.x;
                acc.y += p[j] * w.y;
            }
            float v0 = lrelu(acc.x), v1 = lrelu(acc.y);
            float h0 = __bfloat162float(__float2bfloat16(v0));
            float h1 = __bfloat162float(__float2bfloat16(v1));
            uint32_t off = (uint32_t)row * ASTR + (uint32_t)d0 * 2;
            *(uint32_t*)(smc + BY_AHI + off) = bf16pair(h0, h1);
            *(uint32_t*)(smc + BY_ALO + off) = bf16pair(v0 - h0, v1 - h1);
        }
        __syncthreads();

        float c[2][4][4];
        #pragma unroll
        for (int mi = 0; mi < 2; mi++)
        #pragma unroll
        for (int ni = 0; ni < 4; ni++)
        #pragma unroll
        for (int j = 0; j < 4; j++) c[mi][ni][j] = 0.f;

        #pragma unroll
        for (int kk = 0; kk < 8; kk++) {
            const uint32_t ko = kk * 32;
            uint32_t ah[2][4], al[2][4], bh[2][4], bl[2][4];
            LDSM_X4(ah[0][0], ah[0][1], ah[0][2], ah[0][3], aBase0 + ko);
            LDSM_X4(ah[1][0], ah[1][1], ah[1][2], ah[1][3], aBase1 + ko);
            LDSM_X4(al[0][0], al[0][1], al[0][2], al[0][3], alBase0 + ko);
            LDSM_X4(al[1][0], al[1][1], al[1][2], al[1][3], alBase1 + ko);
            // bh[g] regs: {ntile(2g) khalf0, ntile(2g) khalf1, ntile(2g+1) khalf0, ntile(2g+1) khalf1}
            LDSM_X4(bh[0][0], bh[0][1], bh[0][2], bh[0][3], bBase0 + ko);
            LDSM_X4(bh[1][0], bh[1][1], bh[1][2], bh[1][3], bBase1 + ko);
            LDSM_X4(bl[0][0], bl[0][1], bl[0][2], bl[0][3], blBase0 + ko);
            LDSM_X4(bl[1][0], bl[1][1], bl[1][2], bl[1][3], blBase1 + ko);

            #pragma unroll
            for (int mi = 0; mi < 2; mi++)
            #pragma unroll
            for (int ni = 0; ni < 4; ni++) {
                const uint32_t* bfh = &bh[ni >> 1][(ni & 1) * 2];
                const uint32_t* bfl = &bl[ni >> 1][(ni & 1) * 2];
                mma_bf16(c[mi][ni], ah[mi], bfh);
                mma_bf16(c[mi][ni], al[mi], bfh);
                mma_bf16(c[mi][ni], ah[mi], bfl);
            }
        }

        // epilogue: scores from C fragments
        #pragma unroll
        for (int mi = 0; mi < 2; mi++)
        #pragma unroll
        for (int ci = 0; ci < 2; ci++) {
            int trow = 32 * wr + 16 * mi + 8 * ci + (lane >> 2);
            int r = trow >> 3, nn = trow & 7;
            const float* qr = &sQ[r * D];
            float s = 0.f;
            #pragma unroll
            for (int ni = 0; ni < 4; ni++) {
                int col = 32 * wc + 8 * ni + 2 * (lane & 3);
                s += tanh_ap(qr[col]     + c[mi][ni][2 * ci])     * sVatt[col];
                s += tanh_ap(qr[col + 1] + c[mi][ni][2 * ci + 1]) * sVatt[col + 1];
            }
            s += __shfl_xor_sync(0xffffffffu, s, 1);
            s += __shfl_xor_sync(0xffffffffu, s, 2);
            if ((lane & 3) == 0) atomicAdd(&sSc[r * N_INTR + cc * NC + nn], s);
        }
        __syncthreads();
    }

    // softmax over 32 interactors (16 warps, 1 row each)
    {
        float s = sSc[wid * N_INTR + lane];
        float m = s;
        #pragma unroll
        for (int o = 16; o > 0; o >>= 1) m = fmaxf(m, __shfl_xor_sync(0xffffffffu, m, o));
        float e = (m == NEG_INF) ? 0.f : __expf(s - m);
        float sum = e;
        #pragma unroll
        for (int o = 16; o > 0; o >>= 1) sum += __shfl_xor_sync(0xffffffffu, sum, o);
        sAl[wid * N_INTR + lane] = (sum > 0.f) ? (e / sum) : 0.f;
    }
    __syncthreads();

    // wsum = alpha @ int_e
    {
        float wIW[INT_DIM][4];
        float wB[4];
        #pragma unroll
        for (int cq = 0; cq < 4; cq++) {
            wB[cq] = sIntB[4 * tx5 + cq];
            #pragma unroll
            for (int j = 0; j < INT_DIM; j++) wIW[j][cq] = sIntW[j * D + 4 * tx5 + cq];
        }
        float ws[4] = {0.f,0.f,0.f,0.f};
        for (int n = 0; n < N_INTR; n++) {
            float al = sAl[ty5 * N_INTR + n];
            if (al != 0.f) {
                const float* p = &sObs[ty5 * OBS_DIM + OWN_DIM + n * INT_DIM];
                float pj[INT_DIM];
                #pragma unroll
                for (int j = 0; j < INT_DIM; j++) pj[j] = p[j];
                #pragma unroll
                for (int cq = 0; cq < 4; cq++) {
                    float pre = wB[cq];
                    #pragma unroll
                    for (int j = 0; j < INT_DIM; j++) pre += pj[j] * wIW[j][cq];
                    ws[cq] += al * lrelu(pre);
                }
            }
        }
        #pragma unroll
        for (int cq = 0; cq < 4; cq++) sCtx[ty5 * D + 4 * tx5 + cq] = ws[cq];
    }
    __syncthreads();

    // ctx = wsum @ Wv -> sQ (Wv into overlay; A region free now)
    for (int i = tid; i < D * D / 4; i += NT)
        ((float4*)sW)[i] = ((const float4*)Wv)[i];
    __syncthreads();
    {
        float a0[4] = {0.f,0.f,0.f,0.f};
        const float* ce = &sCtx[ty5 * D];
        #pragma unroll 4
        for (int e = 0; e < D; e++) {
            float a = ce[e];
            float4 w = *(const float4*)&sW[e * D + 4 * tx5];
            a0[0] += a * w.x; a0[1] += a * w.y; a0[2] += a * w.z; a0[3] += a * w.w;
        }
        __syncthreads();
        #pragma unroll
        for (int j = 0; j < 4; j++) sQ[ty5 * D + 4 * tx5 + j] = a0[j];
    }
    __syncthreads();

    // attn_vec = tanh(ctx @ proj + b) -> g_x[:,128:256]
    for (int i = tid; i < D * D / 4; i += NT)
        ((float4*)sW)[i] = ((const float4*)projW)[i];
    __syncthreads();
    {
        float a0[4] = {0.f,0.f,0.f,0.f};
        const float* ce = &sQ[ty5 * D];
        #pragma unroll 4
        for (int e = 0; e < D; e++) {
            float a = ce[e];
            float4 w = *(const float4*)&sW[e * D + 4 * tx5];
            a0[0] += a * w.x; a0[1] += a * w.y; a0[2] += a * w.z; a0[3] += a * w.w;
        }
        size_t base = (size_t)(b0 + ty5) * 256 + 128;
        #pragma unroll
        for (int j = 0; j < 4; j++) {
            int c0 = 4 * tx5 + j;
            g_x[base + c0] = tanhf(a0[j] + projB[c0]);
        }
    }
}

// =====================================================================
// Kernel 2: MLP (R3 version, known good)
// =====================================================================
__global__ void __launch_bounds__(NT, 1)
k_mlp(const float* __restrict__ W1, const float* __restrict__ b1,
      const float* __restrict__ W2, const float* __restrict__ b2,
      const float* __restrict__ Wo, const float* __restrict__ bo,
      float* __restrict__ out)
{
    extern __shared__ float sm[];
    float* sX  = sm + OFF_X2;
    float* sWt = sm + OFF_W2;

    const int tid = threadIdx.x;
    const int tx  = tid & 31;
    const int tyg = tid >> 5;
    const int b0  = blockIdx.x * R2;

    for (int i = tid; i < R2 * HID; i += NT) {
        int r = i >> 8, e = i & 255;
        sX[r * X_STR + e] = g_x[(size_t)b0 * HID + i];
    }
    __syncthreads();

    for (int layer = 0; layer < 2; layer++) {
        const float* W    = layer ? W2 : W1;
        const float* bias = layer ? b2 : b1;

        u64 acc2[4][2][2];
        #pragma unroll
        for (int i = 0; i < 4; i++)
        #pragma unroll
        for (int c = 0; c < 2; c++)
        #pragma unroll
        for (int d = 0; d < 2; d++) acc2[i][c][d] = 0ull;

        for (int kk = 0; kk < 4; kk++) {
            for (int i = tid; i < 64 * HID / 4; i += NT)
                ((float4*)sWt)[i] = ((const float4*)W)[kk * (64 * HID / 4) + i];
            __syncthreads();

            const float* x0 = &sX[(4 * tyg) * X_STR + kk * 64];
            #pragma unroll 4
            for (int el = 0; el < 64; el++) {
                u64 dv[4];
                #pragma unroll
                for (int i = 0; i < 4; i++) dv[i] = dup2(x0[i * X_STR + el]);
                ulonglong2 w0 = *(const ulonglong2*)&sWt[el * HID + 4 * tx];
                ulonglong2 w1 = *(const ulonglong2*)&sWt[el * HID + 128 + 4 * tx];
                #pragma unroll
                for (int i = 0; i < 4; i++) {
                    fma2(acc2[i][0][0], dv[i], w0.x);
                    fma2(acc2[i][0][1], dv[i], w0.y);
                    fma2(acc2[i][1][0], dv[i], w1.x);
                    fma2(acc2[i][1][1], dv[i], w1.y);
                }
            }
            __syncthreads();
        }

        #pragma unroll
        for (int i = 0; i < 4; i++)
        #pragma unroll
        for (int ch = 0; ch < 2; ch++)
        #pragma unroll
        for (int jp = 0; jp < 2; jp++) {
            int row = 4 * tyg + i;
            int col = ch * 128 + 4 * tx + 2 * jp;
            float2 v = unpack2(acc2[i][ch][jp]);
            sX[row * X_STR + col]     = lrelu(v.x + bias[col]);
            sX[row * X_STR + col + 1] = lrelu(v.y + bias[col + 1]);
        }
        __syncthreads();
    }

    if (tid < R2) {
        int r = tid;
        float a0 = bo[0], a1 = bo[1];
        const float* xr = &sX[r * X_STR];
        #pragma unroll 4
        for (int e = 0; e < HID; e++) {
            float2 w = ((const float2*)Wo)[e];
            a0 += xr[e] * w.x;
            a1 += xr[e] * w.y;
        }
        out[(size_t)(b0 + r) * 2 + 0] = a0;
        out[(size_t)(b0 + r) * 2 + 1] = a1;
    }
}

extern "C" void kernel_launch(void* const* d_in, const int* in_sizes, int n_in,
                              void* d_out, int out_size)
{
    const float* obs   = (const float*)d_in[0];
    const float* ownW  = (const float*)d_in[1];
    const float* ownB  = (const float*)d_in[2];
    const float* intW  = (const float*)d_in[3];
    const float* intB  = (const float*)d_in[4];
    const float* Wq    = (const float*)d_in[5];
    const float* Wk    = (const float*)d_in[6];
    const float* Wv    = (const float*)d_in[7];
    const float* vatt  = (const float*)d_in[8];
    const float* projW = (const float*)d_in[9];
    const float* projB = (const float*)d_in[10];
    const float* W1    = (const float*)d_in[11];
    const float* b1    = (const float*)d_in[12];
    const float* W2    = (const float*)d_in[13];
    const float* b2    = (const float*)d_in[14];
    const float* Wo    = (const float*)d_in[15];
    const float* bo    = (const float*)d_in[16];
    float* out = (float*)d_out;

    cudaFuncSetAttribute(k_attn, cudaFuncAttributeMaxDynamicSharedMemorySize, SMEM1_BYTES);
    cudaFuncSetAttribute(k_mlp,  cudaFuncAttributeMaxDynamicSharedMemorySize, SMEM2_FLOATS * 4);

    k_attn<<<B_TOT / R1, NT, SMEM1_BYTES>>>(obs, ownW, ownB, intW, intB,
                                            Wq, Wk, Wv, vatt, projW, projB);
    k_mlp<<<B_TOT / R2, NT, SMEM2_FLOATS * 4>>>(W1, b1, W2, b2, Wo, bo, out);
}

// round 7
// speedup vs baseline: 3.0946x; 1.1583x over previous
#include <cuda_runtime.h>
#include <cuda_bf16.h>
#include <math.h>
#include <stdint.h>

#define B_TOT   32768
#define OWN_DIM 3
#define N_INTR  32
#define INT_DIM 7
#define D       128
#define OBS_DIM 227
#define HID     256

#define R1      16
#define R2      64
#define X_STR   260
#define NT      512

#define ASTR    272             // bf16 row stride bytes (17 x 16B, conflict-free ldmatrix)
#define TILE_BYTES (128 * ASTR) // 34816

// ---- k_attn smem (byte offsets) ----
#define BY_AHI    1024
#define BY_ALO    (BY_AHI + TILE_BYTES)
#define BY_BHI    (BY_ALO + TILE_BYTES)
#define BY_BLO    (BY_BHI + TILE_BYTES)
#define BY_F32    (BY_BLO + TILE_BYTES)          // 140288
#define F_OBS   (BY_F32 / 4)
#define F_OWNE  (F_OBS  + R1 * OBS_DIM)
#define F_Q     (F_OWNE + R1 * D)
#define F_CTX   (F_Q    + R1 * D)
#define F_SC    (F_CTX  + R1 * D)
#define F_AL    (F_SC   + R1 * N_INTR)
#define F_INTW  (F_AL   + R1 * N_INTR)
#define F_OWNW  (F_INTW + INT_DIM * D)
#define F_INTB  (F_OWNW + OWN_DIM * D)
#define F_VATT  (F_INTB + D)
#define F_MAP   (F_VATT + D)      // 512 ints (compacted row map)
#define F_WS    (F_MAP + 512)     // 16 warp sums
#define F_NC    (F_WS + 16)       // count
#define SMEM1_BYTES ((F_NC + 1) * 4)

// ---- k_mlp smem (bytes) ----
#define XSTRB   144                               // 9 x 16B
#define M_BYXH  (R2 * X_STR * 4)                  // 66560 (after fp32 sX)
#define M_BYXL  (M_BYXH + 64 * XSTRB)
#define M_BYWH  (M_BYXL + 64 * XSTRB)
#define M_BYWL  (M_BYWH + 256 * XSTRB)
#define SMEM2_BYTES (M_BYWL + 256 * XSTRB)        // 158720

__device__ float g_x[(size_t)B_TOT * 256];

typedef unsigned long long u64;

__device__ __forceinline__ float lrelu(float x) { return fmaxf(x, 0.2f * x); }
__device__ __forceinline__ float tanh_ap(float x) {
    float y; asm("tanh.approx.f32 %0, %1;" : "=f"(y) : "f"(x)); return y;
}
__device__ __forceinline__ uint32_t smem_u32(const void* p) {
    uint32_t a;
    asm("{ .reg .u64 t; cvta.to.shared.u64 t, %1; cvt.u32.u64 %0, t; }" : "=r"(a) : "l"(p));
    return a;
}
__device__ __forceinline__ uint32_t bf16pair(float a, float b) {
    __nv_bfloat162 t = __floats2bfloat162_rn(a, b);
    return *(uint32_t*)&t;
}

#define LDSM_X4(r0, r1, r2, r3, addr) \
    asm volatile("ldmatrix.sync.aligned.m8n8.x4.shared.b16 {%0,%1,%2,%3}, [%4];" \
                 : "=r"(r0), "=r"(r1), "=r"(r2), "=r"(r3) : "r"(addr))

__device__ __forceinline__ void mma_bf16(float* c, const uint32_t* a, const uint32_t* b) {
    asm volatile(
        "mma.sync.aligned.m16n8k16.row.col.f32.bf16.bf16.f32 "
        "{%0,%1,%2,%3}, {%4,%5,%6,%7}, {%8,%9}, {%0,%1,%2,%3};"
        : "+f"(c[0]), "+f"(c[1]), "+f"(c[2]), "+f"(c[3])
        : "r"(a[0]), "r"(a[1]), "r"(a[2]), "r"(a[3]), "r"(b[0]), "r"(b[1]));
}

// =====================================================================
// Kernel 1: attention front-end (HMMA split-bf16 + padded-row compaction)
// =====================================================================
__global__ void __launch_bounds__(NT, 1)
k_attn(const float* __restrict__ obs,
       const float* __restrict__ ownW, const float* __restrict__ ownB,
       const float* __restrict__ intW, const float* __restrict__ intB,
       const float* __restrict__ Wq,   const float* __restrict__ Wk,
       const float* __restrict__ Wv,   const float* __restrict__ vatt,
       const float* __restrict__ projW,const float* __restrict__ projB)
{
    extern __shared__ float sm[];
    char* smc = (char*)sm;
    const uint32_t smb = smem_u32(sm);

    float* sW    = (float*)(smc + BY_AHI);   // fp32 overlay over A hi+lo (Wq/Wv/proj)
    float* sObs  = sm + F_OBS;
    float* sOwnE = sm + F_OWNE;
    float* sQ    = sm + F_Q;
    float* sCtx  = sm + F_CTX;
    float* sSc   = sm + F_SC;
    float* sAl   = sm + F_AL;
    float* sIntW = sm + F_INTW;
    float* sOwnW = sm + F_OWNW;
    float* sIntB = sm + F_INTB;
    float* sVatt = sm + F_VATT;
    int*   sMap  = (int*)(sm + F_MAP);
    int*   sWs   = (int*)(sm + F_WS);
    int*   sNC   = (int*)(sm + F_NC);

    const int tid  = threadIdx.x;
    const int wid  = tid >> 5;
    const int lane = tid & 31;
    const int tx5  = tid & 31;
    const int ty5  = tid >> 5;
    const int b0   = blockIdx.x * R1;
    const float NEG_INF = __int_as_float(0xff800000u);

    // stage obs + small weights; Wq into overlay
    for (int i = tid; i < R1 * OBS_DIM; i += NT) sObs[i] = obs[(size_t)b0 * OBS_DIM + i];
    for (int i = tid; i < INT_DIM * D; i += NT)  sIntW[i] = intW[i];
    for (int i = tid; i < OWN_DIM * D; i += NT)  sOwnW[i] = ownW[i];
    if (tid < D) { sIntB[tid] = intB[tid]; sVatt[tid] = vatt[tid]; }
    for (int i = tid; i < D * D / 4; i += NT)
        ((float4*)sW)[i] = ((const float4*)Wq)[i];
    __syncthreads();

    // own_e; pad mask -> score init
    for (int i = tid; i < R1 * D; i += NT) {
        int r = i >> 7, d = i & 127;
        const float* o = &sObs[r * OBS_DIM];
        float a = ownB[d] + o[0] * sOwnW[d] + o[1] * sOwnW[D + d] + o[2] * sOwnW[2 * D + d];
        a = lrelu(a);
        sOwnE[i] = a;
        g_x[(size_t)(b0 + r) * 256 + d] = a;
    }
    {
        int r = tid >> 5, n = tid & 31;
        const float* p = &sObs[r * OBS_DIM + OWN_DIM + n * INT_DIM];
        float s = 0.f;
        #pragma unroll
        for (int j = 0; j < INT_DIM; j++) s += fabsf(p[j]);
        sSc[tid] = (s < 1e-6f) ? NEG_INF : 0.f;
    }
    __syncthreads();

    // q = own_e @ Wq
    {
        float a0[4] = {0.f,0.f,0.f,0.f};
        const float* ae = &sOwnE[ty5 * D];
        #pragma unroll 4
        for (int e = 0; e < D; e++) {
            float a = ae[e];
            float4 w = *(const float4*)&sW[e * D + 4 * tx5];
            a0[0] += a * w.x; a0[1] += a * w.y; a0[2] += a * w.z; a0[3] += a * w.w;
        }
        #pragma unroll
        for (int j = 0; j < 4; j++) sQ[ty5 * D + 4 * tx5 + j] = a0[j];
    }
    __syncthreads();

    // ---- compaction: prefix-sum non-padded (r,n) pairs ----
    {
        int flag = (sSc[tid] == 0.f) ? 1 : 0;
        unsigned bal = __ballot_sync(0xffffffffu, flag);
        int wpos = __popc(bal & ((1u << lane) - 1));
        if (lane == 0) sWs[wid] = __popc(bal);
        __syncthreads();
        if (tid == 0) {
            int acc = 0;
            for (int w = 0; w < 16; w++) { int t = sWs[w]; sWs[w] = acc; acc += t; }
            *sNC = acc;
        }
        __syncthreads();
        if (flag) sMap[sWs[wid] + wpos] = tid;
        __syncthreads();
    }
    const int n_comp = *sNC;
    const int nch = (n_comp + 127) >> 7;

    // B = Wk^T hi/lo
    for (int i = tid; i < 64 * D; i += NT) {
        int ep = i >> 7, n = i & 127;
        int e0 = 2 * ep;
        float w0 = Wk[e0 * D + n], w1 = Wk[(e0 + 1) * D + n];
        float h0 = __bfloat162float(__float2bfloat16(w0));
        float h1 = __bfloat162float(__float2bfloat16(w1));
        uint32_t off = (uint32_t)n * ASTR + (uint32_t)e0 * 2;
        *(uint32_t*)(smc + BY_BHI + off) = bf16pair(h0, h1);
        *(uint32_t*)(smc + BY_BLO + off) = bf16pair(w0 - h0, w1 - h1);
    }

    const int wr = wid >> 2, wc = wid & 3;
    const int lt = lane >> 3, lw = lane & 7;
    const uint32_t aoff = (uint32_t)(((lt & 1) * 8 + lw) * ASTR + (lt >> 1) * 16);
    const uint32_t boff = (uint32_t)((((lt >> 1) * 8 + lw) + 32 * wc) * ASTR + (lt & 1) * 16);
    const uint32_t aBase0 = smb + BY_AHI + (uint32_t)(32 * wr) * ASTR + aoff;
    const uint32_t aBase1 = aBase0 + 16 * ASTR;
    const uint32_t alBase0 = aBase0 + TILE_BYTES;
    const uint32_t alBase1 = aBase1 + TILE_BYTES;
    const uint32_t bBase0 = smb + BY_BHI + boff;
    const uint32_t bBase1 = bBase0 + 16 * ASTR;
    const uint32_t blBase0 = bBase0 + TILE_BYTES;
    const uint32_t blBase1 = bBase1 + TILE_BYTES;

    // ================= compacted chunk loop =================
    for (int cc = 0; cc < nch; cc++) {
        for (int i = tid; i < 64 * 128; i += NT) {
            int row = i >> 6, dp = i & 63;
            int d0 = 2 * dp;
            int g = cc * 128 + row;
            uint32_t off = (uint32_t)row * ASTR + (uint32_t)d0 * 2;
            if (g < n_comp) {
                int pr = sMap[g];
                const float* p = &sObs[(pr >> 5) * OBS_DIM + OWN_DIM + (pr & 31) * INT_DIM];
                float2 acc = *(const float2*)&sIntB[d0];
                #pragma unroll
                for (int j = 0; j < INT_DIM; j++) {
                    float2 w = *(const float2*)&sIntW[j * D + d0];
                    acc.x += p[j] * w.x;
                    acc.y += p[j] * w.y;
                }
                float v0 = lrelu(acc.x), v1 = lrelu(acc.y);
                float h0 = __bfloat162float(__float2bfloat16(v0));
                float h1 = __bfloat162float(__float2bfloat16(v1));
                *(uint32_t*)(smc + BY_AHI + off) = bf16pair(h0, h1);
                *(uint32_t*)(smc + BY_ALO + off) = bf16pair(v0 - h0, v1 - h1);
            } else {
                *(uint32_t*)(smc + BY_AHI + off) = 0u;
                *(uint32_t*)(smc + BY_ALO + off) = 0u;
            }
        }
        __syncthreads();

        if (cc * 128 + 32 * wr < n_comp) {  // warp band active
            float c[2][4][4];
            #pragma unroll
            for (int mi = 0; mi < 2; mi++)
            #pragma unroll
            for (int ni = 0; ni < 4; ni++)
            #pragma unroll
            for (int j = 0; j < 4; j++) c[mi][ni][j] = 0.f;

            #pragma unroll
            for (int kk = 0; kk < 8; kk++) {
                const uint32_t ko = kk * 32;
                uint32_t ah[2][4], al[2][4], bh[2][4], bl[2][4];
                LDSM_X4(ah[0][0], ah[0][1], ah[0][2], ah[0][3], aBase0 + ko);
                LDSM_X4(ah[1][0], ah[1][1], ah[1][2], ah[1][3], aBase1 + ko);
                LDSM_X4(al[0][0], al[0][1], al[0][2], al[0][3], alBase0 + ko);
                LDSM_X4(al[1][0], al[1][1], al[1][2], al[1][3], alBase1 + ko);
                LDSM_X4(bh[0][0], bh[0][1], bh[0][2], bh[0][3], bBase0 + ko);
                LDSM_X4(bh[1][0], bh[1][1], bh[1][2], bh[1][3], bBase1 + ko);
                LDSM_X4(bl[0][0], bl[0][1], bl[0][2], bl[0][3], blBase0 + ko);
                LDSM_X4(bl[1][0], bl[1][1], bl[1][2], bl[1][3], blBase1 + ko);

                #pragma unroll
                for (int mi = 0; mi < 2; mi++)
                #pragma unroll
                for (int ni = 0; ni < 4; ni++) {
                    const uint32_t* bfh = &bh[ni >> 1][(ni & 1) * 2];
                    const uint32_t* bfl = &bl[ni >> 1][(ni & 1) * 2];
                    mma_bf16(c[mi][ni], ah[mi], bfh);
                    mma_bf16(c[mi][ni], al[mi], bfh);
                    mma_bf16(c[mi][ni], ah[mi], bfl);
                }
            }

            // epilogue: tanh scores, mapped back through sMap
            // NOTE: 4 wc-warps each contribute a 32-column partial per row -> atomicAdd
            #pragma unroll
            for (int mi = 0; mi < 2; mi++)
            #pragma unroll
            for (int ci = 0; ci < 2; ci++) {
                int crow = 32 * wr + 16 * mi + 8 * ci + (lane >> 2);
                int g = cc * 128 + crow;
                bool ok = (g < n_comp);
                int pr = ok ? sMap[g] : 0;
                const float* qr = &sQ[(pr >> 5) * D];
                float s = 0.f;
                #pragma unroll
                for (int ni = 0; ni < 4; ni++) {
                    int col = 32 * wc + 8 * ni + 2 * (lane & 3);
                    s += tanh_ap(qr[col]     + c[mi][ni][2 * ci])     * sVatt[col];
                    s += tanh_ap(qr[col + 1] + c[mi][ni][2 * ci + 1]) * sVatt[col + 1];
                }
                s += __shfl_xor_sync(0xffffffffu, s, 1);
                s += __shfl_xor_sync(0xffffffffu, s, 2);
                if (ok && (lane & 3) == 0) atomicAdd(&sSc[pr], s);
            }
        }
        __syncthreads();
    }

    // softmax over 32 interactors (16 warps, 1 row each)
    {
        float s = sSc[wid * N_INTR + lane];
        float m = s;
        #pragma unroll
        for (int o = 16; o > 0; o >>= 1) m = fmaxf(m, __shfl_xor_sync(0xffffffffu, m, o));
        float e = (m == NEG_INF) ? 0.f : __expf(s - m);
        float sum = e;
        #pragma unroll
        for (int o = 16; o > 0; o >>= 1) sum += __shfl_xor_sync(0xffffffffu, sum, o);
        sAl[wid * N_INTR + lane] = (sum > 0.f) ? (e / sum) : 0.f;
    }
    __syncthreads();

    // wsum = alpha @ int_e
    {
        float wIW[INT_DIM][4];
        float wB[4];
        #pragma unroll
        for (int cq = 0; cq < 4; cq++) {
            wB[cq] = sIntB[4 * tx5 + cq];
            #pragma unroll
            for (int j = 0; j < INT_DIM; j++) wIW[j][cq] = sIntW[j * D + 4 * tx5 + cq];
        }
        float ws[4] = {0.f,0.f,0.f,0.f};
        for (int n = 0; n < N_INTR; n++) {
            float al = sAl[ty5 * N_INTR + n];
            if (al != 0.f) {
                const float* p = &sObs[ty5 * OBS_DIM + OWN_DIM + n * INT_DIM];
                float pj[INT_DIM];
                #pragma unroll
                for (int j = 0; j < INT_DIM; j++) pj[j] = p[j];
                #pragma unroll
                for (int cq = 0; cq < 4; cq++) {
                    float pre = wB[cq];
                    #pragma unroll
                    for (int j = 0; j < INT_DIM; j++) pre += pj[j] * wIW[j][cq];
                    ws[cq] += al * lrelu(pre);
                }
            }
        }
        #pragma unroll
        for (int cq = 0; cq < 4; cq++) sCtx[ty5 * D + 4 * tx5 + cq] = ws[cq];
    }
    __syncthreads();

    // ctx = wsum @ Wv -> sQ
    for (int i = tid; i < D * D / 4; i += NT)
        ((float4*)sW)[i] = ((const float4*)Wv)[i];
    __syncthreads();
    {
        float a0[4] = {0.f,0.f,0.f,0.f};
        const float* ce = &sCtx[ty5 * D];
        #pragma unroll 4
        for (int e = 0; e < D; e++) {
            float a = ce[e];
            float4 w = *(const float4*)&sW[e * D + 4 * tx5];
            a0[0] += a * w.x; a0[1] += a * w.y; a0[2] += a * w.z; a0[3] += a * w.w;
        }
        __syncthreads();
        #pragma unroll
        for (int j = 0; j < 4; j++) sQ[ty5 * D + 4 * tx5 + j] = a0[j];
    }
    __syncthreads();

    // attn_vec = tanh(ctx @ proj + b)
    for (int i = tid; i < D * D / 4; i += NT)
        ((float4*)sW)[i] = ((const float4*)projW)[i];
    __syncthreads();
    {
        float a0[4] = {0.f,0.f,0.f,0.f};
        const float* ce = &sQ[ty5 * D];
        #pragma unroll 4
        for (int e = 0; e < D; e++) {
            float a = ce[e];
            float4 w = *(const float4*)&sW[e * D + 4 * tx5];
            a0[0] += a * w.x; a0[1] += a * w.y; a0[2] += a * w.z; a0[3] += a * w.w;
        }
        size_t base = (size_t)(b0 + ty5) * 256 + 128;
        #pragma unroll
        for (int j = 0; j < 4; j++) {
            int c0 = 4 * tx5 + j;
            g_x[base + c0] = tanhf(a0[j] + projB[c0]);
        }
    }
}

// =====================================================================
// Kernel 2: MLP on HMMA split-bf16 (64x256 C tile, K chunked by 64)
// =====================================================================
__global__ void __launch_bounds__(NT, 1)
k_mlp(const float* __restrict__ W1, const float* __restrict__ b1,
      const float* __restrict__ W2, const float* __restrict__ b2,
      const float* __restrict__ Wo, const float* __restrict__ bo,
      float* __restrict__ out)
{
    extern __shared__ float sm[];
    char* smc = (char*)sm;
    const uint32_t smb = smem_u32(sm);
    float* sX = sm;                      // [64][260] fp32

    const int tid  = threadIdx.x;
    const int wid  = tid >> 5;
    const int lane = tid & 31;
    const int b0   = blockIdx.x * R2;
    const int wr = wid >> 3, wc = wid & 7;      // 2 x 8 warp grid, 32x32 C tiles
    const int lt = lane >> 3, lw = lane & 7;

    for (int i = tid; i < R2 * HID; i += NT) {
        int r = i >> 8, e = i & 255;
        sX[r * X_STR + e] = g_x[(size_t)b0 * HID + i];
    }
    __syncthreads();

    const uint32_t aoff = (uint32_t)(((lt & 1) * 8 + lw) * XSTRB + (lt >> 1) * 16);
    const uint32_t boff = (uint32_t)((32 * wc + (lt >> 1) * 8 + lw) * XSTRB + (lt & 1) * 16);
    const uint32_t aB0 = smb + M_BYXH + (uint32_t)(32 * wr) * XSTRB + aoff;
    const uint32_t aB1 = aB0 + 16 * XSTRB;
    const uint32_t aL0 = aB0 + 64 * XSTRB;   // lo buffer
    const uint32_t aL1 = aB1 + 64 * XSTRB;
    const uint32_t bB0 = smb + M_BYWH + boff;
    const uint32_t bB1 = bB0 + 16 * XSTRB;
    const uint32_t bL0 = bB0 + 256 * XSTRB;
    const uint32_t bL1 = bB1 + 256 * XSTRB;

    for (int layer = 0; layer < 2; layer++) {
        const float* W    = layer ? W2 : W1;
        const float* bias = layer ? b2 : b1;

        float c[2][4][4];
        #pragma unroll
        for (int mi = 0; mi < 2; mi++)
        #pragma unroll
        for (int ni = 0; ni < 4; ni++)
        #pragma unroll
        for (int j = 0; j < 4; j++) c[mi][ni][j] = 0.f;

        for (int kk = 0; kk < 4; kk++) {
            // X chunk hi/lo: 64 rows x 64 k
            for (int i = tid; i < 64 * 32; i += NT) {
                int row = i >> 5, dp = i & 31, d0 = 2 * dp;
                const float* xr = &sX[row * X_STR + kk * 64 + d0];
                float x0 = xr[0], x1 = xr[1];
                float h0 = __bfloat162float(__float2bfloat16(x0));
                float h1 = __bfloat162float(__float2bfloat16(x1));
                uint32_t off = (uint32_t)row * XSTRB + (uint32_t)d0 * 2;
                *(uint32_t*)(smc + M_BYXH + off) = bf16pair(h0, h1);
                *(uint32_t*)(smc + M_BYXL + off) = bf16pair(x0 - h0, x1 - h1);
            }
            // W chunk hi/lo: 256 n-rows x 64 k
            for (int i = tid; i < 256 * 32; i += NT) {
                int n = i & 255, kp = i >> 8;
                int k0 = kk * 64 + 2 * kp;
                float w0 = W[(size_t)k0 * HID + n], w1 = W[(size_t)(k0 + 1) * HID + n];
                float h0 = __bfloat162float(__float2bfloat16(w0));
                float h1 = __bfloat162float(__float2bfloat16(w1));
                uint32_t off = (uint32_t)n * XSTRB + (uint32_t)kp * 4;
                *(uint32_t*)(smc + M_BYWH + off) = bf16pair(h0, h1);
                *(uint32_t*)(smc + M_BYWL + off) = bf16pair(w0 - h0, w1 - h1);
            }
            __syncthreads();

            #pragma unroll
            for (int ks = 0; ks < 4; ks++) {
                const uint32_t ko = ks * 32;
                uint32_t ah[2][4], al[2][4], bh[2][4], bl[2][4];
                LDSM_X4(ah[0][0], ah[0][1], ah[0][2], ah[0][3], aB0 + ko);
                LDSM_X4(ah[1][0], ah[1][1], ah[1][2], ah[1][3], aB1 + ko);
                LDSM_X4(al[0][0], al[0][1], al[0][2], al[0][3], aL0 + ko);
                LDSM_X4(al[1][0], al[1][1], al[1][2], al[1][3], aL1 + ko);
                LDSM_X4(bh[0][0], bh[0][1], bh[0][2], bh[0][3], bB0 + ko);
                LDSM_X4(bh[1][0], bh[1][1], bh[1][2], bh[1][3], bB1 + ko);
                LDSM_X4(bl[0][0], bl[0][1], bl[0][2], bl[0][3], bL0 + ko);
                LDSM_X4(bl[1][0], bl[1][1], bl[1][2], bl[1][3], bL1 + ko);

                #pragma unroll
                for (int mi = 0; mi < 2; mi++)
                #pragma unroll
                for (int ni = 0; ni < 4; ni++) {
                    const uint32_t* bfh = &bh[ni >> 1][(ni & 1) * 2];
                    const uint32_t* bfl = &bl[ni >> 1][(ni & 1) * 2];
                    mma_bf16(c[mi][ni], ah[mi], bfh);
                    mma_bf16(c[mi][ni], al[mi], bfh);
                    mma_bf16(c[mi][ni], ah[mi], bfl);
                }
            }
            __syncthreads();
        }

        // epilogue: bias + lrelu -> sX
        #pragma unroll
        for (int mi = 0; mi < 2; mi++)
        #pragma unroll
        for (int ci = 0; ci < 2; ci++) {
            int row = 32 * wr + 16 * mi + 8 * ci + (lane >> 2);
            #pragma unroll
            for (int ni = 0; ni < 4; ni++) {
                int col = 32 * wc + 8 * ni + 2 * (lane & 3);
                sX[row * X_STR + col]     = lrelu(c[mi][ni][2 * ci]     + bias[col]);
                sX[row * X_STR + col + 1] = lrelu(c[mi][ni][2 * ci + 1] + bias[col + 1]);
            }
        }
        __syncthreads();
    }

    // out layer: 256 -> 2
    if (tid < R2) {
        int r = tid;
        float a0 = bo[0], a1 = bo[1];
        const float* xr = &sX[r * X_STR];
        #pragma unroll 4
        for (int e = 0; e < HID; e++) {
            float2 w = ((const float2*)Wo)[e];
            a0 += xr[e] * w.x;
            a1 += xr[e] * w.y;
        }
        out[(size_t)(b0 + r) * 2 + 0] = a0;
        out[(size_t)(b0 + r) * 2 + 1] = a1;
    }
}

extern "C" void kernel_launch(void* const* d_in, const int* in_sizes, int n_in,
                              void* d_out, int out_size)
{
    const float* obs   = (const float*)d_in[0];
    const float* ownW  = (const float*)d_in[1];
    const float* ownB  = (const float*)d_in[2];
    const float* intW  = (const float*)d_in[3];
    const float* intB  = (const float*)d_in[4];
    const float* Wq    = (const float*)d_in[5];
    const float* Wk    = (const float*)d_in[6];
    const float* Wv    = (const float*)d_in[7];
    const float* vatt  = (const float*)d_in[8];
    const float* projW = (const float*)d_in[9];
    const float* projB = (const float*)d_in[10];
    const float* W1    = (const float*)d_in[11];
    const float* b1    = (const float*)d_in[12];
    const float* W2    = (const float*)d_in[13];
    const float* b2    = (const float*)d_in[14];
    const float* Wo    = (const float*)d_in[15];
    const float* bo    = (const float*)d_in[16];
    float* out = (float*)d_out;

    cudaFuncSetAttribute(k_attn, cudaFuncAttributeMaxDynamicSharedMemorySize, SMEM1_BYTES);
    cudaFuncSetAttribute(k_mlp,  cudaFuncAttributeMaxDynamicSharedMemorySize, SMEM2_BYTES);

    k_attn<<<B_TOT / R1, NT, SMEM1_BYTES>>>(obs, ownW, ownB, intW, intB,
                                            Wq, Wk, Wv, vatt, projW, projB);
    k_mlp<<<B_TOT / R2, NT, SMEM2_BYTES>>>(W1, b1, W2, b2, Wo, bo, out);
}

// round 8
// speedup vs baseline: 3.2273x; 1.0429x over previous
#include <cuda_runtime.h>
#include <cuda_bf16.h>
#include <math.h>
#include <stdint.h>

#define B_TOT   32768
#define OWN_DIM 3
#define N_INTR  32
#define INT_DIM 7
#define D       128
#define OBS_DIM 227
#define HID     256

#define R1      16
#define R2      64
#define X_STR   260
#define NT      512

#define ASTR    272             // bf16 row stride bytes (17 x 16B, conflict-free ldmatrix)
#define TILE_BYTES (128 * ASTR) // 34816

// ---- k_attn smem (byte offsets) ----
#define BY_AHI    1024
#define BY_ALO    (BY_AHI + TILE_BYTES)
#define BY_BHI    (BY_ALO + TILE_BYTES)
#define BY_BLO    (BY_BHI + TILE_BYTES)
#define BY_F32    (BY_BLO + TILE_BYTES)          // 140288
#define F_OBS   (BY_F32 / 4)
#define F_OWNE  (F_OBS  + R1 * OBS_DIM)
#define F_Q     (F_OWNE + R1 * D)
#define F_CTX   (F_Q    + R1 * D)
#define F_SC    (F_CTX  + R1 * D)
#define F_AL    (F_SC   + R1 * N_INTR)
#define F_INTW  (F_AL   + R1 * N_INTR)
#define F_OWNW  (F_INTW + INT_DIM * D)
#define F_INTB  (F_OWNW + OWN_DIM * D)
#define F_VATT  (F_INTB + D)
#define F_MAP   (F_VATT + D)      // 512 ints (compacted row map)
#define F_WS    (F_MAP + 512)     // 16 warp sums
#define F_NC    (F_WS + 16)       // count
#define SMEM1_BYTES ((F_NC + 1) * 4)

// ---- k_mlp smem (bytes) ----
#define XSTRB   144                               // 9 x 16B
#define M_BYXH  (R2 * X_STR * 4)                  // 66560
#define M_BYXL  (M_BYXH + 64 * XSTRB)
#define M_BYWH  (M_BYXL + 64 * XSTRB)
#define M_BYWL  (M_BYWH + 256 * XSTRB)
#define SMEM2_BYTES (M_BYWL + 256 * XSTRB)        // 158720

// ---- prequantized weight images + bf16 interchange ----
__device__ uint32_t gWkHi[8704], gWkLo[8704];            // 128 x ASTR image
__device__ uint32_t gW1Hi[4][9216], gW1Lo[4][9216];      // per-kk 256 x XSTRB images
__device__ uint32_t gW2Hi[4][9216], gW2Lo[4][9216];
__device__ __nv_bfloat16 g_xh[(size_t)B_TOT * 256];
__device__ __nv_bfloat16 g_xl[(size_t)B_TOT * 256];

typedef unsigned long long u64;

__device__ __forceinline__ float lrelu(float x) { return fmaxf(x, 0.2f * x); }
__device__ __forceinline__ float tanh_ap(float x) {
    float y; asm("tanh.approx.f32 %0, %1;" : "=f"(y) : "f"(x)); return y;
}
__device__ __forceinline__ uint32_t smem_u32(const void* p) {
    uint32_t a;
    asm("{ .reg .u64 t; cvta.to.shared.u64 t, %1; cvt.u32.u64 %0, t; }" : "=r"(a) : "l"(p));
    return a;
}
__device__ __forceinline__ uint32_t bf16pair(float a, float b) {
    __nv_bfloat162 t = __floats2bfloat162_rn(a, b);
    return *(uint32_t*)&t;
}

#define LDSM_X4(r0, r1, r2, r3, addr) \
    asm volatile("ldmatrix.sync.aligned.m8n8.x4.shared.b16 {%0,%1,%2,%3}, [%4];" \
                 : "=r"(r0), "=r"(r1), "=r"(r2), "=r"(r3) : "r"(addr))

__device__ __forceinline__ void mma_bf16(float* c, const uint32_t* a, const uint32_t* b) {
    asm volatile(
        "mma.sync.aligned.m16n8k16.row.col.f32.bf16.bf16.f32 "
        "{%0,%1,%2,%3}, {%4,%5,%6,%7}, {%8,%9}, {%0,%1,%2,%3};"
        : "+f"(c[0]), "+f"(c[1]), "+f"(c[2]), "+f"(c[3])
        : "r"(a[0]), "r"(a[1]), "r"(a[2]), "r"(a[3]), "r"(b[0]), "r"(b[1]));
}

// =====================================================================
// Prep: quantize Wk, W1, W2 to split-bf16 images (exact smem layouts)
// =====================================================================
__global__ void __launch_bounds__(256, 4)
k_prep(const float* __restrict__ Wk, const float* __restrict__ W1,
       const float* __restrict__ W2)
{
    int idx = blockIdx.x * 256 + threadIdx.x;
    if (idx < 8192) {                       // Wk: 64 e-pairs x 128 n
        int ep = idx >> 7, n = idx & 127;
        int e0 = 2 * ep;
        float w0 = Wk[e0 * D + n], w1 = Wk[(e0 + 1) * D + n];
        float h0 = __bfloat162float(__float2bfloat16(w0));
        float h1 = __bfloat162float(__float2bfloat16(w1));
        int o = n * 68 + ep;                // (n*ASTR + e0*2)/4
        gWkHi[o] = bf16pair(h0, h1);
        gWkLo[o] = bf16pair(w0 - h0, w1 - h1);
    } else if (idx < 8192 + 2 * 32768) {    // W1 then W2
        int j = idx - 8192;
        const float* W = (j < 32768) ? W1 : W2;
        uint32_t* WH = (j < 32768) ? &gW1Hi[0][0] : &gW2Hi[0][0];
        uint32_t* WL = (j < 32768) ? &gW1Lo[0][0] : &gW2Lo[0][0];
        j &= 32767;
        int kk = j >> 13, r = j & 8191;
        int n = r & 255, kp = r >> 8;
        int k0 = kk * 64 + 2 * kp;
        float w0 = W[(size_t)k0 * HID + n], w1 = W[(size_t)(k0 + 1) * HID + n];
        float h0 = __bfloat162float(__float2bfloat16(w0));
        float h1 = __bfloat162float(__float2bfloat16(w1));
        int o = kk * 9216 + n * 36 + kp;
        WH[o] = bf16pair(h0, h1);
        WL[o] = bf16pair(w0 - h0, w1 - h1);
    }
}

// =====================================================================
// Kernel 1: attention front-end (HMMA split-bf16 + compaction)
// =====================================================================
__global__ void __launch_bounds__(NT, 1)
k_attn(const float* __restrict__ obs,
       const float* __restrict__ ownW, const float* __restrict__ ownB,
       const float* __restrict__ intW, const float* __restrict__ intB,
       const float* __restrict__ Wq,   const float* __restrict__ Wv,
       const float* __restrict__ vatt,
       const float* __restrict__ projW,const float* __restrict__ projB)
{
    extern __shared__ float sm[];
    char* smc = (char*)sm;
    const uint32_t smb = smem_u32(sm);

    float* sW    = (float*)(smc + BY_AHI);   // fp32 overlay over A hi+lo (Wq/Wv/proj)
    float* sObs  = sm + F_OBS;
    float* sOwnE = sm + F_OWNE;
    float* sQ    = sm + F_Q;
    float* sCtx  = sm + F_CTX;
    float* sSc   = sm + F_SC;
    float* sAl   = sm + F_AL;
    float* sIntW = sm + F_INTW;
    float* sOwnW = sm + F_OWNW;
    float* sIntB = sm + F_INTB;
    float* sVatt = sm + F_VATT;
    int*   sMap  = (int*)(sm + F_MAP);
    int*   sWs   = (int*)(sm + F_WS);
    int*   sNC   = (int*)(sm + F_NC);

    const int tid  = threadIdx.x;
    const int wid  = tid >> 5;
    const int lane = tid & 31;
    const int tx5  = tid & 31;
    const int ty5  = tid >> 5;
    const int b0   = blockIdx.x * R1;
    const float NEG_INF = __int_as_float(0xff800000u);

    // stage obs + small weights; Wq into overlay
    for (int i = tid; i < R1 * OBS_DIM; i += NT) sObs[i] = obs[(size_t)b0 * OBS_DIM + i];
    for (int i = tid; i < INT_DIM * D; i += NT)  sIntW[i] = intW[i];
    for (int i = tid; i < OWN_DIM * D; i += NT)  sOwnW[i] = ownW[i];
    if (tid < D) { sIntB[tid] = intB[tid]; sVatt[tid] = vatt[tid]; }
    for (int i = tid; i < D * D / 4; i += NT)
        ((float4*)sW)[i] = ((const float4*)Wq)[i];
    __syncthreads();

    // own_e -> sOwnE + g_xh/g_xl[:,0:128]; pad mask -> score init
    for (int i = tid; i < R1 * D; i += NT) {
        int r = i >> 7, d = i & 127;
        const float* o = &sObs[r * OBS_DIM];
        float a = ownB[d] + o[0] * sOwnW[d] + o[1] * sOwnW[D + d] + o[2] * sOwnW[2 * D + d];
        a = lrelu(a);
        sOwnE[i] = a;
        __nv_bfloat16 h = __float2bfloat16(a);
        size_t gi = (size_t)(b0 + r) * 256 + d;
        g_xh[gi] = h;
        g_xl[gi] = __float2bfloat16(a - __bfloat162float(h));
    }
    {
        int r = tid >> 5, n = tid & 31;
        const float* p = &sObs[r * OBS_DIM + OWN_DIM + n * INT_DIM];
        float s = 0.f;
        #pragma unroll
        for (int j = 0; j < INT_DIM; j++) s += fabsf(p[j]);
        sSc[tid] = (s < 1e-6f) ? NEG_INF : 0.f;
    }
    __syncthreads();

    // q = own_e @ Wq
    {
        float a0[4] = {0.f,0.f,0.f,0.f};
        const float* ae = &sOwnE[ty5 * D];
        #pragma unroll 4
        for (int e = 0; e < D; e++) {
            float a = ae[e];
            float4 w = *(const float4*)&sW[e * D + 4 * tx5];
            a0[0] += a * w.x; a0[1] += a * w.y; a0[2] += a * w.z; a0[3] += a * w.w;
        }
        #pragma unroll
        for (int j = 0; j < 4; j++) sQ[ty5 * D + 4 * tx5 + j] = a0[j];
    }
    __syncthreads();

    // ---- compaction: prefix-sum non-padded (r,n) pairs ----
    {
        int flag = (sSc[tid] == 0.f) ? 1 : 0;
        unsigned bal = __ballot_sync(0xffffffffu, flag);
        int wpos = __popc(bal & ((1u << lane) - 1));
        if (lane == 0) sWs[wid] = __popc(bal);
        __syncthreads();
        if (tid == 0) {
            int acc = 0;
            for (int w = 0; w < 16; w++) { int t = sWs[w]; sWs[w] = acc; acc += t; }
            *sNC = acc;
        }
        __syncthreads();
        if (flag) sMap[sWs[wid] + wpos] = tid;
        __syncthreads();
    }
    const int n_comp = *sNC;
    const int nch = (n_comp + 127) >> 7;

    // B = Wk^T hi/lo: pure uint4 copy of prequantized image
    for (int i = tid; i < 2176; i += NT) {
        ((uint4*)(smc + BY_BHI))[i] = ((const uint4*)gWkHi)[i];
        ((uint4*)(smc + BY_BLO))[i] = ((const uint4*)gWkLo)[i];
    }

    const int wr = wid >> 2, wc = wid & 3;
    const int lt = lane >> 3, lw = lane & 7;
    const uint32_t aoff = (uint32_t)(((lt & 1) * 8 + lw) * ASTR + (lt >> 1) * 16);
    const uint32_t boff = (uint32_t)((((lt >> 1) * 8 + lw) + 32 * wc) * ASTR + (lt & 1) * 16);
    const uint32_t aBase0 = smb + BY_AHI + (uint32_t)(32 * wr) * ASTR + aoff;
    const uint32_t aBase1 = aBase0 + 16 * ASTR;
    const uint32_t alBase0 = aBase0 + TILE_BYTES;
    const uint32_t alBase1 = aBase1 + TILE_BYTES;
    const uint32_t bBase0 = smb + BY_BHI + boff;
    const uint32_t bBase1 = bBase0 + 16 * ASTR;
    const uint32_t blBase0 = bBase0 + TILE_BYTES;
    const uint32_t blBase1 = bBase1 + TILE_BYTES;

    // ================= compacted chunk loop =================
    for (int cc = 0; cc < nch; cc++) {
        for (int i = tid; i < 64 * 128; i += NT) {
            int row = i >> 6, dp = i & 63;
            int d0 = 2 * dp;
            int g = cc * 128 + row;
            uint32_t off = (uint32_t)row * ASTR + (uint32_t)d0 * 2;
            if (g < n_comp) {
                int pr = sMap[g];
                const float* p = &sObs[(pr >> 5) * OBS_DIM + OWN_DIM + (pr & 31) * INT_DIM];
                float2 acc = *(const float2*)&sIntB[d0];
                #pragma unroll
                for (int j = 0; j < INT_DIM; j++) {
                    float2 w = *(const float2*)&sIntW[j * D + d0];
                    acc.x += p[j] * w.x;
                    acc.y += p[j] * w.y;
                }
                float v0 = lrelu(acc.x), v1 = lrelu(acc.y);
                float h0 = __bfloat162float(__float2bfloat16(v0));
                float h1 = __bfloat162float(__float2bfloat16(v1));
                *(uint32_t*)(smc + BY_AHI + off) = bf16pair(h0, h1);
                *(uint32_t*)(smc + BY_ALO + off) = bf16pair(v0 - h0, v1 - h1);
            } else {
                *(uint32_t*)(smc + BY_AHI + off) = 0u;
                *(uint32_t*)(smc + BY_ALO + off) = 0u;
            }
        }
        __syncthreads();

        if (cc * 128 + 32 * wr < n_comp) {  // warp band active
            float c[2][4][4];
            #pragma unroll
            for (int mi = 0; mi < 2; mi++)
            #pragma unroll
            for (int ni = 0; ni < 4; ni++)
            #pragma unroll
            for (int j = 0; j < 4; j++) c[mi][ni][j] = 0.f;

            #pragma unroll
            for (int kk = 0; kk < 8; kk++) {
                const uint32_t ko = kk * 32;
                uint32_t ah[2][4], al[2][4], bh[2][4], bl[2][4];
                LDSM_X4(ah[0][0], ah[0][1], ah[0][2], ah[0][3], aBase0 + ko);
                LDSM_X4(ah[1][0], ah[1][1], ah[1][2], ah[1][3], aBase1 + ko);
                LDSM_X4(al[0][0], al[0][1], al[0][2], al[0][3], alBase0 + ko);
                LDSM_X4(al[1][0], al[1][1], al[1][2], al[1][3], alBase1 + ko);
                LDSM_X4(bh[0][0], bh[0][1], bh[0][2], bh[0][3], bBase0 + ko);
                LDSM_X4(bh[1][0], bh[1][1], bh[1][2], bh[1][3], bBase1 + ko);
                LDSM_X4(bl[0][0], bl[0][1], bl[0][2], bl[0][3], blBase0 + ko);
                LDSM_X4(bl[1][0], bl[1][1], bl[1][2], bl[1][3], blBase1 + ko);

                #pragma unroll
                for (int mi = 0; mi < 2; mi++)
                #pragma unroll
                for (int ni = 0; ni < 4; ni++) {
                    const uint32_t* bfh = &bh[ni >> 1][(ni & 1) * 2];
                    const uint32_t* bfl = &bl[ni >> 1][(ni & 1) * 2];
                    mma_bf16(c[mi][ni], ah[mi], bfh);
                    mma_bf16(c[mi][ni], al[mi], bfh);
                    mma_bf16(c[mi][ni], ah[mi], bfl);
                }
            }

            // epilogue: tanh scores (4 wc-warps -> atomicAdd partials)
            #pragma unroll
            for (int mi = 0; mi < 2; mi++)
            #pragma unroll
            for (int ci = 0; ci < 2; ci++) {
                int crow = 32 * wr + 16 * mi + 8 * ci + (lane >> 2);
                int g = cc * 128 + crow;
                bool ok = (g < n_comp);
                int pr = ok ? sMap[g] : 0;
                const float* qr = &sQ[(pr >> 5) * D];
                float s = 0.f;
                #pragma unroll
                for (int ni = 0; ni < 4; ni++) {
                    int col = 32 * wc + 8 * ni + 2 * (lane & 3);
                    s += tanh_ap(qr[col]     + c[mi][ni][2 * ci])     * sVatt[col];
                    s += tanh_ap(qr[col + 1] + c[mi][ni][2 * ci + 1]) * sVatt[col + 1];
                }
                s += __shfl_xor_sync(0xffffffffu, s, 1);
                s += __shfl_xor_sync(0xffffffffu, s, 2);
                if (ok && (lane & 3) == 0) atomicAdd(&sSc[pr], s);
            }
        }
        __syncthreads();
    }

    // softmax over 32 interactors (16 warps, 1 row each)
    {
        float s = sSc[wid * N_INTR + lane];
        float m = s;
        #pragma unroll
        for (int o = 16; o > 0; o >>= 1) m = fmaxf(m, __shfl_xor_sync(0xffffffffu, m, o));
        float e = (m == NEG_INF) ? 0.f : __expf(s - m);
        float sum = e;
        #pragma unroll
        for (int o = 16; o > 0; o >>= 1) sum += __shfl_xor_sync(0xffffffffu, sum, o);
        sAl[wid * N_INTR + lane] = (sum > 0.f) ? (e / sum) : 0.f;
    }
    __syncthreads();

    // wsum = alpha @ int_e
    {
        float wIW[INT_DIM][4];
        float wB[4];
        #pragma unroll
        for (int cq = 0; cq < 4; cq++) {
            wB[cq] = sIntB[4 * tx5 + cq];
            #pragma unroll
            for (int j = 0; j < INT_DIM; j++) wIW[j][cq] = sIntW[j * D + 4 * tx5 + cq];
        }
        float ws[4] = {0.f,0.f,0.f,0.f};
        for (int n = 0; n < N_INTR; n++) {
            float al = sAl[ty5 * N_INTR + n];
            if (al != 0.f) {
                const float* p = &sObs[ty5 * OBS_DIM + OWN_DIM + n * INT_DIM];
                float pj[INT_DIM];
                #pragma unroll
                for (int j = 0; j < INT_DIM; j++) pj[j] = p[j];
                #pragma unroll
                for (int cq = 0; cq < 4; cq++) {
                    float pre = wB[cq];
                    #pragma unroll
                    for (int j = 0; j < INT_DIM; j++) pre += pj[j] * wIW[j][cq];
                    ws[cq] += al * lrelu(pre);
                }
            }
        }
        #pragma unroll
        for (int cq = 0; cq < 4; cq++) sCtx[ty5 * D + 4 * tx5 + cq] = ws[cq];
    }
    __syncthreads();

    // ctx = wsum @ Wv -> sQ
    for (int i = tid; i < D * D / 4; i += NT)
        ((float4*)sW)[i] = ((const float4*)Wv)[i];
    __syncthreads();
    {
        float a0[4] = {0.f,0.f,0.f,0.f};
        const float* ce = &sCtx[ty5 * D];
        #pragma unroll 4
        for (int e = 0; e < D; e++) {
            float a = ce[e];
            float4 w = *(const float4*)&sW[e * D + 4 * tx5];
            a0[0] += a * w.x; a0[1] += a * w.y; a0[2] += a * w.z; a0[3] += a * w.w;
        }
        __syncthreads();
        #pragma unroll
        for (int j = 0; j < 4; j++) sQ[ty5 * D + 4 * tx5 + j] = a0[j];
    }
    __syncthreads();

    // attn_vec = tanh(ctx @ proj + b) -> g_xh/g_xl[:,128:256]
    for (int i = tid; i < D * D / 4; i += NT)
        ((float4*)sW)[i] = ((const float4*)projW)[i];
    __syncthreads();
    {
        float a0[4] = {0.f,0.f,0.f,0.f};
        const float* ce = &sQ[ty5 * D];
        #pragma unroll 4
        for (int e = 0; e < D; e++) {
            float a = ce[e];
            float4 w = *(const float4*)&sW[e * D + 4 * tx5];
            a0[0] += a * w.x; a0[1] += a * w.y; a0[2] += a * w.z; a0[3] += a * w.w;
        }
        size_t base = (size_t)(b0 + ty5) * 256 + 128;
        #pragma unroll
        for (int j = 0; j < 4; j++) {
            int c0 = 4 * tx5 + j;
            float t = tanhf(a0[j] + projB[c0]);
            __nv_bfloat16 h = __float2bfloat16(t);
            g_xh[base + c0] = h;
            g_xl[base + c0] = __float2bfloat16(t - __bfloat162float(h));
        }
    }
}

// =====================================================================
// Kernel 2: MLP on HMMA split-bf16, weights prequantized
// =====================================================================
__global__ void __launch_bounds__(NT, 1)
k_mlp(const float* __restrict__ b1, const float* __restrict__ b2,
      const float* __restrict__ Wo, const float* __restrict__ bo,
      float* __restrict__ out)
{
    extern __shared__ float sm[];
    char* smc = (char*)sm;
    const uint32_t smb = smem_u32(sm);
    float* sX = sm;                      // [64][260] fp32 (layer outputs)

    const int tid  = threadIdx.x;
    const int wid  = tid >> 5;
    const int lane = tid & 31;
    const int b0   = blockIdx.x * R2;
    const int wr = wid >> 3, wc = wid & 7;      // 2 x 8 warp grid, 32x32 C tiles
    const int lt = lane >> 3, lw = lane & 7;

    const uint32_t aoff = (uint32_t)(((lt & 1) * 8 + lw) * XSTRB + (lt >> 1) * 16);
    const uint32_t boff = (uint32_t)((32 * wc + (lt >> 1) * 8 + lw) * XSTRB + (lt & 1) * 16);
    const uint32_t aB0 = smb + M_BYXH + (uint32_t)(32 * wr) * XSTRB + aoff;
    const uint32_t aB1 = aB0 + 16 * XSTRB;
    const uint32_t aL0 = aB0 + 64 * XSTRB;
    const uint32_t aL1 = aB1 + 64 * XSTRB;
    const uint32_t bB0 = smb + M_BYWH + boff;
    const uint32_t bB1 = bB0 + 16 * XSTRB;
    const uint32_t bL0 = bB0 + 256 * XSTRB;
    const uint32_t bL1 = bB1 + 256 * XSTRB;

    for (int layer = 0; layer < 2; layer++) {
        const float* bias = layer ? b2 : b1;

        float c[2][4][4];
        #pragma unroll
        for (int mi = 0; mi < 2; mi++)
        #pragma unroll
        for (int ni = 0; ni < 4; ni++)
        #pragma unroll
        for (int j = 0; j < 4; j++) c[mi][ni][j] = 0.f;

        for (int kk = 0; kk < 4; kk++) {
            // X chunk: layer 0 copies prequantized interchange; layer 1 converts sX
            if (layer == 0) {
                int i = tid;   // 512 items, 1 per thread
                int row = i >> 3, q = i & 7;
                size_t src = (size_t)(b0 + row) * 32 + (size_t)kk * 8 + q;
                *(uint4*)(smc + M_BYXH + row * XSTRB + q * 16) = ((const uint4*)g_xh)[src];
                *(uint4*)(smc + M_BYXL + row * XSTRB + q * 16) = ((const uint4*)g_xl)[src];
            } else {
                for (int i = tid; i < 64 * 32; i += NT) {
                    int row = i >> 5, dp = i & 31, d0 = 2 * dp;
                    const float* xr = &sX[row * X_STR + kk * 64 + d0];
                    float x0 = xr[0], x1 = xr[1];
                    float h0 = __bfloat162float(__float2bfloat16(x0));
                    float h1 = __bfloat162float(__float2bfloat16(x1));
                    uint32_t off = (uint32_t)row * XSTRB + (uint32_t)d0 * 2;
                    *(uint32_t*)(smc + M_BYXH + off) = bf16pair(h0, h1);
                    *(uint32_t*)(smc + M_BYXL + off) = bf16pair(x0 - h0, x1 - h1);
                }
            }
            // W chunk: pure uint4 copy of prequantized image
            {
                const uint4* WH = (const uint4*)(layer ? gW2Hi[kk] : gW1Hi[kk]);
                const uint4* WL = (const uint4*)(layer ? gW2Lo[kk] : gW1Lo[kk]);
                for (int i = tid; i < 2304; i += NT) {
                    ((uint4*)(smc + M_BYWH))[i] = WH[i];
                    ((uint4*)(smc + M_BYWL))[i] = WL[i];
                }
            }
            __syncthreads();

            #pragma unroll
            for (int ks = 0; ks < 4; ks++) {
                const uint32_t ko = ks * 32;
                uint32_t ah[2][4], al[2][4], bh[2][4], bl[2][4];
                LDSM_X4(ah[0][0], ah[0][1], ah[0][2], ah[0][3], aB0 + ko);
                LDSM_X4(ah[1][0], ah[1][1], ah[1][2], ah[1][3], aB1 + ko);
                LDSM_X4(al[0][0], al[0][1], al[0][2], al[0][3], aL0 + ko);
                LDSM_X4(al[1][0], al[1][1], al[1][2], al[1][3], aL1 + ko);
                LDSM_X4(bh[0][0], bh[0][1], bh[0][2], bh[0][3], bB0 + ko);
                LDSM_X4(bh[1][0], bh[1][1], bh[1][2], bh[1][3], bB1 + ko);
                LDSM_X4(bl[0][0], bl[0][1], bl[0][2], bl[0][3], bL0 + ko);
                LDSM_X4(bl[1][0], bl[1][1], bl[1][2], bl[1][3], bL1 + ko);

                #pragma unroll
                for (int mi = 0; mi < 2; mi++)
                #pragma unroll
                for (int ni = 0; ni < 4; ni++) {
                    const uint32_t* bfh = &bh[ni >> 1][(ni & 1) * 2];
                    const uint32_t* bfl = &bl[ni >> 1][(ni & 1) * 2];
                    mma_bf16(c[mi][ni], ah[mi], bfh);
                    mma_bf16(c[mi][ni], al[mi], bfh);
                    mma_bf16(c[mi][ni], ah[mi], bfl);
                }
            }
            __syncthreads();
        }

        // epilogue: bias + lrelu -> sX
        #pragma unroll
        for (int mi = 0; mi < 2; mi++)
        #pragma unroll
        for (int ci = 0; ci < 2; ci++) {
            int row = 32 * wr + 16 * mi + 8 * ci + (lane >> 2);
            #pragma unroll
            for (int ni = 0; ni < 4; ni++) {
                int col = 32 * wc + 8 * ni + 2 * (lane & 3);
                sX[row * X_STR + col]     = lrelu(c[mi][ni][2 * ci]     + bias[col]);
                sX[row * X_STR + col + 1] = lrelu(c[mi][ni][2 * ci + 1] + bias[col + 1]);
            }
        }
        __syncthreads();
    }

    // out layer: 256 -> 2
    if (tid < R2) {
        int r = tid;
        float a0 = bo[0], a1 = bo[1];
        const float* xr = &sX[r * X_STR];
        #pragma unroll 4
        for (int e = 0; e < HID; e++) {
            float2 w = ((const float2*)Wo)[e];
            a0 += xr[e] * w.x;
            a1 += xr[e] * w.y;
        }
        out[(size_t)(b0 + r) * 2 + 0] = a0;
        out[(size_t)(b0 + r) * 2 + 1] = a1;
    }
}

extern "C" void kernel_launch(void* const* d_in, const int* in_sizes, int n_in,
                              void* d_out, int out_size)
{
    const float* obs   = (const float*)d_in[0];
    const float* ownW  = (const float*)d_in[1];
    const float* ownB  = (const float*)d_in[2];
    const float* intW  = (const float*)d_in[3];
    const float* intB  = (const float*)d_in[4];
    const float* Wq    = (const float*)d_in[5];
    const float* Wk    = (const float*)d_in[6];
    const float* Wv    = (const float*)d_in[7];
    const float* vatt  = (const float*)d_in[8];
    const float* projW = (const float*)d_in[9];
    const float* projB = (const float*)d_in[10];
    const float* W1    = (const float*)d_in[11];
    const float* b1    = (const float*)d_in[12];
    const float* W2    = (const float*)d_in[13];
    const float* b2    = (const float*)d_in[14];
    const float* Wo    = (const float*)d_in[15];
    const float* bo    = (const float*)d_in[16];
    float* out = (float*)d_out;

    cudaFuncSetAttribute(k_attn, cudaFuncAttributeMaxDynamicSharedMemorySize, SMEM1_BYTES);
    cudaFuncSetAttribute(k_mlp,  cudaFuncAttributeMaxDynamicSharedMemorySize, SMEM2_BYTES);

    k_prep<<<288, 256>>>(Wk, W1, W2);
    k_attn<<<B_TOT / R1, NT, SMEM1_BYTES>>>(obs, ownW, ownB, intW, intB,
                                            Wq, Wv, vatt, projW, projB);
    k_mlp<<<B_TOT / R2, NT, SMEM2_BYTES>>>(b1, b2, Wo, bo, out);
}

// round 9
// speedup vs baseline: 3.4730x; 1.0761x over previous
#include <cuda_runtime.h>
#include <cuda_bf16.h>
#include <math.h>
#include <stdint.h>

#define B_TOT   32768
#define OWN_DIM 3
#define N_INTR  32
#define INT_DIM 7
#define D       128
#define OBS_DIM 227
#define HID     256

#define R1      16
#define R2      64
#define X_STR   260
#define NT      512

#define ASTR    272             // bf16 row stride bytes (17 x 16B, conflict-free ldmatrix)
#define TILE_BYTES (128 * ASTR) // 34816

// ---- k_attn smem (byte offsets) ----
#define BY_AHI    1024
#define BY_ALO    (BY_AHI + TILE_BYTES)
#define BY_BHI    (BY_ALO + TILE_BYTES)
#define BY_BLO    (BY_BHI + TILE_BYTES)
#define BY_F32    (BY_BLO + TILE_BYTES)          // 140288
#define F_OBS   (BY_F32 / 4)
#define F_OWNE  (F_OBS  + R1 * OBS_DIM)
#define F_Q     (F_OWNE + R1 * D)
#define F_CTX   (F_Q    + R1 * D)
#define F_SC    (F_CTX  + R1 * D)
#define F_AL    (F_SC   + R1 * N_INTR)
#define F_INTW  (F_AL   + R1 * N_INTR)
#define F_OWNW  (F_INTW + INT_DIM * D)
#define F_INTB  (F_OWNW + OWN_DIM * D)
#define F_VATT  (F_INTB + D)
#define F_MAP   (F_VATT + D)      // 512 ints (compacted row map)
#define F_WS    (F_MAP + 512)     // 16 warp sums
#define F_NC    (F_WS + 16)       // count
#define SMEM1_BYTES ((F_NC + 1) * 4)

// ---- k_mlp smem (bytes) ----
#define XSTRB   144                               // 9 x 16B
#define M_BYXH  (R2 * X_STR * 4)                  // 66560
#define M_BYXL  (M_BYXH + 64 * XSTRB)
#define M_BYWH  (M_BYXL + 64 * XSTRB)
#define M_BYWL  (M_BYWH + 256 * XSTRB)
#define SMEM2_BYTES (M_BYWL + 256 * XSTRB)        // 158720

// ---- prequantized weight images + bf16 interchange ----
__device__ uint32_t gWkHi[8704], gWkLo[8704];            // 128 x ASTR image
__device__ uint32_t gW1Hi[4][9216], gW1Lo[4][9216];      // per-kk 256 x XSTRB images
__device__ uint32_t gW2Hi[4][9216], gW2Lo[4][9216];
__device__ __nv_bfloat16 g_xh[(size_t)B_TOT * 256];
__device__ __nv_bfloat16 g_xl[(size_t)B_TOT * 256];

typedef unsigned long long u64;

__device__ __forceinline__ float lrelu(float x) { return fmaxf(x, 0.2f * x); }
__device__ __forceinline__ float tanh_ap(float x) {
    float y; asm("tanh.approx.f32 %0, %1;" : "=f"(y) : "f"(x)); return y;
}
__device__ __forceinline__ uint32_t smem_u32(const void* p) {
    uint32_t a;
    asm("{ .reg .u64 t; cvta.to.shared.u64 t, %1; cvt.u32.u64 %0, t; }" : "=r"(a) : "l"(p));
    return a;
}
__device__ __forceinline__ uint32_t bf16pair(float a, float b) {
    __nv_bfloat162 t = __floats2bfloat162_rn(a, b);
    return *(uint32_t*)&t;
}

#define LDSM_X4(r0, r1, r2, r3, addr) \
    asm volatile("ldmatrix.sync.aligned.m8n8.x4.shared.b16 {%0,%1,%2,%3}, [%4];" \
                 : "=r"(r0), "=r"(r1), "=r"(r2), "=r"(r3) : "r"(addr))

__device__ __forceinline__ void mma_bf16(float* c, const uint32_t* a, const uint32_t* b) {
    asm volatile(
        "mma.sync.aligned.m16n8k16.row.col.f32.bf16.bf16.f32 "
        "{%0,%1,%2,%3}, {%4,%5,%6,%7}, {%8,%9}, {%0,%1,%2,%3};"
        : "+f"(c[0]), "+f"(c[1]), "+f"(c[2]), "+f"(c[3])
        : "r"(a[0]), "r"(a[1]), "r"(a[2]), "r"(a[3]), "r"(b[0]), "r"(b[1]));
}

#define GROUP_BAR(id) \
    asm volatile("bar.sync %0, 128;" :: "r"(id) : "memory")

// =====================================================================
// Prep: quantize Wk, W1, W2 to split-bf16 images (exact smem layouts)
// =====================================================================
__global__ void __launch_bounds__(256, 4)
k_prep(const float* __restrict__ Wk, const float* __restrict__ W1,
       const float* __restrict__ W2)
{
    int idx = blockIdx.x * 256 + threadIdx.x;
    if (idx < 8192) {                       // Wk: 64 e-pairs x 128 n
        int ep = idx >> 7, n = idx & 127;
        int e0 = 2 * ep;
        float w0 = Wk[e0 * D + n], w1 = Wk[(e0 + 1) * D + n];
        float h0 = __bfloat162float(__float2bfloat16(w0));
        float h1 = __bfloat162float(__float2bfloat16(w1));
        int o = n * 68 + ep;                // (n*ASTR + e0*2)/4
        gWkHi[o] = bf16pair(h0, h1);
        gWkLo[o] = bf16pair(w0 - h0, w1 - h1);
    } else if (idx < 8192 + 2 * 32768) {    // W1 then W2
        int j = idx - 8192;
        const float* W = (j < 32768) ? W1 : W2;
        uint32_t* WH = (j < 32768) ? &gW1Hi[0][0] : &gW2Hi[0][0];
        uint32_t* WL = (j < 32768) ? &gW1Lo[0][0] : &gW2Lo[0][0];
        j &= 32767;
        int kk = j >> 13, r = j & 8191;
        int n = r & 255, kp = r >> 8;
        int k0 = kk * 64 + 2 * kp;
        float w0 = W[(size_t)k0 * HID + n], w1 = W[(size_t)(k0 + 1) * HID + n];
        float h0 = __bfloat162float(__float2bfloat16(w0));
        float h1 = __bfloat162float(__float2bfloat16(w1));
        int o = kk * 9216 + n * 36 + kp;
        WH[o] = bf16pair(h0, h1);
        WL[o] = bf16pair(w0 - h0, w1 - h1);
    }
}

// =====================================================================
// Kernel 1: attention front-end (HMMA split-bf16 + compaction +
//           per-wr-group barriers so build/MMA overlap across groups)
// =====================================================================
__global__ void __launch_bounds__(NT, 1)
k_attn(const float* __restrict__ obs,
       const float* __restrict__ ownW, const float* __restrict__ ownB,
       const float* __restrict__ intW, const float* __restrict__ intB,
       const float* __restrict__ Wq,   const float* __restrict__ Wv,
       const float* __restrict__ vatt,
       const float* __restrict__ projW,const float* __restrict__ projB)
{
    extern __shared__ float sm[];
    char* smc = (char*)sm;
    const uint32_t smb = smem_u32(sm);

    float* sW    = (float*)(smc + BY_AHI);   // fp32 overlay over A hi+lo (Wq/Wv/proj)
    float* sObs  = sm + F_OBS;
    float* sOwnE = sm + F_OWNE;
    float* sQ    = sm + F_Q;
    float* sCtx  = sm + F_CTX;
    float* sSc   = sm + F_SC;
    float* sAl   = sm + F_AL;
    float* sIntW = sm + F_INTW;
    float* sOwnW = sm + F_OWNW;
    float* sIntB = sm + F_INTB;
    float* sVatt = sm + F_VATT;
    int*   sMap  = (int*)(sm + F_MAP);
    int*   sWs   = (int*)(sm + F_WS);
    int*   sNC   = (int*)(sm + F_NC);

    const int tid  = threadIdx.x;
    const int wid  = tid >> 5;
    const int lane = tid & 31;
    const int tx5  = tid & 31;
    const int ty5  = tid >> 5;
    const int b0   = blockIdx.x * R1;
    const float NEG_INF = __int_as_float(0xff800000u);

    // stage obs + small weights; Wq into overlay
    for (int i = tid; i < R1 * OBS_DIM; i += NT) sObs[i] = obs[(size_t)b0 * OBS_DIM + i];
    for (int i = tid; i < INT_DIM * D; i += NT)  sIntW[i] = intW[i];
    for (int i = tid; i < OWN_DIM * D; i += NT)  sOwnW[i] = ownW[i];
    if (tid < D) { sIntB[tid] = intB[tid]; sVatt[tid] = vatt[tid]; }
    for (int i = tid; i < D * D / 4; i += NT)
        ((float4*)sW)[i] = ((const float4*)Wq)[i];
    __syncthreads();

    // own_e -> sOwnE + g_xh/g_xl[:,0:128]; pad mask -> score init
    for (int i = tid; i < R1 * D; i += NT) {
        int r = i >> 7, d = i & 127;
        const float* o = &sObs[r * OBS_DIM];
        float a = ownB[d] + o[0] * sOwnW[d] + o[1] * sOwnW[D + d] + o[2] * sOwnW[2 * D + d];
        a = lrelu(a);
        sOwnE[i] = a;
        __nv_bfloat16 h = __float2bfloat16(a);
        size_t gi = (size_t)(b0 + r) * 256 + d;
        g_xh[gi] = h;
        g_xl[gi] = __float2bfloat16(a - __bfloat162float(h));
    }
    {
        int r = tid >> 5, n = tid & 31;
        const float* p = &sObs[r * OBS_DIM + OWN_DIM + n * INT_DIM];
        float s = 0.f;
        #pragma unroll
        for (int j = 0; j < INT_DIM; j++) s += fabsf(p[j]);
        sSc[tid] = (s < 1e-6f) ? NEG_INF : 0.f;
    }
    __syncthreads();

    // q = own_e @ Wq
    {
        float a0[4] = {0.f,0.f,0.f,0.f};
        const float* ae = &sOwnE[ty5 * D];
        #pragma unroll 4
        for (int e = 0; e < D; e++) {
            float a = ae[e];
            float4 w = *(const float4*)&sW[e * D + 4 * tx5];
            a0[0] += a * w.x; a0[1] += a * w.y; a0[2] += a * w.z; a0[3] += a * w.w;
        }
        #pragma unroll
        for (int j = 0; j < 4; j++) sQ[ty5 * D + 4 * tx5 + j] = a0[j];
    }
    __syncthreads();

    // ---- compaction: prefix-sum non-padded (r,n) pairs ----
    {
        int flag = (sSc[tid] == 0.f) ? 1 : 0;
        unsigned bal = __ballot_sync(0xffffffffu, flag);
        int wpos = __popc(bal & ((1u << lane) - 1));
        if (lane == 0) sWs[wid] = __popc(bal);
        __syncthreads();
        if (tid == 0) {
            int acc = 0;
            for (int w = 0; w < 16; w++) { int t = sWs[w]; sWs[w] = acc; acc += t; }
            *sNC = acc;
        }
        __syncthreads();
        if (flag) sMap[sWs[wid] + wpos] = tid;
    }

    // B = Wk^T hi/lo: pure uint4 copy of prequantized image
    for (int i = tid; i < 2176; i += NT) {
        ((uint4*)(smc + BY_BHI))[i] = ((const uint4*)gWkHi)[i];
        ((uint4*)(smc + BY_BLO))[i] = ((const uint4*)gWkLo)[i];
    }
    __syncthreads();   // B + sMap/sNC visible to all before group-local loop

    const int n_comp = *sNC;
    const int nch = (n_comp + 127) >> 7;

    const int wr = wid >> 2, wc = wid & 3;
    const int lt = lane >> 3, lw = lane & 7;
    const uint32_t aoff = (uint32_t)(((lt & 1) * 8 + lw) * ASTR + (lt >> 1) * 16);
    const uint32_t boff = (uint32_t)((((lt >> 1) * 8 + lw) + 32 * wc) * ASTR + (lt & 1) * 16);
    const uint32_t aBase0 = smb + BY_AHI + (uint32_t)(32 * wr) * ASTR + aoff;
    const uint32_t aBase1 = aBase0 + 16 * ASTR;
    const uint32_t alBase0 = aBase0 + TILE_BYTES;
    const uint32_t alBase1 = aBase1 + TILE_BYTES;
    const uint32_t bBase0 = smb + BY_BHI + boff;
    const uint32_t bBase1 = bBase0 + 16 * ASTR;
    const uint32_t blBase0 = bBase0 + TILE_BYTES;
    const uint32_t blBase1 = bBase1 + TILE_BYTES;

    // group-local build constants: fixed d-pair per thread -> hoist weights
    const int gt  = tid & 127;          // index within wr-group (groups are contiguous)
    const int d0b = 2 * (gt & 63);
    float2 wj[INT_DIM];
    #pragma unroll
    for (int j = 0; j < INT_DIM; j++) wj[j] = *(const float2*)&sIntW[j * D + d0b];
    const float2 bb = *(const float2*)&sIntB[d0b];

    // ================= compacted chunk loop (per-group sync) =================
    for (int cc = 0; cc < nch; cc++) {
        // group wr builds ONLY its 32-row A slice (rows 32wr..32wr+31)
        for (int it = gt; it < 32 * 64; it += 128) {
            int row = 32 * wr + (it >> 6);
            int g = cc * 128 + row;
            uint32_t off = (uint32_t)row * ASTR + (uint32_t)d0b * 2;
            if (g < n_comp) {
                int pr = sMap[g];
                const float* p = &sObs[(pr >> 5) * OBS_DIM + OWN_DIM + (pr & 31) * INT_DIM];
                float2 acc = bb;
                #pragma unroll
                for (int j = 0; j < INT_DIM; j++) {
                    acc.x += p[j] * wj[j].x;
                    acc.y += p[j] * wj[j].y;
                }
                float v0 = lrelu(acc.x), v1 = lrelu(acc.y);
                float h0 = __bfloat162float(__float2bfloat16(v0));
                float h1 = __bfloat162float(__float2bfloat16(v1));
                *(uint32_t*)(smc + BY_AHI + off) = bf16pair(h0, h1);
                *(uint32_t*)(smc + BY_ALO + off) = bf16pair(v0 - h0, v1 - h1);
            } else {
                *(uint32_t*)(smc + BY_AHI + off) = 0u;
                *(uint32_t*)(smc + BY_ALO + off) = 0u;
            }
        }
        GROUP_BAR(wr + 1);

        if (cc * 128 + 32 * wr < n_comp) {  // band active (uniform per group)
            float c[2][4][4];
            #pragma unroll
            for (int mi = 0; mi < 2; mi++)
            #pragma unroll
            for (int ni = 0; ni < 4; ni++)
            #pragma unroll
            for (int j = 0; j < 4; j++) c[mi][ni][j] = 0.f;

            #pragma unroll
            for (int kk = 0; kk < 8; kk++) {
                const uint32_t ko = kk * 32;
                uint32_t ah[2][4], al[2][4], bh[2][4], bl[2][4];
                LDSM_X4(ah[0][0], ah[0][1], ah[0][2], ah[0][3], aBase0 + ko);
                LDSM_X4(ah[1][0], ah[1][1], ah[1][2], ah[1][3], aBase1 + ko);
                LDSM_X4(al[0][0], al[0][1], al[0][2], al[0][3], alBase0 + ko);
                LDSM_X4(al[1][0], al[1][1], al[1][2], al[1][3], alBase1 + ko);
                LDSM_X4(bh[0][0], bh[0][1], bh[0][2], bh[0][3], bBase0 + ko);
                LDSM_X4(bh[1][0], bh[1][1], bh[1][2], bh[1][3], bBase1 + ko);
                LDSM_X4(bl[0][0], bl[0][1], bl[0][2], bl[0][3], blBase0 + ko);
                LDSM_X4(bl[1][0], bl[1][1], bl[1][2], bl[1][3], blBase1 + ko);

                #pragma unroll
                for (int mi = 0; mi < 2; mi++)
                #pragma unroll
                for (int ni = 0; ni < 4; ni++) {
                    const uint32_t* bfh = &bh[ni >> 1][(ni & 1) * 2];
                    const uint32_t* bfl = &bl[ni >> 1][(ni & 1) * 2];
                    mma_bf16(c[mi][ni], ah[mi], bfh);
                    mma_bf16(c[mi][ni], al[mi], bfh);
                    mma_bf16(c[mi][ni], ah[mi], bfl);
                }
            }

            // epilogue: tanh scores (4 wc-warps -> atomicAdd partials; rows owned by this group)
            #pragma unroll
            for (int mi = 0; mi < 2; mi++)
            #pragma unroll
            for (int ci = 0; ci < 2; ci++) {
                int crow = 32 * wr + 16 * mi + 8 * ci + (lane >> 2);
                int g = cc * 128 + crow;
                bool ok = (g < n_comp);
                int pr = ok ? sMap[g] : 0;
                const float* qr = &sQ[(pr >> 5) * D];
                float s = 0.f;
                #pragma unroll
                for (int ni = 0; ni < 4; ni++) {
                    int col = 32 * wc + 8 * ni + 2 * (lane & 3);
                    s += tanh_ap(qr[col]     + c[mi][ni][2 * ci])     * sVatt[col];
                    s += tanh_ap(qr[col + 1] + c[mi][ni][2 * ci + 1]) * sVatt[col + 1];
                }
                s += __shfl_xor_sync(0xffffffffu, s, 1);
                s += __shfl_xor_sync(0xffffffffu, s, 2);
                if (ok && (lane & 3) == 0) atomicAdd(&sSc[pr], s);
            }
        }
        GROUP_BAR(wr + 1);   // MMA reads done before next build overwrites
    }
    __syncthreads();         // all groups' scores complete before softmax

    // softmax over 32 interactors (16 warps, 1 row each)
    {
        float s = sSc[wid * N_INTR + lane];
        float m = s;
        #pragma unroll
        for (int o = 16; o > 0; o >>= 1) m = fmaxf(m, __shfl_xor_sync(0xffffffffu, m, o));
        float e = (m == NEG_INF) ? 0.f : __expf(s - m);
        float sum = e;
        #pragma unroll
        for (int o = 16; o > 0; o >>= 1) sum += __shfl_xor_sync(0xffffffffu, sum, o);
        sAl[wid * N_INTR + lane] = (sum > 0.f) ? (e / sum) : 0.f;
    }
    __syncthreads();

    // wsum = alpha @ int_e
    {
        float wIW[INT_DIM][4];
        float wB[4];
        #pragma unroll
        for (int cq = 0; cq < 4; cq++) {
            wB[cq] = sIntB[4 * tx5 + cq];
            #pragma unroll
            for (int j = 0; j < INT_DIM; j++) wIW[j][cq] = sIntW[j * D + 4 * tx5 + cq];
        }
        float ws[4] = {0.f,0.f,0.f,0.f};
        for (int n = 0; n < N_INTR; n++) {
            float al = sAl[ty5 * N_INTR + n];
            if (al != 0.f) {
                const float* p = &sObs[ty5 * OBS_DIM + OWN_DIM + n * INT_DIM];
                float pj[INT_DIM];
                #pragma unroll
                for (int j = 0; j < INT_DIM; j++) pj[j] = p[j];
                #pragma unroll
                for (int cq = 0; cq < 4; cq++) {
                    float pre = wB[cq];
                    #pragma unroll
                    for (int j = 0; j < INT_DIM; j++) pre += pj[j] * wIW[j][cq];
                    ws[cq] += al * lrelu(pre);
                }
            }
        }
        #pragma unroll
        for (int cq = 0; cq < 4; cq++) sCtx[ty5 * D + 4 * tx5 + cq] = ws[cq];
    }
    __syncthreads();

    // ctx = wsum @ Wv -> sQ
    for (int i = tid; i < D * D / 4; i += NT)
        ((float4*)sW)[i] = ((const float4*)Wv)[i];
    __syncthreads();
    {
        float a0[4] = {0.f,0.f,0.f,0.f};
        const float* ce = &sCtx[ty5 * D];
        #pragma unroll 4
        for (int e = 0; e < D; e++) {
            float a = ce[e];
            float4 w = *(const float4*)&sW[e * D + 4 * tx5];
            a0[0] += a * w.x; a0[1] += a * w.y; a0[2] += a * w.z; a0[3] += a * w.w;
        }
        __syncthreads();
        #pragma unroll
        for (int j = 0; j < 4; j++) sQ[ty5 * D + 4 * tx5 + j] = a0[j];
    }
    __syncthreads();

    // attn_vec = tanh(ctx @ proj + b) -> g_xh/g_xl[:,128:256]
    for (int i = tid; i < D * D / 4; i += NT)
        ((float4*)sW)[i] = ((const float4*)projW)[i];
    __syncthreads();
    {
        float a0[4] = {0.f,0.f,0.f,0.f};
        const float* ce = &sQ[ty5 * D];
        #pragma unroll 4
        for (int e = 0; e < D; e++) {
            float a = ce[e];
            float4 w = *(const float4*)&sW[e * D + 4 * tx5];
            a0[0] += a * w.x; a0[1] += a * w.y; a0[2] += a * w.z; a0[3] += a * w.w;
        }
        size_t base = (size_t)(b0 + ty5) * 256 + 128;
        #pragma unroll
        for (int j = 0; j < 4; j++) {
            int c0 = 4 * tx5 + j;
            float t = tanhf(a0[j] + projB[c0]);
            __nv_bfloat16 h = __float2bfloat16(t);
            g_xh[base + c0] = h;
            g_xl[base + c0] = __float2bfloat16(t - __bfloat162float(h));
        }
    }
}

// =====================================================================
// Kernel 2: MLP on HMMA split-bf16, weights prequantized
// =====================================================================
__global__ void __launch_bounds__(NT, 1)
k_mlp(const float* __restrict__ b1, const float* __restrict__ b2,
      const float* __restrict__ Wo, const float* __restrict__ bo,
      float* __restrict__ out)
{
    extern __shared__ float sm[];
    char* smc = (char*)sm;
    const uint32_t smb = smem_u32(sm);
    float* sX = sm;                      // [64][260] fp32 (layer outputs)

    const int tid  = threadIdx.x;
    const int wid  = tid >> 5;
    const int lane = tid & 31;
    const int b0   = blockIdx.x * R2;
    const int wr = wid >> 3, wc = wid & 7;      // 2 x 8 warp grid, 32x32 C tiles
    const int lt = lane >> 3, lw = lane & 7;

    const uint32_t aoff = (uint32_t)(((lt & 1) * 8 + lw) * XSTRB + (lt >> 1) * 16);
    const uint32_t boff = (uint32_t)((32 * wc + (lt >> 1) * 8 + lw) * XSTRB + (lt & 1) * 16);
    const uint32_t aB0 = smb + M_BYXH + (uint32_t)(32 * wr) * XSTRB + aoff;
    const uint32_t aB1 = aB0 + 16 * XSTRB;
    const uint32_t aL0 = aB0 + 64 * XSTRB;
    const uint32_t aL1 = aB1 + 64 * XSTRB;
    const uint32_t bB0 = smb + M_BYWH + boff;
    const uint32_t bB1 = bB0 + 16 * XSTRB;
    const uint32_t bL0 = bB0 + 256 * XSTRB;
    const uint32_t bL1 = bB1 + 256 * XSTRB;

    for (int layer = 0; layer < 2; layer++) {
        const float* bias = layer ? b2 : b1;

        float c[2][4][4];
        #pragma unroll
        for (int mi = 0; mi < 2; mi++)
        #pragma unroll
        for (int ni = 0; ni < 4; ni++)
        #pragma unroll
        for (int j = 0; j < 4; j++) c[mi][ni][j] = 0.f;

        for (int kk = 0; kk < 4; kk++) {
            if (layer == 0) {
                int i = tid;   // 512 items, 1 per thread
                int row = i >> 3, q = i & 7;
                size_t src = (size_t)(b0 + row) * 32 + (size_t)kk * 8 + q;
                *(uint4*)(smc + M_BYXH + row * XSTRB + q * 16) = ((const uint4*)g_xh)[src];
                *(uint4*)(smc + M_BYXL + row * XSTRB + q * 16) = ((const uint4*)g_xl)[src];
            } else {
                for (int i = tid; i < 64 * 32; i += NT) {
                    int row = i >> 5, dp = i & 31, d0 = 2 * dp;
                    const float* xr = &sX[row * X_STR + kk * 64 + d0];
                    float x0 = xr[0], x1 = xr[1];
                    float h0 = __bfloat162float(__float2bfloat16(x0));
                    float h1 = __bfloat162float(__float2bfloat16(x1));
                    uint32_t off = (uint32_t)row * XSTRB + (uint32_t)d0 * 2;
                    *(uint32_t*)(smc + M_BYXH + off) = bf16pair(h0, h1);
                    *(uint32_t*)(smc + M_BYXL + off) = bf16pair(x0 - h0, x1 - h1);
                }
            }
            {
                const uint4* WH = (const uint4*)(layer ? gW2Hi[kk] : gW1Hi[kk]);
                const uint4* WL = (const uint4*)(layer ? gW2Lo[kk] : gW1Lo[kk]);
                for (int i = tid; i < 2304; i += NT) {
                    ((uint4*)(smc + M_BYWH))[i] = WH[i];
                    ((uint4*)(smc + M_BYWL))[i] = WL[i];
                }
            }
            __syncthreads();

            #pragma unroll
            for (int ks = 0; ks < 4; ks++) {
                const uint32_t ko = ks * 32;
                uint32_t ah[2][4], al[2][4], bh[2][4], bl[2][4];
                LDSM_X4(ah[0][0], ah[0][1], ah[0][2], ah[0][3], aB0 + ko);
                LDSM_X4(ah[1][0], ah[1][1], ah[1][2], ah[1][3], aB1 + ko);
                LDSM_X4(al[0][0], al[0][1], al[0][2], al[0][3], aL0 + ko);
                LDSM_X4(al[1][0], al[1][1], al[1][2], al[1][3], aL1 + ko);
                LDSM_X4(bh[0][0], bh[0][1], bh[0][2], bh[0][3], bB0 + ko);
                LDSM_X4(bh[1][0], bh[1][1], bh[1][2], bh[1][3], bB1 + ko);
                LDSM_X4(bl[0][0], bl[0][1], bl[0][2], bl[0][3], bL0 + ko);
                LDSM_X4(bl[1][0], bl[1][1], bl[1][2], bl[1][3], bL1 + ko);

                #pragma unroll
                for (int mi = 0; mi < 2; mi++)
                #pragma unroll
                for (int ni = 0; ni < 4; ni++) {
                    const uint32_t* bfh = &bh[ni >> 1][(ni & 1) * 2];
                    const uint32_t* bfl = &bl[ni >> 1][(ni & 1) * 2];
                    mma_bf16(c[mi][ni], ah[mi], bfh);
                    mma_bf16(c[mi][ni], al[mi], bfh);
                    mma_bf16(c[mi][ni], ah[mi], bfl);
                }
            }
            __syncthreads();
        }

        // epilogue: bias + lrelu -> sX
        #pragma unroll
        for (int mi = 0; mi < 2; mi++)
        #pragma unroll
        for (int ci = 0; ci < 2; ci++) {
            int row = 32 * wr + 16 * mi + 8 * ci + (lane >> 2);
            #pragma unroll
            for (int ni = 0; ni < 4; ni++) {
                int col = 32 * wc + 8 * ni + 2 * (lane & 3);
                sX[row * X_STR + col]     = lrelu(c[mi][ni][2 * ci]     + bias[col]);
                sX[row * X_STR + col + 1] = lrelu(c[mi][ni][2 * ci + 1] + bias[col + 1]);
            }
        }
        __syncthreads();
    }

    // out layer: 256 -> 2
    if (tid < R2) {
        int r = tid;
        float a0 = bo[0], a1 = bo[1];
        const float* xr = &sX[r * X_STR];
        #pragma unroll 4
        for (int e = 0; e < HID; e++) {
            float2 w = ((const float2*)Wo)[e];
            a0 += xr[e] * w.x;
            a1 += xr[e] * w.y;
        }
        out[(size_t)(b0 + r) * 2 + 0] = a0;
        out[(size_t)(b0 + r) * 2 + 1] = a1;
    }
}

extern "C" void kernel_launch(void* const* d_in, const int* in_sizes, int n_in,
                              void* d_out, int out_size)
{
    const float* obs   = (const float*)d_in[0];
    const float* ownW  = (const float*)d_in[1];
    const float* ownB  = (const float*)d_in[2];
    const float* intW  = (const float*)d_in[3];
    const float* intB  = (const float*)d_in[4];
    const float* Wq    = (const float*)d_in[5];
    const float* Wk    = (const float*)d_in[6];
    const float* Wv    = (const float*)d_in[7];
    const float* vatt  = (const float*)d_in[8];
    const float* projW = (const float*)d_in[9];
    const float* projB = (const float*)d_in[10];
    const float* W1    = (const float*)d_in[11];
    const float* b1    = (const float*)d_in[12];
    const float* W2    = (const float*)d_in[13];
    const float* b2    = (const float*)d_in[14];
    const float* Wo    = (const float*)d_in[15];
    const float* bo    = (const float*)d_in[16];
    float* out = (float*)d_out;

    cudaFuncSetAttribute(k_attn, cudaFuncAttributeMaxDynamicSharedMemorySize, SMEM1_BYTES);
    cudaFuncSetAttribute(k_mlp,  cudaFuncAttributeMaxDynamicSharedMemorySize, SMEM2_BYTES);

    k_prep<<<288, 256>>>(Wk, W1, W2);
    k_attn<<<B_TOT / R1, NT, SMEM1_BYTES>>>(obs, ownW, ownB, intW, intB,
                                            Wq, Wv, vatt, projW, projB);
    k_mlp<<<B_TOT / R2, NT, SMEM2_BYTES>>>(b1, b2, Wo, bo, out);
}

// round 10
// speedup vs baseline: 4.6167x; 1.3293x over previous
#include <cuda_runtime.h>
#include <cuda_bf16.h>
#include <math.h>
#include <stdint.h>

#define B_TOT   32768
#define OWN_DIM 3
#define N_INTR  32
#define INT_DIM 7
#define D       128
#define OBS_DIM 227
#define HID     256

#define R1      32
#define R2      64
#define X_STR   260
#define NT      512

#define ASTR    272
#define TILE_BYTES (128 * ASTR)

#define BY_AHI    1024
#define BY_ALO    (BY_AHI + TILE_BYTES)
#define BY_BHI    (BY_ALO + TILE_BYTES)
#define BY_BLO    (BY_BHI + TILE_BYTES)
#define BY_F32    (BY_BLO + TILE_BYTES)
#define F_OBS   (BY_F32 / 4)
#define F_OWNE  (F_OBS  + R1 * OBS_DIM)
#define F_Q     (F_OWNE + R1 * D)
#define F_SC    (F_Q    + R1 * D)
#define F_AL    (F_SC   + R1 * N_INTR)
#define F_INTW  (F_AL   + R1 * N_INTR)
#define F_OWNW  (F_INTW + INT_DIM * D)
#define F_INTB  (F_OWNW + OWN_DIM * D)
#define F_VATT  (F_INTB + D)
#define F_MAP   (F_VATT + D)
#define F_WS    (F_MAP + R1 * N_INTR)
#define F_NC    (F_WS + 32)
#define SMEM1_BYTES ((F_NC + 1) * 4)

#define XSTRB   144
#define M_BYXH  (R2 * X_STR * 4)
#define M_BYXL  (M_BYXH + 64 * XSTRB)
#define M_BYWH  (M_BYXL + 64 * XSTRB)
#define M_BYWL  (M_BYWH + 256 * XSTRB)
#define SMEM2_BYTES (M_BYWL + 256 * XSTRB)

__device__ uint32_t gWkHi[8704], gWkLo[8704];
__device__ uint32_t gW1Hi[4][9216], gW1Lo[4][9216];
__device__ uint32_t gW2Hi[4][9216], gW2Lo[4][9216];
__device__ float    gWvProj[D * D];
__device__ __nv_bfloat16 g_xh[(size_t)B_TOT * 256];
__device__ __nv_bfloat16 g_xl[(size_t)B_TOT * 256];

typedef unsigned long long u64;

__device__ __forceinline__ float lrelu(float x) { return fmaxf(x, 0.2f * x); }
__device__ __forceinline__ float tanh_ap(float x) {
    float y; asm("tanh.approx.f32 %0, %1;" : "=f"(y) : "f"(x)); return y;
}
__device__ __forceinline__ uint32_t smem_u32(const void* p) {
    uint32_t a;
    asm("{ .reg .u64 t; cvta.to.shared.u64 t, %1; cvt.u32.u64 %0, t; }" : "=r"(a) : "l"(p));
    return a;
}
__device__ __forceinline__ uint32_t bf16pair(float a, float b) {
    __nv_bfloat162 t = __floats2bfloat162_rn(a, b);
    return *(uint32_t*)&t;
}

#define LDSM_X4(r0, r1, r2, r3, addr) \
    asm volatile("ldmatrix.sync.aligned.m8n8.x4.shared.b16 {%0,%1,%2,%3}, [%4];" \
                 : "=r"(r0), "=r"(r1), "=r"(r2), "=r"(r3) : "r"(addr))

__device__ __forceinline__ void mma_bf16(float* c, const uint32_t* a, const uint32_t* b) {
    asm volatile(
        "mma.sync.aligned.m16n8k16.row.col.f32.bf16.bf16.f32 "
        "{%0,%1,%2,%3}, {%4,%5,%6,%7}, {%8,%9}, {%0,%1,%2,%3};"
        : "+f"(c[0]), "+f"(c[1]), "+f"(c[2]), "+f"(c[3])
        : "r"(a[0]), "r"(a[1]), "r"(a[2]), "r"(a[3]), "r"(b[0]), "r"(b[1]));
}

#define GROUP_BAR(id) \
    asm volatile("bar.sync %0, 128;" :: "r"(id) : "memory")

__global__ void __launch_bounds__(256, 4)
k_prep(const float* __restrict__ Wk, const float* __restrict__ W1,
       const float* __restrict__ W2, const float* __restrict__ Wv,
       const float* __restrict__ projW)
{
    int idx = blockIdx.x * 256 + threadIdx.x;
    if (idx < 8192) {
        int ep = idx >> 7, n = idx & 127;
        int e0 = 2 * ep;
        float w0 = Wk[e0 * D + n], w1 = Wk[(e0 + 1) * D + n];
        float h0 = __bfloat162float(__float2bfloat16(w0));
        float h1 = __bfloat162float(__float2bfloat16(w1));
        int o = n * 68 + ep;
        gWkHi[o] = bf16pair(h0, h1);
        gWkLo[o] = bf16pair(w0 - h0, w1 - h1);
    } else if (idx < 8192 + 2 * 32768) {
        int j = idx - 8192;
        const float* W = (j < 32768) ? W1 : W2;
        uint32_t* WH = (j < 32768) ? &gW1Hi[0][0] : &gW2Hi[0][0];
        uint32_t* WL = (j < 32768) ? &gW1Lo[0][0] : &gW2Lo[0][0];
        j &= 32767;
        int kk = j >> 13, r = j & 8191;
        int n = r & 255, kp = r >> 8;
        int k0 = kk * 64 + 2 * kp;
        float w0 = W[(size_t)k0 * HID + n], w1 = W[(size_t)(k0 + 1) * HID + n];
        float h0 = __bfloat162float(__float2bfloat16(w0));
        float h1 = __bfloat162float(__float2bfloat16(w1));
        int o = kk * 9216 + n * 36 + kp;
        WH[o] = bf16pair(h0, h1);
        WL[o] = bf16pair(w0 - h0, w1 - h1);
    } else if (idx < 8192 + 2 * 32768 + D * D) {
        int j = idx - (8192 + 2 * 32768);
        int f = j >> 7, c = j & 127;
        float s = 0.f;
        #pragma unroll 4
        for (int e = 0; e < D; e++)
            s += Wv[f * D + e] * projW[e * D + c];
        gWvProj[j] = s;
    }
}

__global__ void __launch_bounds__(NT, 1)
k_attn(const float* __restrict__ obs,
       const float* __restrict__ ownW, const float* __restrict__ ownB,
       const float* __restrict__ intW, const float* __restrict__ intB,
       const float* __restrict__ Wq,   const float* __restrict__ vatt,
       const float* __restrict__ projB)
{
    extern __shared__ float sm[];
    char* smc = (char*)sm;
    const uint32_t smb = smem_u32(sm);

    float* sW    = (float*)(smc + BY_AHI);
    float* sObs  = sm + F_OBS;
    float* sOwnE = sm + F_OWNE;
    float* sQ    = sm + F_Q;
    float* sSc   = sm + F_SC;
    float* sAl   = sm + F_AL;
    float* sIntW = sm + F_INTW;
    float* sOwnW = sm + F_OWNW;
    float* sIntB = sm + F_INTB;
    float* sVatt = sm + F_VATT;
    int*   sMap  = (int*)(sm + F_MAP);
    int*   sWs   = (int*)(sm + F_WS);
    int*   sNC   = (int*)(sm + F_NC);

    const int tid  = threadIdx.x;
    const int wid  = tid >> 5;
    const int lane = tid & 31;
    const int tx5  = tid & 31;
    const int ty5  = tid >> 5;
    const int b0   = blockIdx.x * R1;
    const float NEG_INF = __int_as_float(0xff800000u);

    for (int i = tid; i < R1 * OBS_DIM; i += NT) sObs[i] = obs[(size_t)b0 * OBS_DIM + i];
    for (int i = tid; i < INT_DIM * D; i += NT)  sIntW[i] = intW[i];
    for (int i = tid; i < OWN_DIM * D; i += NT)  sOwnW[i] = ownW[i];
    if (tid < D) { sIntB[tid] = intB[tid]; sVatt[tid] = vatt[tid]; }
    for (int i = tid; i < D * D / 4; i += NT)
        ((float4*)sW)[i] = ((const float4*)Wq)[i];
    __syncthreads();

    for (int i = tid; i < R1 * D; i += NT) {
        int r = i >> 7, d = i & 127;
        const float* o = &sObs[r * OBS_DIM];
        float a = ownB[d] + o[0] * sOwnW[d] + o[1] * sOwnW[D + d] + o[2] * sOwnW[2 * D + d];
        a = lrelu(a);
        sOwnE[i] = a;
        __nv_bfloat16 h = __float2bfloat16(a);
        size_t gi = (size_t)(b0 + r) * 256 + d;
        g_xh[gi] = h;
        g_xl[gi] = __float2bfloat16(a - __bfloat162float(h));
    }
    for (int i = tid; i < R1 * N_INTR; i += NT) {
        int r = i >> 5, n = i & 31;
        const float* p = &sObs[r * OBS_DIM + OWN_DIM + n * INT_DIM];
        float s = 0.f;
        #pragma unroll
        for (int j = 0; j < INT_DIM; j++) s += fabsf(p[j]);
        sSc[i] = (s < 1e-6f) ? NEG_INF : 0.f;
    }
    __syncthreads();

    // q = own_e @ Wq (2 rows per thread)
    {
        float a0[4] = {0.f,0.f,0.f,0.f}, a1[4] = {0.f,0.f,0.f,0.f};
        const float* ae0 = &sOwnE[ty5 * D];
        const float* ae1 = &sOwnE[(ty5 + 16) * D];
        #pragma unroll 4
        for (int e = 0; e < D; e++) {
            float v0 = ae0[e], v1 = ae1[e];
            float4 w = *(const float4*)&sW[e * D + 4 * tx5];
            a0[0] += v0 * w.x; a0[1] += v0 * w.y; a0[2] += v0 * w.z; a0[3] += v0 * w.w;
            a1[0] += v1 * w.x; a1[1] += v1 * w.y; a1[2] += v1 * w.z; a1[3] += v1 * w.w;
        }
        #pragma unroll
        for (int j = 0; j < 4; j++) {
            sQ[ty5 * D + 4 * tx5 + j]        = a0[j];
            sQ[(ty5 + 16) * D + 4 * tx5 + j] = a1[j];
        }
    }
    __syncthreads();

    // compaction over 1024 (r,n) pairs
    {
        int flag0 = (sSc[tid] == 0.f) ? 1 : 0;
        int flag1 = (sSc[tid + 512] == 0.f) ? 1 : 0;
        unsigned bal0 = __ballot_sync(0xffffffffu, flag0);
        unsigned bal1 = __ballot_sync(0xffffffffu, flag1);
        int wpos0 = __popc(bal0 & ((1u << lane) - 1));
        int wpos1 = __popc(bal1 & ((1u << lane) - 1));
        if (lane == 0) { sWs[wid] = __popc(bal0); sWs[16 + wid] = __popc(bal1); }
        __syncthreads();
        if (tid == 0) {
            int acc = 0;
            for (int w = 0; w < 32; w++) { int t = sWs[w]; sWs[w] = acc; acc += t; }
            *sNC = acc;
        }
        __syncthreads();
        if (flag0) sMap[sWs[wid] + wpos0]      = tid;
        if (flag1) sMap[sWs[16 + wid] + wpos1] = tid + 512;
    }

    for (int i = tid; i < 2176; i += NT) {
        ((uint4*)(smc + BY_BHI))[i] = ((const uint4*)gWkHi)[i];
        ((uint4*)(smc + BY_BLO))[i] = ((const uint4*)gWkLo)[i];
    }
    __syncthreads();

    const int n_comp = *sNC;
    const int nch = (n_comp + 127) >> 7;

    const int wr = wid >> 2, wc = wid & 3;
    const int lt = lane >> 3, lw = lane & 7;
    const uint32_t aoff = (uint32_t)(((lt & 1) * 8 + lw) * ASTR + (lt >> 1) * 16);
    const uint32_t boff = (uint32_t)((((lt >> 1) * 8 + lw) + 32 * wc) * ASTR + (lt & 1) * 16);
    const uint32_t aBase0 = smb + BY_AHI + (uint32_t)(32 * wr) * ASTR + aoff;
    const uint32_t aBase1 = aBase0 + 16 * ASTR;
    const uint32_t alBase0 = aBase0 + TILE_BYTES;
    const uint32_t alBase1 = aBase1 + TILE_BYTES;
    const uint32_t bBase0 = smb + BY_BHI + boff;
    const uint32_t bBase1 = bBase0 + 16 * ASTR;
    const uint32_t blBase0 = bBase0 + TILE_BYTES;
    const uint32_t blBase1 = bBase1 + TILE_BYTES;

    const int gt  = tid & 127;
    const int d0b = 2 * (gt & 63);
    float2 wj[INT_DIM];
    #pragma unroll
    for (int j = 0; j < INT_DIM; j++) wj[j] = *(const float2*)&sIntW[j * D + d0b];
    const float2 bb = *(const float2*)&sIntB[d0b];

    for (int cc = 0; cc < nch; cc++) {
        for (int it = gt; it < 32 * 64; it += 128) {
            int row = 32 * wr + (it >> 6);
            int g = cc * 128 + row;
            uint32_t off = (uint32_t)row * ASTR + (uint32_t)d0b * 2;
            if (g < n_comp) {
                int pr = sMap[g];
                const float* p = &sObs[(pr >> 5) * OBS_DIM + OWN_DIM + (pr & 31) * INT_DIM];
                float2 acc = bb;
                #pragma unroll
                for (int j = 0; j < INT_DIM; j++) {
                    acc.x += p[j] * wj[j].x;
                    acc.y += p[j] * wj[j].y;
                }
                float v0 = lrelu(acc.x), v1 = lrelu(acc.y);
                float h0 = __bfloat162float(__float2bfloat16(v0));
                float h1 = __bfloat162float(__float2bfloat16(v1));
                *(uint32_t*)(smc + BY_AHI + off) = bf16pair(h0, h1);
                *(uint32_t*)(smc + BY_ALO + off) = bf16pair(v0 - h0, v1 - h1);
            } else {
                *(uint32_t*)(smc + BY_AHI + off) = 0u;
                *(uint32_t*)(smc + BY_ALO + off) = 0u;
            }
        }
        GROUP_BAR(wr + 1);

        if (cc * 128 + 32 * wr < n_comp) {
            float c[2][4][4];
            #pragma unroll
            for (int mi = 0; mi < 2; mi++)
            #pragma unroll
            for (int ni = 0; ni < 4; ni++)
            #pragma unroll
            for (int j = 0; j < 4; j++) c[mi][ni][j] = 0.f;

            #pragma unroll
            for (int kk = 0; kk < 8; kk++) {
                const uint32_t ko = kk * 32;
                uint32_t ah[2][4], al[2][4], bh[2][4], bl[2][4];
                LDSM_X4(ah[0][0], ah[0][1], ah[0][2], ah[0][3], aBase0 + ko);
                LDSM_X4(ah[1][0], ah[1][1], ah[1][2], ah[1][3], aBase1 + ko);
                LDSM_X4(al[0][0], al[0][1], al[0][2], al[0][3], alBase0 + ko);
                LDSM_X4(al[1][0], al[1][1], al[1][2], al[1][3], alBase1 + ko);
                LDSM_X4(bh[0][0], bh[0][1], bh[0][2], bh[0][3], bBase0 + ko);
                LDSM_X4(bh[1][0], bh[1][1], bh[1][2], bh[1][3], bBase1 + ko);
                LDSM_X4(bl[0][0], bl[0][1], bl[0][2], bl[0][3], blBase0 + ko);
                LDSM_X4(bl[1][0], bl[1][1], bl[1][2], bl[1][3], blBase1 + ko);

                #pragma unroll
                for (int mi = 0; mi < 2; mi++)
                #pragma unroll
                for (int ni = 0; ni < 4; ni++) {
                    const uint32_t* bfh = &bh[ni >> 1][(ni & 1) * 2];
                    const uint32_t* bfl = &bl[ni >> 1][(ni & 1) * 2];
                    mma_bf16(c[mi][ni], ah[mi], bfh);
                    mma_bf16(c[mi][ni], al[mi], bfh);
                    mma_bf16(c[mi][ni], ah[mi], bfl);
                }
            }

            #pragma unroll
            for (int mi = 0; mi < 2; mi++)
            #pragma unroll
            for (int ci = 0; ci < 2; ci++) {
                int crow = 32 * wr + 16 * mi + 8 * ci + (lane >> 2);
                int g = cc * 128 + crow;
                bool ok = (g < n_comp);
                int pr = ok ? sMap[g] : 0;
                const float* qr = &sQ[(pr >> 5) * D];
                float s = 0.f;
                #pragma unroll
                for (int ni = 0; ni < 4; ni++) {
                    int col = 32 * wc + 8 * ni + 2 * (lane & 3);
                    s += tanh_ap(qr[col]     + c[mi][ni][2 * ci])     * sVatt[col];
                    s += tanh_ap(qr[col + 1] + c[mi][ni][2 * ci + 1]) * sVatt[col + 1];
                }
                s += __shfl_xor_sync(0xffffffffu, s, 1);
                s += __shfl_xor_sync(0xffffffffu, s, 2);
                if (ok && (lane & 3) == 0) atomicAdd(&sSc[pr], s);
            }
        }
        GROUP_BAR(wr + 1);
    }
    __syncthreads();

    // softmax (32 rows / 16 warps) + WvProj copy into freed A region
    for (int r = wid; r < R1; r += 16) {
        float s = sSc[r * N_INTR + lane];
        float m = s;
        #pragma unroll
        for (int o = 16; o > 0; o >>= 1) m = fmaxf(m, __shfl_xor_sync(0xffffffffu, m, o));
        float e = (m == NEG_INF) ? 0.f : __expf(s - m);
        float sum = e;
        #pragma unroll
        for (int o = 16; o > 0; o >>= 1) sum += __shfl_xor_sync(0xffffffffu, sum, o);
        sAl[r * N_INTR + lane] = (sum > 0.f) ? (e / sum) : 0.f;
    }
    for (int i = tid; i < D * D / 4; i += NT)
        ((float4*)sW)[i] = ((const float4*)gWvProj)[i];
    __syncthreads();

    // wsum = alpha @ int_e (2 rows per thread) -> sOwnE overlay
    {
        float wIW[INT_DIM][4];
        float wB[4];
        #pragma unroll
        for (int cq = 0; cq < 4; cq++) {
            wB[cq] = sIntB[4 * tx5 + cq];
            #pragma unroll
            for (int j = 0; j < INT_DIM; j++) wIW[j][cq] = sIntW[j * D + 4 * tx5 + cq];
        }
        #pragma unroll
        for (int rr = 0; rr < 2; rr++) {
            int r = ty5 + 16 * rr;
            float ws[4] = {0.f,0.f,0.f,0.f};
            for (int n = 0; n < N_INTR; n++) {
                float al = sAl[r * N_INTR + n];
                if (al != 0.f) {
                    const float* p = &sObs[r * OBS_DIM + OWN_DIM + n * INT_DIM];
                    float pj[INT_DIM];
                    #pragma unroll
                    for (int j = 0; j < INT_DIM; j++) pj[j] = p[j];
                    #pragma unroll
                    for (int cq = 0; cq < 4; cq++) {
                        float pre = wB[cq];
                        #pragma unroll
                        for (int j = 0; j < INT_DIM; j++) pre += pj[j] * wIW[j][cq];
                        ws[cq] += al * lrelu(pre);
                    }
                }
            }
            #pragma unroll
            for (int cq = 0; cq < 4; cq++) sOwnE[r * D + 4 * tx5 + cq] = ws[cq];
        }
    }
    __syncthreads();

    // attn_vec = tanh(wsum @ WvProj + projB) -> g_xh/g_xl[:,128:256]
    {
        float a0[4] = {0.f,0.f,0.f,0.f}, a1[4] = {0.f,0.f,0.f,0.f};
        const float* ce0 = &sOwnE[ty5 * D];
        const float* ce1 = &sOwnE[(ty5 + 16) * D];
        #pragma unroll 4
        for (int e = 0; e < D; e++) {
            float v0 = ce0[e], v1 = ce1[e];
            float4 w = *(const float4*)&sW[e * D + 4 * tx5];
            a0[0] += v0 * w.x; a0[1] += v0 * w.y; a0[2] += v0 * w.z; a0[3] += v0 * w.w;
            a1[0] += v1 * w.x; a1[1] += v1 * w.y; a1[2] += v1 * w.z; a1[3] += v1 * w.w;
        }
        size_t base0 = (size_t)(b0 + ty5) * 256 + 128;
        size_t base1 = (size_t)(b0 + ty5 + 16) * 256 + 128;
        #pragma unroll
        for (int j = 0; j < 4; j++) {
            int c0 = 4 * tx5 + j;
            float t0 = tanhf(a0[j] + projB[c0]);
            float t1 = tanhf(a1[j] + projB[c0]);
            __nv_bfloat16 h0 = __float2bfloat16(t0);
            __nv_bfloat16 h1 = __float2bfloat16(t1);
            g_xh[base0 + c0] = h0;
            g_xl[base0 + c0] = __float2bfloat16(t0 - __bfloat162float(h0));
            g_xh[base1 + c0] = h1;
            g_xl[base1 + c0] = __float2bfloat16(t1 - __bfloat162float(h1));
        }
    }
}

__global__ void __launch_bounds__(NT, 1)
k_mlp(const float* __restrict__ b1, const float* __restrict__ b2,
      const float* __restrict__ Wo, const float* __restrict__ bo,
      float* __restrict__ out)
{
    extern __shared__ float sm[];
    char* smc = (char*)sm;
    const uint32_t smb = smem_u32(sm);
    float* sX = sm;

    const int tid  = threadIdx.x;
    const int wid  = tid >> 5;
    const int lane = tid & 31;
    const int b0   = blockIdx.x * R2;
    const int wr = wid >> 3, wc = wid & 7;
    const int lt = lane >> 3, lw = lane & 7;

    const uint32_t aoff = (uint32_t)(((lt & 1) * 8 + lw) * XSTRB + (lt >> 1) * 16);
    const uint32_t boff = (uint32_t)((32 * wc + (lt >> 1) * 8 + lw) * XSTRB + (lt & 1) * 16);
    const uint32_t aB0 = smb + M_BYXH + (uint32_t)(32 * wr) * XSTRB + aoff;
    const uint32_t aB1 = aB0 + 16 * XSTRB;
    const uint32_t aL0 = aB0 + 64 * XSTRB;
    const uint32_t aL1 = aB1 + 64 * XSTRB;
    const uint32_t bB0 = smb + M_BYWH + boff;
    const uint32_t bB1 = bB0 + 16 * XSTRB;
    const uint32_t bL0 = bB0 + 256 * XSTRB;
    const uint32_t bL1 = bB1 + 256 * XSTRB;

    for (int layer = 0; layer < 2; layer++) {
        const float* bias = layer ? b2 : b1;

        float c[2][4][4];
        #pragma unroll
        for (int mi = 0; mi < 2; mi++)
        #pragma unroll
        for (int ni = 0; ni < 4; ni++)
        #pragma unroll
        for (int j = 0; j < 4; j++) c[mi][ni][j] = 0.f;

        for (int kk = 0; kk < 4; kk++) {
            if (layer == 0) {
                int i = tid;
                int row = i >> 3, q = i & 7;
                size_t src = (size_t)(b0 + row) * 32 + (size_t)kk * 8 + q;
                *(uint4*)(smc + M_BYXH + row * XSTRB + q * 16) = ((const uint4*)g_xh)[src];
                *(uint4*)(smc + M_BYXL + row * XSTRB + q * 16) = ((const uint4*)g_xl)[src];
            } else {
                for (int i = tid; i < 64 * 32; i += NT) {
                    int row = i >> 5, dp = i & 31, d0 = 2 * dp;
                    const float* xr = &sX[row * X_STR + kk * 64 + d0];
                    float x0 = xr[0], x1 = xr[1];
                    float h0 = __bfloat162float(__float2bfloat16(x0));
                    float h1 = __bfloat162float(__float2bfloat16(x1));
                    uint32_t off = (uint32_t)row * XSTRB + (uint32_t)d0 * 2;
                    *(uint32_t*)(smc + M_BYXH + off) = bf16pair(h0, h1);
                    *(uint32_t*)(smc + M_BYXL + off) = bf16pair(x0 - h0, x1 - h1);
                }
            }
            {
                const uint4* WH = (const uint4*)(layer ? gW2Hi[kk] : gW1Hi[kk]);
                const uint4* WL = (const uint4*)(layer ? gW2Lo[kk] : gW1Lo[kk]);
                for (int i = tid; i < 2304; i += NT) {
                    ((uint4*)(smc + M_BYWH))[i] = WH[i];
                    ((uint4*)(smc + M_BYWL))[i] = WL[i];
                }
            }
            __syncthreads();

            #pragma unroll
            for (int ks = 0; ks < 4; ks++) {
                const uint32_t ko = ks * 32;
                uint32_t ah[2][4], al[2][4], bh[2][4], bl[2][4];
                LDSM_X4(ah[0][0], ah[0][1], ah[0][2], ah[0][3], aB0 + ko);
                LDSM_X4(ah[1][0], ah[1][1], ah[1][2], ah[1][3], aB1 + ko);
                LDSM_X4(al[0][0], al[0][1], al[0][2], al[0][3], aL0 + ko);
                LDSM_X4(al[1][0], al[1][1], al[1][2], al[1][3], aL1 + ko);
                LDSM_X4(bh[0][0], bh[0][1], bh[0][2], bh[0][3], bB0 + ko);
                LDSM_X4(bh[1][0], bh[1][1], bh[1][2], bh[1][3], bB1 + ko);
                LDSM_X4(bl[0][0], bl[0][1], bl[0][2], bl[0][3], bL0 + ko);
                LDSM_X4(bl[1][0], bl[1][1], bl[1][2], bl[1][3], bL1 + ko);

                #pragma unroll
                for (int mi = 0; mi < 2; mi++)
                #pragma unroll
                for (int ni = 0; ni < 4; ni++) {
                    const uint32_t* bfh = &bh[ni >> 1][(ni & 1) * 2];
                    const uint32_t* bfl = &bl[ni >> 1][(ni & 1) * 2];
                    mma_bf16(c[mi][ni], ah[mi], bfh);
                    mma_bf16(c[mi][ni], al[mi], bfh);
                    mma_bf16(c[mi][ni], ah[mi], bfl);
                }
            }
            __syncthreads();
        }

        #pragma unroll
        for (int mi = 0; mi < 2; mi++)
        #pragma unroll
        for (int ci = 0; ci < 2; ci++) {
            int row = 32 * wr + 16 * mi + 8 * ci + (lane >> 2);
            #pragma unroll
            for (int ni = 0; ni < 4; ni++) {
                int col = 32 * wc + 8 * ni + 2 * (lane & 3);
                sX[row * X_STR + col]     = lrelu(c[mi][ni][2 * ci]     + bias[col]);
                sX[row * X_STR + col + 1] = lrelu(c[mi][ni][2 * ci + 1] + bias[col + 1]);
            }
        }
        __syncthreads();
    }

    // out layer: 256 -> 2, warp-parallel shuffle reduce (4 rows/warp)
    {
        float bo0 = bo[0], bo1 = bo[1];
        #pragma unroll
        for (int rr = 0; rr < 4; rr++) {
            int r = wid * 4 + rr;
            const float* xr = &sX[r * X_STR + lane * 8];
            float a0 = 0.f, a1 = 0.f;
            #pragma unroll
            for (int k = 0; k < 8; k++) {
                float x = xr[k];
                float2 w = ((const float2*)Wo)[lane * 8 + k];
                a0 += x * w.x;
                a1 += x * w.y;
            }
            #pragma unroll
            for (int o = 16; o > 0; o >>= 1) {
                a0 += __shfl_xor_sync(0xffffffffu, a0, o);
                a1 += __shfl_xor_sync(0xffffffffu, a1, o);
            }
            if (lane == 0) {
                out[(size_t)(b0 + r) * 2 + 0] = a0 + bo0;
                out[(size_t)(b0 + r) * 2 + 1] = a1 + bo1;
            }
        }
    }
}

extern "C" void kernel_launch(void* const* d_in, const int* in_sizes, int n_in,
                              void* d_out, int out_size)
{
    const float* obs   = (const float*)d_in[0];
    const float* ownW  = (const float*)d_in[1];
    const float* ownB  = (const float*)d_in[2];
    const float* intW  = (const float*)d_in[3];
    const float* intB  = (const float*)d_in[4];
    const float* Wq    = (const float*)d_in[5];
    const float* Wk    = (const float*)d_in[6];
    const float* Wv    = (const float*)d_in[7];
    const float* vatt  = (const float*)d_in[8];
    const float* projW = (const float*)d_in[9];
    const float* projB = (const float*)d_in[10];
    const float* W1    = (const float*)d_in[11];
    const float* b1    = (const float*)d_in[12];
    const float* W2    = (const float*)d_in[13];
    const float* b2    = (const float*)d_in[14];
    const float* Wo    = (const float*)d_in[15];
    const float* bo    = (const float*)d_in[16];
    float* out = (float*)d_out;

    cudaFuncSetAttribute(k_attn, cudaFuncAttributeMaxDynamicSharedMemorySize, SMEM1_BYTES);
    cudaFuncSetAttribute(k_mlp,  cudaFuncAttributeMaxDynamicSharedMemorySize, SMEM2_BYTES);

    k_prep<<<352, 256>>>(Wk, W1, W2, Wv, projW);
    k_attn<<<B_TOT / R1, NT, SMEM1_BYTES>>>(obs, ownW, ownB, intW, intB, Wq, vatt, projB);
    k_mlp<<<B_TOT / R2, NT, SMEM2_BYTES>>>(b1, b2, Wo, bo, out);
}

// round 11
// speedup vs baseline: 4.8071x; 1.0412x over previous
#include <cuda_runtime.h>
#include <cuda_bf16.h>
#include <math.h>
#include <stdint.h>

#define B_TOT   32768
#define OWN_DIM 3
#define N_INTR  32
#define INT_DIM 7
#define D       128
#define OBS_DIM 227
#define HID     256

#define R1      32
#define R2      128
#define X_STR   260
#define NT      512

#define ASTR    272
#define TILE_BYTES (128 * ASTR)

#define BY_AHI    1024
#define BY_ALO    (BY_AHI + TILE_BYTES)
#define BY_BHI    (BY_ALO + TILE_BYTES)
#define BY_BLO    (BY_BHI + TILE_BYTES)
#define BY_F32    (BY_BLO + TILE_BYTES)
#define F_OBS   (BY_F32 / 4)
#define F_OWNE  (F_OBS  + R1 * OBS_DIM)
#define F_Q     (F_OWNE + R1 * D)
#define F_SC    (F_Q    + R1 * D)
#define F_AL    (F_SC   + R1 * N_INTR)
#define F_INTW  (F_AL   + R1 * N_INTR)
#define F_OWNW  (F_INTW + INT_DIM * D)
#define F_INTB  (F_OWNW + OWN_DIM * D)
#define F_VATT  (F_INTB + D)
#define F_MAP   (F_VATT + D)
#define F_WS    (F_MAP + R1 * N_INTR)
#define F_NC    (F_WS + 32)
#define SMEM1_BYTES ((F_NC + 1) * 4)

// ---- k_mlp smem (bytes): X resident as bf16 hi/lo, 4 k-chunks ----
#define XSTRB   144
#define XCH     (R2 * XSTRB)            // 18432 per chunk
#define M_XH    0
#define M_XL    (4 * XCH)               // 73728
#define M_WH    (8 * XCH)               // 147456
#define M_WL    (M_WH + 256 * XSTRB)    // 184320
#define SMEM2_BYTES (M_WL + 256 * XSTRB) // 221184

__device__ uint32_t gWkHi[8704], gWkLo[8704];
__device__ uint32_t gW1Hi[4][9216], gW1Lo[4][9216];
__device__ uint32_t gW2Hi[4][9216], gW2Lo[4][9216];
__device__ float    gWvProj[D * D];
__device__ __nv_bfloat16 g_xh[(size_t)B_TOT * 256];
__device__ __nv_bfloat16 g_xl[(size_t)B_TOT * 256];

typedef unsigned long long u64;

__device__ __forceinline__ float lrelu(float x) { return fmaxf(x, 0.2f * x); }
__device__ __forceinline__ float tanh_ap(float x) {
    float y; asm("tanh.approx.f32 %0, %1;" : "=f"(y) : "f"(x)); return y;
}
__device__ __forceinline__ uint32_t smem_u32(const void* p) {
    uint32_t a;
    asm("{ .reg .u64 t; cvta.to.shared.u64 t, %1; cvt.u32.u64 %0, t; }" : "=r"(a) : "l"(p));
    return a;
}
__device__ __forceinline__ uint32_t bf16pair(float a, float b) {
    __nv_bfloat162 t = __floats2bfloat162_rn(a, b);
    return *(uint32_t*)&t;
}

#define LDSM_X4(r0, r1, r2, r3, addr) \
    asm volatile("ldmatrix.sync.aligned.m8n8.x4.shared.b16 {%0,%1,%2,%3}, [%4];" \
                 : "=r"(r0), "=r"(r1), "=r"(r2), "=r"(r3) : "r"(addr))

__device__ __forceinline__ void mma_bf16(float* c, const uint32_t* a, const uint32_t* b) {
    asm volatile(
        "mma.sync.aligned.m16n8k16.row.col.f32.bf16.bf16.f32 "
        "{%0,%1,%2,%3}, {%4,%5,%6,%7}, {%8,%9}, {%0,%1,%2,%3};"
        : "+f"(c[0]), "+f"(c[1]), "+f"(c[2]), "+f"(c[3])
        : "r"(a[0]), "r"(a[1]), "r"(a[2]), "r"(a[3]), "r"(b[0]), "r"(b[1]));
}

#define GROUP_BAR(id) \
    asm volatile("bar.sync %0, 128;" :: "r"(id) : "memory")

// =====================================================================
// Prep (unchanged from R10)
// =====================================================================
__global__ void __launch_bounds__(256, 4)
k_prep(const float* __restrict__ Wk, const float* __restrict__ W1,
       const float* __restrict__ W2, const float* __restrict__ Wv,
       const float* __restrict__ projW)
{
    int idx = blockIdx.x * 256 + threadIdx.x;
    if (idx < 8192) {
        int ep = idx >> 7, n = idx & 127;
        int e0 = 2 * ep;
        float w0 = Wk[e0 * D + n], w1 = Wk[(e0 + 1) * D + n];
        float h0 = __bfloat162float(__float2bfloat16(w0));
        float h1 = __bfloat162float(__float2bfloat16(w1));
        int o = n * 68 + ep;
        gWkHi[o] = bf16pair(h0, h1);
        gWkLo[o] = bf16pair(w0 - h0, w1 - h1);
    } else if (idx < 8192 + 2 * 32768) {
        int j = idx - 8192;
        const float* W = (j < 32768) ? W1 : W2;
        uint32_t* WH = (j < 32768) ? &gW1Hi[0][0] : &gW2Hi[0][0];
        uint32_t* WL = (j < 32768) ? &gW1Lo[0][0] : &gW2Lo[0][0];
        j &= 32767;
        int kk = j >> 13, r = j & 8191;
        int n = r & 255, kp = r >> 8;
        int k0 = kk * 64 + 2 * kp;
        float w0 = W[(size_t)k0 * HID + n], w1 = W[(size_t)(k0 + 1) * HID + n];
        float h0 = __bfloat162float(__float2bfloat16(w0));
        float h1 = __bfloat162float(__float2bfloat16(w1));
        int o = kk * 9216 + n * 36 + kp;
        WH[o] = bf16pair(h0, h1);
        WL[o] = bf16pair(w0 - h0, w1 - h1);
    } else if (idx < 8192 + 2 * 32768 + D * D) {
        int j = idx - (8192 + 2 * 32768);
        int f = j >> 7, c = j & 127;
        float s = 0.f;
        #pragma unroll 4
        for (int e = 0; e < D; e++)
            s += Wv[f * D + e] * projW[e * D + c];
        gWvProj[j] = s;
    }
}

// =====================================================================
// Kernel 1 (unchanged from R10)
// =====================================================================
__global__ void __launch_bounds__(NT, 1)
k_attn(const float* __restrict__ obs,
       const float* __restrict__ ownW, const float* __restrict__ ownB,
       const float* __restrict__ intW, const float* __restrict__ intB,
       const float* __restrict__ Wq,   const float* __restrict__ vatt,
       const float* __restrict__ projB)
{
    extern __shared__ float sm[];
    char* smc = (char*)sm;
    const uint32_t smb = smem_u32(sm);

    float* sW    = (float*)(smc + BY_AHI);
    float* sObs  = sm + F_OBS;
    float* sOwnE = sm + F_OWNE;
    float* sQ    = sm + F_Q;
    float* sSc   = sm + F_SC;
    float* sAl   = sm + F_AL;
    float* sIntW = sm + F_INTW;
    float* sOwnW = sm + F_OWNW;
    float* sIntB = sm + F_INTB;
    float* sVatt = sm + F_VATT;
    int*   sMap  = (int*)(sm + F_MAP);
    int*   sWs   = (int*)(sm + F_WS);
    int*   sNC   = (int*)(sm + F_NC);

    const int tid  = threadIdx.x;
    const int wid  = tid >> 5;
    const int lane = tid & 31;
    const int tx5  = tid & 31;
    const int ty5  = tid >> 5;
    const int b0   = blockIdx.x * R1;
    const float NEG_INF = __int_as_float(0xff800000u);

    for (int i = tid; i < R1 * OBS_DIM; i += NT) sObs[i] = obs[(size_t)b0 * OBS_DIM + i];
    for (int i = tid; i < INT_DIM * D; i += NT)  sIntW[i] = intW[i];
    for (int i = tid; i < OWN_DIM * D; i += NT)  sOwnW[i] = ownW[i];
    if (tid < D) { sIntB[tid] = intB[tid]; sVatt[tid] = vatt[tid]; }
    for (int i = tid; i < D * D / 4; i += NT)
        ((float4*)sW)[i] = ((const float4*)Wq)[i];
    __syncthreads();

    for (int i = tid; i < R1 * D; i += NT) {
        int r = i >> 7, d = i & 127;
        const float* o = &sObs[r * OBS_DIM];
        float a = ownB[d] + o[0] * sOwnW[d] + o[1] * sOwnW[D + d] + o[2] * sOwnW[2 * D + d];
        a = lrelu(a);
        sOwnE[i] = a;
        __nv_bfloat16 h = __float2bfloat16(a);
        size_t gi = (size_t)(b0 + r) * 256 + d;
        g_xh[gi] = h;
        g_xl[gi] = __float2bfloat16(a - __bfloat162float(h));
    }
    for (int i = tid; i < R1 * N_INTR; i += NT) {
        int r = i >> 5, n = i & 31;
        const float* p = &sObs[r * OBS_DIM + OWN_DIM + n * INT_DIM];
        float s = 0.f;
        #pragma unroll
        for (int j = 0; j < INT_DIM; j++) s += fabsf(p[j]);
        sSc[i] = (s < 1e-6f) ? NEG_INF : 0.f;
    }
    __syncthreads();

    {
        float a0[4] = {0.f,0.f,0.f,0.f}, a1[4] = {0.f,0.f,0.f,0.f};
        const float* ae0 = &sOwnE[ty5 * D];
        const float* ae1 = &sOwnE[(ty5 + 16) * D];
        #pragma unroll 4
        for (int e = 0; e < D; e++) {
            float v0 = ae0[e], v1 = ae1[e];
            float4 w = *(const float4*)&sW[e * D + 4 * tx5];
            a0[0] += v0 * w.x; a0[1] += v0 * w.y; a0[2] += v0 * w.z; a0[3] += v0 * w.w;
            a1[0] += v1 * w.x; a1[1] += v1 * w.y; a1[2] += v1 * w.z; a1[3] += v1 * w.w;
        }
        #pragma unroll
        for (int j = 0; j < 4; j++) {
            sQ[ty5 * D + 4 * tx5 + j]        = a0[j];
            sQ[(ty5 + 16) * D + 4 * tx5 + j] = a1[j];
        }
    }
    __syncthreads();

    {
        int flag0 = (sSc[tid] == 0.f) ? 1 : 0;
        int flag1 = (sSc[tid + 512] == 0.f) ? 1 : 0;
        unsigned bal0 = __ballot_sync(0xffffffffu, flag0);
        unsigned bal1 = __ballot_sync(0xffffffffu, flag1);
        int wpos0 = __popc(bal0 & ((1u << lane) - 1));
        int wpos1 = __popc(bal1 & ((1u << lane) - 1));
        if (lane == 0) { sWs[wid] = __popc(bal0); sWs[16 + wid] = __popc(bal1); }
        __syncthreads();
        if (tid == 0) {
            int acc = 0;
            for (int w = 0; w < 32; w++) { int t = sWs[w]; sWs[w] = acc; acc += t; }
            *sNC = acc;
        }
        __syncthreads();
        if (flag0) sMap[sWs[wid] + wpos0]      = tid;
        if (flag1) sMap[sWs[16 + wid] + wpos1] = tid + 512;
    }

    for (int i = tid; i < 2176; i += NT) {
        ((uint4*)(smc + BY_BHI))[i] = ((const uint4*)gWkHi)[i];
        ((uint4*)(smc + BY_BLO))[i] = ((const uint4*)gWkLo)[i];
    }
    __syncthreads();

    const int n_comp = *sNC;
    const int nch = (n_comp + 127) >> 7;

    const int wr = wid >> 2, wc = wid & 3;
    const int lt = lane >> 3, lw = lane & 7;
    const uint32_t aoff = (uint32_t)(((lt & 1) * 8 + lw) * ASTR + (lt >> 1) * 16);
    const uint32_t boff = (uint32_t)((((lt >> 1) * 8 + lw) + 32 * wc) * ASTR + (lt & 1) * 16);
    const uint32_t aBase0 = smb + BY_AHI + (uint32_t)(32 * wr) * ASTR + aoff;
    const uint32_t aBase1 = aBase0 + 16 * ASTR;
    const uint32_t alBase0 = aBase0 + TILE_BYTES;
    const uint32_t alBase1 = aBase1 + TILE_BYTES;
    const uint32_t bBase0 = smb + BY_BHI + boff;
    const uint32_t bBase1 = bBase0 + 16 * ASTR;
    const uint32_t blBase0 = bBase0 + TILE_BYTES;
    const uint32_t blBase1 = bBase1 + TILE_BYTES;

    const int gt  = tid & 127;
    const int d0b = 2 * (gt & 63);
    float2 wj[INT_DIM];
    #pragma unroll
    for (int j = 0; j < INT_DIM; j++) wj[j] = *(const float2*)&sIntW[j * D + d0b];
    const float2 bb = *(const float2*)&sIntB[d0b];

    for (int cc = 0; cc < nch; cc++) {
        for (int it = gt; it < 32 * 64; it += 128) {
            int row = 32 * wr + (it >> 6);
            int g = cc * 128 + row;
            uint32_t off = (uint32_t)row * ASTR + (uint32_t)d0b * 2;
            if (g < n_comp) {
                int pr = sMap[g];
                const float* p = &sObs[(pr >> 5) * OBS_DIM + OWN_DIM + (pr & 31) * INT_DIM];
                float2 acc = bb;
                #pragma unroll
                for (int j = 0; j < INT_DIM; j++) {
                    acc.x += p[j] * wj[j].x;
                    acc.y += p[j] * wj[j].y;
                }
                float v0 = lrelu(acc.x), v1 = lrelu(acc.y);
                float h0 = __bfloat162float(__float2bfloat16(v0));
                float h1 = __bfloat162float(__float2bfloat16(v1));
                *(uint32_t*)(smc + BY_AHI + off) = bf16pair(h0, h1);
                *(uint32_t*)(smc + BY_ALO + off) = bf16pair(v0 - h0, v1 - h1);
            } else {
                *(uint32_t*)(smc + BY_AHI + off) = 0u;
                *(uint32_t*)(smc + BY_ALO + off) = 0u;
            }
        }
        GROUP_BAR(wr + 1);

        if (cc * 128 + 32 * wr < n_comp) {
            float c[2][4][4];
            #pragma unroll
            for (int mi = 0; mi < 2; mi++)
            #pragma unroll
            for (int ni = 0; ni < 4; ni++)
            #pragma unroll
            for (int j = 0; j < 4; j++) c[mi][ni][j] = 0.f;

            #pragma unroll
            for (int kk = 0; kk < 8; kk++) {
                const uint32_t ko = kk * 32;
                uint32_t ah[2][4], al[2][4], bh[2][4], bl[2][4];
                LDSM_X4(ah[0][0], ah[0][1], ah[0][2], ah[0][3], aBase0 + ko);
                LDSM_X4(ah[1][0], ah[1][1], ah[1][2], ah[1][3], aBase1 + ko);
                LDSM_X4(al[0][0], al[0][1], al[0][2], al[0][3], alBase0 + ko);
                LDSM_X4(al[1][0], al[1][1], al[1][2], al[1][3], alBase1 + ko);
                LDSM_X4(bh[0][0], bh[0][1], bh[0][2], bh[0][3], bBase0 + ko);
                LDSM_X4(bh[1][0], bh[1][1], bh[1][2], bh[1][3], bBase1 + ko);
                LDSM_X4(bl[0][0], bl[0][1], bl[0][2], bl[0][3], blBase0 + ko);
                LDSM_X4(bl[1][0], bl[1][1], bl[1][2], bl[1][3], blBase1 + ko);

                #pragma unroll
                for (int mi = 0; mi < 2; mi++)
                #pragma unroll
                for (int ni = 0; ni < 4; ni++) {
                    const uint32_t* bfh = &bh[ni >> 1][(ni & 1) * 2];
                    const uint32_t* bfl = &bl[ni >> 1][(ni & 1) * 2];
                    mma_bf16(c[mi][ni], ah[mi], bfh);
                    mma_bf16(c[mi][ni], al[mi], bfh);
                    mma_bf16(c[mi][ni], ah[mi], bfl);
                }
            }

            #pragma unroll
            for (int mi = 0; mi < 2; mi++)
            #pragma unroll
            for (int ci = 0; ci < 2; ci++) {
                int crow = 32 * wr + 16 * mi + 8 * ci + (lane >> 2);
                int g = cc * 128 + crow;
                bool ok = (g < n_comp);
                int pr = ok ? sMap[g] : 0;
                const float* qr = &sQ[(pr >> 5) * D];
                float s = 0.f;
                #pragma unroll
                for (int ni = 0; ni < 4; ni++) {
                    int col = 32 * wc + 8 * ni + 2 * (lane & 3);
                    s += tanh_ap(qr[col]     + c[mi][ni][2 * ci])     * sVatt[col];
                    s += tanh_ap(qr[col + 1] + c[mi][ni][2 * ci + 1]) * sVatt[col + 1];
                }
                s += __shfl_xor_sync(0xffffffffu, s, 1);
                s += __shfl_xor_sync(0xffffffffu, s, 2);
                if (ok && (lane & 3) == 0) atomicAdd(&sSc[pr], s);
            }
        }
        GROUP_BAR(wr + 1);
    }
    __syncthreads();

    for (int r = wid; r < R1; r += 16) {
        float s = sSc[r * N_INTR + lane];
        float m = s;
        #pragma unroll
        for (int o = 16; o > 0; o >>= 1) m = fmaxf(m, __shfl_xor_sync(0xffffffffu, m, o));
        float e = (m == NEG_INF) ? 0.f : __expf(s - m);
        float sum = e;
        #pragma unroll
        for (int o = 16; o > 0; o >>= 1) sum += __shfl_xor_sync(0xffffffffu, sum, o);
        sAl[r * N_INTR + lane] = (sum > 0.f) ? (e / sum) : 0.f;
    }
    for (int i = tid; i < D * D / 4; i += NT)
        ((float4*)sW)[i] = ((const float4*)gWvProj)[i];
    __syncthreads();

    {
        float wIW[INT_DIM][4];
        float wB[4];
        #pragma unroll
        for (int cq = 0; cq < 4; cq++) {
            wB[cq] = sIntB[4 * tx5 + cq];
            #pragma unroll
            for (int j = 0; j < INT_DIM; j++) wIW[j][cq] = sIntW[j * D + 4 * tx5 + cq];
        }
        #pragma unroll
        for (int rr = 0; rr < 2; rr++) {
            int r = ty5 + 16 * rr;
            float ws[4] = {0.f,0.f,0.f,0.f};
            for (int n = 0; n < N_INTR; n++) {
                float al = sAl[r * N_INTR + n];
                if (al != 0.f) {
                    const float* p = &sObs[r * OBS_DIM + OWN_DIM + n * INT_DIM];
                    float pj[INT_DIM];
                    #pragma unroll
                    for (int j = 0; j < INT_DIM; j++) pj[j] = p[j];
                    #pragma unroll
                    for (int cq = 0; cq < 4; cq++) {
                        float pre = wB[cq];
                        #pragma unroll
                        for (int j = 0; j < INT_DIM; j++) pre += pj[j] * wIW[j][cq];
                        ws[cq] += al * lrelu(pre);
                    }
                }
            }
            #pragma unroll
            for (int cq = 0; cq < 4; cq++) sOwnE[r * D + 4 * tx5 + cq] = ws[cq];
        }
    }
    __syncthreads();

    {
        float a0[4] = {0.f,0.f,0.f,0.f}, a1[4] = {0.f,0.f,0.f,0.f};
        const float* ce0 = &sOwnE[ty5 * D];
        const float* ce1 = &sOwnE[(ty5 + 16) * D];
        #pragma unroll 4
        for (int e = 0; e < D; e++) {
            float v0 = ce0[e], v1 = ce1[e];
            float4 w = *(const float4*)&sW[e * D + 4 * tx5];
            a0[0] += v0 * w.x; a0[1] += v0 * w.y; a0[2] += v0 * w.z; a0[3] += v0 * w.w;
            a1[0] += v1 * w.x; a1[1] += v1 * w.y; a1[2] += v1 * w.z; a1[3] += v1 * w.w;
        }
        size_t base0 = (size_t)(b0 + ty5) * 256 + 128;
        size_t base1 = (size_t)(b0 + ty5 + 16) * 256 + 128;
        #pragma unroll
        for (int j = 0; j < 4; j++) {
            int c0 = 4 * tx5 + j;
            float t0 = tanhf(a0[j] + projB[c0]);
            float t1 = tanhf(a1[j] + projB[c0]);
            __nv_bfloat16 h0 = __float2bfloat16(t0);
            __nv_bfloat16 h1 = __float2bfloat16(t1);
            g_xh[base0 + c0] = h0;
            g_xl[base0 + c0] = __float2bfloat16(t0 - __bfloat162float(h0));
            g_xh[base1 + c0] = h1;
            g_xl[base1 + c0] = __float2bfloat16(t1 - __bfloat162float(h1));
        }
    }
}

// =====================================================================
// Kernel 2: MLP, R2=128, X resident as split-bf16 (no fp32 round trip)
// warp tile 64 rows x 32 cols; 2x8 warp grid
// =====================================================================
__global__ void __launch_bounds__(NT, 1)
k_mlp(const float* __restrict__ b1, const float* __restrict__ b2,
      const float* __restrict__ Wo, const float* __restrict__ bo,
      float* __restrict__ out)
{
    extern __shared__ float sm[];
    char* smc = (char*)sm;
    const uint32_t smb = smem_u32(sm);

    const int tid  = threadIdx.x;
    const int wid  = tid >> 5;
    const int lane = tid & 31;
    const int b0   = blockIdx.x * R2;
    const int wr = wid >> 3, wc = wid & 7;      // 2 row-groups of 64, 8 col-groups of 32
    const int lt = lane >> 3, lw = lane & 7;

    // stage X (layer-0 input) once: bf16 hi/lo, 4 chunks of [128][XSTRB]
    for (int i = tid; i < 128 * 32; i += NT) {
        int row = i >> 5, q = i & 31;
        int ch = q >> 3, qq = q & 7;
        size_t src = (size_t)(b0 + row) * 32 + q;
        uint32_t dst = (uint32_t)(ch * XCH + row * XSTRB + qq * 16);
        *(uint4*)(smc + M_XH + dst) = ((const uint4*)g_xh)[src];
        *(uint4*)(smc + M_XL + dst) = ((const uint4*)g_xl)[src];
    }

    const uint32_t aoff = (uint32_t)(((lt & 1) * 8 + lw) * XSTRB + (lt >> 1) * 16);
    const uint32_t boff = (uint32_t)((32 * wc + (lt >> 1) * 8 + lw) * XSTRB + (lt & 1) * 16);
    const uint32_t bB0 = smb + M_WH + boff;
    const uint32_t bB1 = bB0 + 16 * XSTRB;
    const uint32_t bL0 = bB0 + (M_WL - M_WH);
    const uint32_t bL1 = bB1 + (M_WL - M_WH);

    for (int layer = 0; layer < 2; layer++) {
        const float* bias = layer ? b2 : b1;

        float c[4][4][4];
        #pragma unroll
        for (int mi = 0; mi < 4; mi++)
        #pragma unroll
        for (int ni = 0; ni < 4; ni++)
        #pragma unroll
        for (int j = 0; j < 4; j++) c[mi][ni][j] = 0.f;

        for (int kk = 0; kk < 4; kk++) {
            // stage W chunk (prev MMA reads finished at loop-tail sync)
            {
                const uint4* WH = (const uint4*)(layer ? gW2Hi[kk] : gW1Hi[kk]);
                const uint4* WL = (const uint4*)(layer ? gW2Lo[kk] : gW1Lo[kk]);
                for (int i = tid; i < 2304; i += NT) {
                    ((uint4*)(smc + M_WH))[i] = WH[i];
                    ((uint4*)(smc + M_WL))[i] = WL[i];
                }
            }
            __syncthreads();

            const uint32_t aChunk = smb + M_XH + (uint32_t)(kk * XCH)
                                  + (uint32_t)(64 * wr) * XSTRB + aoff;
            #pragma unroll
            for (int ks = 0; ks < 4; ks++) {
                const uint32_t ko = ks * 32;
                uint32_t af[4][4], bh[2][4], bl[2][4];
                // A hi (4 mi blocks of 16 rows)
                #pragma unroll
                for (int m = 0; m < 4; m++)
                    LDSM_X4(af[m][0], af[m][1], af[m][2], af[m][3],
                            aChunk + (uint32_t)(16 * m) * XSTRB + ko);
                LDSM_X4(bh[0][0], bh[0][1], bh[0][2], bh[0][3], bB0 + ko);
                LDSM_X4(bh[1][0], bh[1][1], bh[1][2], bh[1][3], bB1 + ko);
                LDSM_X4(bl[0][0], bl[0][1], bl[0][2], bl[0][3], bL0 + ko);
                LDSM_X4(bl[1][0], bl[1][1], bl[1][2], bl[1][3], bL1 + ko);

                // hi passes: ah*bh + ah*bl
                #pragma unroll
                for (int mi = 0; mi < 4; mi++)
                #pragma unroll
                for (int ni = 0; ni < 4; ni++) {
                    const uint32_t* bfh = &bh[ni >> 1][(ni & 1) * 2];
                    const uint32_t* bfl = &bl[ni >> 1][(ni & 1) * 2];
                    mma_bf16(c[mi][ni], af[mi], bfh);
                    mma_bf16(c[mi][ni], af[mi], bfl);
                }
                // reload A lo into same regs, lo pass: al*bh
                #pragma unroll
                for (int m = 0; m < 4; m++)
                    LDSM_X4(af[m][0], af[m][1], af[m][2], af[m][3],
                            aChunk + (M_XL - M_XH) + (uint32_t)(16 * m) * XSTRB + ko);
                #pragma unroll
                for (int mi = 0; mi < 4; mi++)
                #pragma unroll
                for (int ni = 0; ni < 4; ni++) {
                    const uint32_t* bfh = &bh[ni >> 1][(ni & 1) * 2];
                    mma_bf16(c[mi][ni], af[mi], bfh);
                }
            }
            __syncthreads();   // MMA reads done before next W restage
        }

        // epilogue: bias + lrelu -> split-bf16 back into X buffers
        const int chn = wc >> 1;
        #pragma unroll
        for (int mi = 0; mi < 4; mi++)
        #pragma unroll
        for (int ci = 0; ci < 2; ci++) {
            int row = 64 * wr + 16 * mi + 8 * ci + (lane >> 2);
            #pragma unroll
            for (int ni = 0; ni < 4; ni++) {
                int col = 32 * wc + 8 * ni + 2 * (lane & 3);
                int colin = (wc & 1) * 32 + 8 * ni + 2 * (lane & 3);
                float x0 = lrelu(c[mi][ni][2 * ci]     + bias[col]);
                float x1 = lrelu(c[mi][ni][2 * ci + 1] + bias[col + 1]);
                float h0 = __bfloat162float(__float2bfloat16(x0));
                float h1 = __bfloat162float(__float2bfloat16(x1));
                uint32_t off = (uint32_t)(chn * XCH + row * XSTRB + colin * 2);
                *(uint32_t*)(smc + M_XH + off) = bf16pair(h0, h1);
                *(uint32_t*)(smc + M_XL + off) = bf16pair(x0 - h0, x1 - h1);
            }
        }
        __syncthreads();
    }

    // out layer: 256 -> 2 from split-bf16 X; 8 rows per warp, shuffle reduce
    {
        float bo0 = bo[0], bo1 = bo[1];
        const int chn = lane >> 3;            // lane*8 / 64
        const int colin0 = (lane & 7) * 8;
        #pragma unroll
        for (int rr = 0; rr < 8; rr++) {
            int r = wid * 8 + rr;
            uint32_t off = (uint32_t)(chn * XCH + r * XSTRB + colin0 * 2);
            float a0 = 0.f, a1 = 0.f;
            #pragma unroll
            for (int kp = 0; kp < 4; kp++) {
                uint32_t uh = *(const uint32_t*)(smc + M_XH + off + kp * 4);
                uint32_t ul = *(const uint32_t*)(smc + M_XL + off + kp * 4);
                __nv_bfloat162 vh = *(__nv_bfloat162*)&uh;
                __nv_bfloat162 vl = *(__nv_bfloat162*)&ul;
                float x0 = __bfloat162float(vh.x) + __bfloat162float(vl.x);
                float x1 = __bfloat162float(vh.y) + __bfloat162float(vl.y);
                int col = lane * 8 + 2 * kp;
                float2 w0 = ((const float2*)Wo)[col];
                float2 w1 = ((const float2*)Wo)[col + 1];
                a0 += x0 * w0.x + x1 * w1.x;
                a1 += x0 * w0.y + x1 * w1.y;
            }
            #pragma unroll
            for (int o = 16; o > 0; o >>= 1) {
                a0 += __shfl_xor_sync(0xffffffffu, a0, o);
                a1 += __shfl_xor_sync(0xffffffffu, a1, o);
            }
            if (lane == 0) {
                out[(size_t)(b0 + r) * 2 + 0] = a0 + bo0;
                out[(size_t)(b0 + r) * 2 + 1] = a1 + bo1;
            }
        }
    }
}

extern "C" void kernel_launch(void* const* d_in, const int* in_sizes, int n_in,
                              void* d_out, int out_size)
{
    const float* obs   = (const float*)d_in[0];
    const float* ownW  = (const float*)d_in[1];
    const float* ownB  = (const float*)d_in[2];
    const float* intW  = (const float*)d_in[3];
    const float* intB  = (const float*)d_in[4];
    const float* Wq    = (const float*)d_in[5];
    const float* Wk    = (const float*)d_in[6];
    const float* Wv    = (const float*)d_in[7];
    const float* vatt  = (const float*)d_in[8];
    const float* projW = (const float*)d_in[9];
    const float* projB = (const float*)d_in[10];
    const float* W1    = (const float*)d_in[11];
    const float* b1    = (const float*)d_in[12];
    const float* W2    = (const float*)d_in[13];
    const float* b2    = (const float*)d_in[14];
    const float* Wo    = (const float*)d_in[15];
    const float* bo    = (const float*)d_in[16];
    float* out = (float*)d_out;

    cudaFuncSetAttribute(k_attn, cudaFuncAttributeMaxDynamicSharedMemorySize, SMEM1_BYTES);
    cudaFuncSetAttribute(k_mlp,  cudaFuncAttributeMaxDynamicSharedMemorySize, SMEM2_BYTES);

    k_prep<<<352, 256>>>(Wk, W1, W2, Wv, projW);
    k_attn<<<B_TOT / R1, NT, SMEM1_BYTES>>>(obs, ownW, ownB, intW, intB, Wq, vatt, projB);
    k_mlp<<<B_TOT / R2, NT, SMEM2_BYTES>>>(b1, b2, Wo, bo, out);
}

// round 12
// speedup vs baseline: 5.0076x; 1.0417x over previous
#include <cuda_runtime.h>
#include <cuda_bf16.h>
#include <math.h>
#include <stdint.h>

#define B_TOT   32768
#define OWN_DIM 3
#define N_INTR  32
#define INT_DIM 7
#define D       128
#define OBS_DIM 227
#define HID     256

#define R1      32
#define R2      128
#define X_STR   260
#define NT      512

#define ASTR    272
#define TILE_BYTES (128 * ASTR)

#define BY_AHI    1024
#define BY_ALO    (BY_AHI + TILE_BYTES)
#define BY_BHI    (BY_ALO + TILE_BYTES)
#define BY_BLO    (BY_BHI + TILE_BYTES)
#define BY_F32    (BY_BLO + TILE_BYTES)
#define F_OBS   (BY_F32 / 4)
#define F_OWNE  (F_OBS  + R1 * OBS_DIM)
#define F_Q     (F_OWNE + R1 * D)
#define F_SC    (F_Q    + R1 * D)
#define F_AL    (F_SC   + R1 * N_INTR)
#define F_INTW  (F_AL   + R1 * N_INTR)
#define F_OWNW  (F_INTW + INT_DIM * D)
#define F_INTB  (F_OWNW + OWN_DIM * D)
#define F_VATT  (F_INTB + D)
#define F_MAP   (F_VATT + D)
#define F_WS    (F_MAP + R1 * N_INTR)
#define F_NC    (F_WS + 32)
#define SMEM1_BYTES ((F_NC + 1) * 4)

// ---- k_mlp smem (bytes): X resident as bf16 hi/lo, 4 k-chunks ----
#define XSTRB   144
#define XCH     (R2 * XSTRB)
#define M_XH    0
#define M_XL    (4 * XCH)
#define M_WH    (8 * XCH)
#define M_WL    (M_WH + 256 * XSTRB)
#define SMEM2_BYTES (M_WL + 256 * XSTRB)

__device__ uint32_t gWkHi[8704], gWkLo[8704];
__device__ uint32_t gWqHi[8704], gWqLo[8704];
__device__ uint32_t gWvpHi[8704], gWvpLo[8704];
__device__ uint32_t gW1Hi[4][9216], gW1Lo[4][9216];
__device__ uint32_t gW2Hi[4][9216], gW2Lo[4][9216];
__device__ __nv_bfloat16 g_xh[(size_t)B_TOT * 256];
__device__ __nv_bfloat16 g_xl[(size_t)B_TOT * 256];

typedef unsigned long long u64;

__device__ __forceinline__ float lrelu(float x) { return fmaxf(x, 0.2f * x); }
__device__ __forceinline__ float tanh_ap(float x) {
    float y; asm("tanh.approx.f32 %0, %1;" : "=f"(y) : "f"(x)); return y;
}
__device__ __forceinline__ uint32_t smem_u32(const void* p) {
    uint32_t a;
    asm("{ .reg .u64 t; cvta.to.shared.u64 t, %1; cvt.u32.u64 %0, t; }" : "=r"(a) : "l"(p));
    return a;
}
__device__ __forceinline__ uint32_t bf16pair(float a, float b) {
    __nv_bfloat162 t = __floats2bfloat162_rn(a, b);
    return *(uint32_t*)&t;
}

#define LDSM_X4(r0, r1, r2, r3, addr) \
    asm volatile("ldmatrix.sync.aligned.m8n8.x4.shared.b16 {%0,%1,%2,%3}, [%4];" \
                 : "=r"(r0), "=r"(r1), "=r"(r2), "=r"(r3) : "r"(addr))

__device__ __forceinline__ void mma_bf16(float* c, const uint32_t* a, const uint32_t* b) {
    asm volatile(
        "mma.sync.aligned.m16n8k16.row.col.f32.bf16.bf16.f32 "
        "{%0,%1,%2,%3}, {%4,%5,%6,%7}, {%8,%9}, {%0,%1,%2,%3};"
        : "+f"(c[0]), "+f"(c[1]), "+f"(c[2]), "+f"(c[3])
        : "r"(a[0]), "r"(a[1]), "r"(a[2]), "r"(a[3]), "r"(b[0]), "r"(b[1]));
}

#define GROUP_BAR(id) \
    asm volatile("bar.sync %0, 128;" :: "r"(id) : "memory")

// =====================================================================
// Prep: quantize Wk, Wq, W1, W2 to split-bf16 images
// =====================================================================
__global__ void __launch_bounds__(256, 4)
k_prep(const float* __restrict__ Wk, const float* __restrict__ W1,
       const float* __restrict__ W2, const float* __restrict__ Wq)
{
    int idx = blockIdx.x * 256 + threadIdx.x;
    if (idx < 2 * 8192) {                   // Wk then Wq: Bn[n][e] images
        const float* W = (idx < 8192) ? Wk : Wq;
        uint32_t* IH = (idx < 8192) ? gWkHi : gWqHi;
        uint32_t* IL = (idx < 8192) ? gWkLo : gWqLo;
        int j = idx & 8191;
        int ep = j >> 7, n = j & 127;
        int e0 = 2 * ep;
        float w0 = W[e0 * D + n], w1 = W[(e0 + 1) * D + n];
        float h0 = __bfloat162float(__float2bfloat16(w0));
        float h1 = __bfloat162float(__float2bfloat16(w1));
        int o = n * 68 + ep;
        IH[o] = bf16pair(h0, h1);
        IL[o] = bf16pair(w0 - h0, w1 - h1);
    } else if (idx < 2 * 8192 + 2 * 32768) {
        int j = idx - 2 * 8192;
        const float* W = (j < 32768) ? W1 : W2;
        uint32_t* WH = (j < 32768) ? &gW1Hi[0][0] : &gW2Hi[0][0];
        uint32_t* WL = (j < 32768) ? &gW1Lo[0][0] : &gW2Lo[0][0];
        j &= 32767;
        int kk = j >> 13, r = j & 8191;
        int n = r & 255, kp = r >> 8;
        int k0 = kk * 64 + 2 * kp;
        float w0 = W[(size_t)k0 * HID + n], w1 = W[(size_t)(k0 + 1) * HID + n];
        float h0 = __bfloat162float(__float2bfloat16(w0));
        float h1 = __bfloat162float(__float2bfloat16(w1));
        int o = kk * 9216 + n * 36 + kp;
        WH[o] = bf16pair(h0, h1);
        WL[o] = bf16pair(w0 - h0, w1 - h1);
    }
}

// Prep2: WvProj = Wv @ projW, fused and quantized to Bn[c][f] image
__global__ void __launch_bounds__(256, 4)
k_prep2(const float* __restrict__ Wv, const float* __restrict__ projW)
{
    int idx = blockIdx.x * 256 + threadIdx.x;   // 8192
    int n = idx & 127, f0 = 2 * (idx >> 7);
    float s0 = 0.f, s1 = 0.f;
    #pragma unroll 4
    for (int e = 0; e < D; e++) {
        float pc = projW[e * D + n];
        s0 += Wv[f0 * D + e] * pc;
        s1 += Wv[(f0 + 1) * D + e] * pc;
    }
    float h0 = __bfloat162float(__float2bfloat16(s0));
    float h1 = __bfloat162float(__float2bfloat16(s1));
    int o = n * 68 + (f0 >> 1);
    gWvpHi[o] = bf16pair(h0, h1);
    gWvpLo[o] = bf16pair(s0 - h0, s1 - h1);
}

// =====================================================================
// Kernel 1: attention, all GEMMs on HMMA
// =====================================================================
__global__ void __launch_bounds__(NT, 1)
k_attn(const float* __restrict__ obs,
       const float* __restrict__ ownW, const float* __restrict__ ownB,
       const float* __restrict__ intW, const float* __restrict__ intB,
       const float* __restrict__ vatt, const float* __restrict__ projB)
{
    extern __shared__ float sm[];
    char* smc = (char*)sm;
    const uint32_t smb = smem_u32(sm);

    float* sObs  = sm + F_OBS;
    float* sWsum = sm + F_OWNE;   // wsum scratch (own_e no longer stored fp32)
    float* sQ    = sm + F_Q;
    float* sSc   = sm + F_SC;
    float* sAl   = sm + F_AL;
    float* sIntW = sm + F_INTW;
    float* sOwnW = sm + F_OWNW;
    float* sIntB = sm + F_INTB;
    float* sVatt = sm + F_VATT;
    int*   sMap  = (int*)(sm + F_MAP);
    int*   sWs   = (int*)(sm + F_WS);
    int*   sNC   = (int*)(sm + F_NC);

    const int tid  = threadIdx.x;
    const int wid  = tid >> 5;
    const int lane = tid & 31;
    const int tx5  = tid & 31;
    const int ty5  = tid >> 5;
    const int b0   = blockIdx.x * R1;
    const float NEG_INF = __int_as_float(0xff800000u);

    // MMA addressing (pure arithmetic, needed early for q GEMM)
    const int wr = wid >> 2, wc = wid & 3;
    const int lt = lane >> 3, lw = lane & 7;
    const uint32_t aoff = (uint32_t)(((lt & 1) * 8 + lw) * ASTR + (lt >> 1) * 16);
    const uint32_t boff = (uint32_t)((((lt >> 1) * 8 + lw) + 32 * wc) * ASTR + (lt & 1) * 16);
    const uint32_t aBase0 = smb + BY_AHI + (uint32_t)(32 * wr) * ASTR + aoff;
    const uint32_t aBase1 = aBase0 + 16 * ASTR;
    const uint32_t alBase0 = aBase0 + TILE_BYTES;
    const uint32_t alBase1 = aBase1 + TILE_BYTES;
    const uint32_t bBase0 = smb + BY_BHI + boff;
    const uint32_t bBase1 = bBase0 + 16 * ASTR;
    const uint32_t blBase0 = bBase0 + TILE_BYTES;
    const uint32_t blBase1 = bBase1 + TILE_BYTES;

    // ---- phase 1: stage obs + small weights + Wq image into B region ----
    for (int i = tid; i < R1 * OBS_DIM; i += NT) sObs[i] = obs[(size_t)b0 * OBS_DIM + i];
    for (int i = tid; i < INT_DIM * D; i += NT)  sIntW[i] = intW[i];
    for (int i = tid; i < OWN_DIM * D; i += NT)  sOwnW[i] = ownW[i];
    if (tid < D) { sIntB[tid] = intB[tid]; sVatt[tid] = vatt[tid]; }
    for (int i = tid; i < 2176; i += NT) {
        ((uint4*)(smc + BY_BHI))[i] = ((const uint4*)gWqHi)[i];
        ((uint4*)(smc + BY_BLO))[i] = ((const uint4*)gWqLo)[i];
    }
    __syncthreads();

    // ---- phase 2: own_e -> A image (hi/lo) + g_x; pad mask ----
    for (int i = tid; i < R1 * D; i += NT) {
        int r = i >> 7, d = i & 127;
        const float* o = &sObs[r * OBS_DIM];
        float a = ownB[d] + o[0] * sOwnW[d] + o[1] * sOwnW[D + d] + o[2] * sOwnW[2 * D + d];
        a = lrelu(a);
        __nv_bfloat16 h = __float2bfloat16(a);
        float hf = __bfloat162float(h);
        uint32_t off = (uint32_t)r * ASTR + (uint32_t)d * 2;
        *(__nv_bfloat16*)(smc + BY_AHI + off) = h;
        *(__nv_bfloat16*)(smc + BY_ALO + off) = __float2bfloat16(a - hf);
        size_t gi = (size_t)(b0 + r) * 256 + d;
        g_xh[gi] = h;
        g_xl[gi] = __float2bfloat16(a - hf);
    }
    for (int i = tid; i < R1 * N_INTR; i += NT) {
        int r = i >> 5, n = i & 31;
        const float* p = &sObs[r * OBS_DIM + OWN_DIM + n * INT_DIM];
        float s = 0.f;
        #pragma unroll
        for (int j = 0; j < INT_DIM; j++) s += fabsf(p[j]);
        sSc[i] = (s < 1e-6f) ? NEG_INF : 0.f;
    }
    __syncthreads();

    // ---- phase 3: q = own_e @ Wq via HMMA (warps 0-3, rows 0-31) ----
    if (wid < 4) {
        float c[2][4][4];
        #pragma unroll
        for (int mi = 0; mi < 2; mi++)
        #pragma unroll
        for (int ni = 0; ni < 4; ni++)
        #pragma unroll
        for (int j = 0; j < 4; j++) c[mi][ni][j] = 0.f;

        #pragma unroll
        for (int kk = 0; kk < 8; kk++) {
            const uint32_t ko = kk * 32;
            uint32_t ah[2][4], al[2][4], bh[2][4], bl[2][4];
            LDSM_X4(ah[0][0], ah[0][1], ah[0][2], ah[0][3], aBase0 + ko);
            LDSM_X4(ah[1][0], ah[1][1], ah[1][2], ah[1][3], aBase1 + ko);
            LDSM_X4(al[0][0], al[0][1], al[0][2], al[0][3], alBase0 + ko);
            LDSM_X4(al[1][0], al[1][1], al[1][2], al[1][3], alBase1 + ko);
            LDSM_X4(bh[0][0], bh[0][1], bh[0][2], bh[0][3], bBase0 + ko);
            LDSM_X4(bh[1][0], bh[1][1], bh[1][2], bh[1][3], bBase1 + ko);
            LDSM_X4(bl[0][0], bl[0][1], bl[0][2], bl[0][3], blBase0 + ko);
            LDSM_X4(bl[1][0], bl[1][1], bl[1][2], bl[1][3], blBase1 + ko);
            #pragma unroll
            for (int mi = 0; mi < 2; mi++)
            #pragma unroll
            for (int ni = 0; ni < 4; ni++) {
                const uint32_t* bfh = &bh[ni >> 1][(ni & 1) * 2];
                const uint32_t* bfl = &bl[ni >> 1][(ni & 1) * 2];
                mma_bf16(c[mi][ni], ah[mi], bfh);
                mma_bf16(c[mi][ni], al[mi], bfh);
                mma_bf16(c[mi][ni], ah[mi], bfl);
            }
        }
        #pragma unroll
        for (int mi = 0; mi < 2; mi++)
        #pragma unroll
        for (int ci = 0; ci < 2; ci++) {
            int row = 16 * mi + 8 * ci + (lane >> 2);
            #pragma unroll
            for (int ni = 0; ni < 4; ni++) {
                int col = 32 * wc + 8 * ni + 2 * (lane & 3);
                sQ[row * D + col]     = c[mi][ni][2 * ci];
                sQ[row * D + col + 1] = c[mi][ni][2 * ci + 1];
            }
        }
    }
    __syncthreads();

    // ---- phase 4: compaction over 1024 (r,n) pairs ----
    {
        int flag0 = (sSc[tid] == 0.f) ? 1 : 0;
        int flag1 = (sSc[tid + 512] == 0.f) ? 1 : 0;
        unsigned bal0 = __ballot_sync(0xffffffffu, flag0);
        unsigned bal1 = __ballot_sync(0xffffffffu, flag1);
        int wpos0 = __popc(bal0 & ((1u << lane) - 1));
        int wpos1 = __popc(bal1 & ((1u << lane) - 1));
        if (lane == 0) { sWs[wid] = __popc(bal0); sWs[16 + wid] = __popc(bal1); }
        __syncthreads();
        if (tid == 0) {
            int acc = 0;
            for (int w = 0; w < 32; w++) { int t = sWs[w]; sWs[w] = acc; acc += t; }
            *sNC = acc;
        }
        __syncthreads();
        if (flag0) sMap[sWs[wid] + wpos0]      = tid;
        if (flag1) sMap[sWs[16 + wid] + wpos1] = tid + 512;
    }

    // ---- phase 5: Wk image into B (overwrites Wq image) ----
    for (int i = tid; i < 2176; i += NT) {
        ((uint4*)(smc + BY_BHI))[i] = ((const uint4*)gWkHi)[i];
        ((uint4*)(smc + BY_BLO))[i] = ((const uint4*)gWkLo)[i];
    }
    __syncthreads();

    const int n_comp = *sNC;
    const int nch = (n_comp + 127) >> 7;

    const int gt = tid & 127;
    const int qd = 4 * (gt & 31);   // d quad per thread

    // ================= chunk loop =================
    for (int cc = 0; cc < nch; cc++) {
        // 4-wide build: 32 rows x 32 quads per group
        for (int it = gt; it < 32 * 32; it += 128) {
            int row = 32 * wr + (it >> 5);
            int g = cc * 128 + row;
            uint32_t off = (uint32_t)row * ASTR + (uint32_t)qd * 2;
            if (g < n_comp) {
                int pr = sMap[g];
                const float* p = &sObs[(pr >> 5) * OBS_DIM + OWN_DIM + (pr & 31) * INT_DIM];
                float4 acc = *(const float4*)&sIntB[qd];
                #pragma unroll
                for (int j = 0; j < INT_DIM; j++) {
                    float4 w = *(const float4*)&sIntW[j * D + qd];
                    float pj = p[j];
                    acc.x += pj * w.x; acc.y += pj * w.y;
                    acc.z += pj * w.z; acc.w += pj * w.w;
                }
                float v0 = lrelu(acc.x), v1 = lrelu(acc.y);
                float v2 = lrelu(acc.z), v3 = lrelu(acc.w);
                float h0 = __bfloat162float(__float2bfloat16(v0));
                float h1 = __bfloat162float(__float2bfloat16(v1));
                float h2 = __bfloat162float(__float2bfloat16(v2));
                float h3 = __bfloat162float(__float2bfloat16(v3));
                *(uint2*)(smc + BY_AHI + off) =
                    make_uint2(bf16pair(h0, h1), bf16pair(h2, h3));
                *(uint2*)(smc + BY_ALO + off) =
                    make_uint2(bf16pair(v0 - h0, v1 - h1), bf16pair(v2 - h2, v3 - h3));
            } else {
                *(uint2*)(smc + BY_AHI + off) = make_uint2(0u, 0u);
                *(uint2*)(smc + BY_ALO + off) = make_uint2(0u, 0u);
            }
        }
        GROUP_BAR(wr + 1);

        if (cc * 128 + 32 * wr < n_comp) {
            float c[2][4][4];
            #pragma unroll
            for (int mi = 0; mi < 2; mi++)
            #pragma unroll
            for (int ni = 0; ni < 4; ni++)
            #pragma unroll
            for (int j = 0; j < 4; j++) c[mi][ni][j] = 0.f;

            #pragma unroll
            for (int kk = 0; kk < 8; kk++) {
                const uint32_t ko = kk * 32;
                uint32_t ah[2][4], al[2][4], bh[2][4], bl[2][4];
                LDSM_X4(ah[0][0], ah[0][1], ah[0][2], ah[0][3], aBase0 + ko);
                LDSM_X4(ah[1][0], ah[1][1], ah[1][2], ah[1][3], aBase1 + ko);
                LDSM_X4(al[0][0], al[0][1], al[0][2], al[0][3], alBase0 + ko);
                LDSM_X4(al[1][0], al[1][1], al[1][2], al[1][3], alBase1 + ko);
                LDSM_X4(bh[0][0], bh[0][1], bh[0][2], bh[0][3], bBase0 + ko);
                LDSM_X4(bh[1][0], bh[1][1], bh[1][2], bh[1][3], bBase1 + ko);
                LDSM_X4(bl[0][0], bl[0][1], bl[0][2], bl[0][3], blBase0 + ko);
                LDSM_X4(bl[1][0], bl[1][1], bl[1][2], bl[1][3], blBase1 + ko);
                #pragma unroll
                for (int mi = 0; mi < 2; mi++)
                #pragma unroll
                for (int ni = 0; ni < 4; ni++) {
                    const uint32_t* bfh = &bh[ni >> 1][(ni & 1) * 2];
                    const uint32_t* bfl = &bl[ni >> 1][(ni & 1) * 2];
                    mma_bf16(c[mi][ni], ah[mi], bfh);
                    mma_bf16(c[mi][ni], al[mi], bfh);
                    mma_bf16(c[mi][ni], ah[mi], bfl);
                }
            }

            // epilogue: vatt hoisted, float2 q loads
            float2 vv[4];
            #pragma unroll
            for (int ni = 0; ni < 4; ni++)
                vv[ni] = ((const float2*)sVatt)[16 * wc + 4 * ni + (lane & 3)];
            #pragma unroll
            for (int mi = 0; mi < 2; mi++)
            #pragma unroll
            for (int ci = 0; ci < 2; ci++) {
                int crow = 32 * wr + 16 * mi + 8 * ci + (lane >> 2);
                int g = cc * 128 + crow;
                bool ok = (g < n_comp);
                int pr = ok ? sMap[g] : 0;
                const float2* qr2 = (const float2*)&sQ[(pr >> 5) * D];
                float s = 0.f;
                #pragma unroll
                for (int ni = 0; ni < 4; ni++) {
                    float2 qv = qr2[16 * wc + 4 * ni + (lane & 3)];
                    s += tanh_ap(qv.x + c[mi][ni][2 * ci])     * vv[ni].x;
                    s += tanh_ap(qv.y + c[mi][ni][2 * ci + 1]) * vv[ni].y;
                }
                s += __shfl_xor_sync(0xffffffffu, s, 1);
                s += __shfl_xor_sync(0xffffffffu, s, 2);
                if (ok && (lane & 3) == 0) atomicAdd(&sSc[pr], s);
            }
        }
        GROUP_BAR(wr + 1);
    }
    __syncthreads();

    // ---- softmax ----
    for (int r = wid; r < R1; r += 16) {
        float s = sSc[r * N_INTR + lane];
        float m = s;
        #pragma unroll
        for (int o = 16; o > 0; o >>= 1) m = fmaxf(m, __shfl_xor_sync(0xffffffffu, m, o));
        float e = (m == NEG_INF) ? 0.f : __expf(s - m);
        float sum = e;
        #pragma unroll
        for (int o = 16; o > 0; o >>= 1) sum += __shfl_xor_sync(0xffffffffu, sum, o);
        sAl[r * N_INTR + lane] = (sum > 0.f) ? (e / sum) : 0.f;
    }
    __syncthreads();

    // ---- wsum = alpha @ int_e (fp32, 2 rows per thread) ----
    {
        float wIW[INT_DIM][4];
        float wB[4];
        #pragma unroll
        for (int cq = 0; cq < 4; cq++) {
            wB[cq] = sIntB[4 * tx5 + cq];
            #pragma unroll
            for (int j = 0; j < INT_DIM; j++) wIW[j][cq] = sIntW[j * D + 4 * tx5 + cq];
        }
        #pragma unroll
        for (int rr = 0; rr < 2; rr++) {
            int r = ty5 + 16 * rr;
            float ws[4] = {0.f,0.f,0.f,0.f};
            for (int n = 0; n < N_INTR; n++) {
                float al = sAl[r * N_INTR + n];
                if (al != 0.f) {
                    const float* p = &sObs[r * OBS_DIM + OWN_DIM + n * INT_DIM];
                    float pj[INT_DIM];
                    #pragma unroll
                    for (int j = 0; j < INT_DIM; j++) pj[j] = p[j];
                    #pragma unroll
                    for (int cq = 0; cq < 4; cq++) {
                        float pre = wB[cq];
                        #pragma unroll
                        for (int j = 0; j < INT_DIM; j++) pre += pj[j] * wIW[j][cq];
                        ws[cq] += al * lrelu(pre);
                    }
                }
            }
            #pragma unroll
            for (int cq = 0; cq < 4; cq++) sWsum[r * D + 4 * tx5 + cq] = ws[cq];
        }
    }
    __syncthreads();

    // ---- split wsum into A image; WvProj image into B ----
    for (int i = tid; i < R1 * D; i += NT) {
        int r = i >> 7, d = i & 127;
        float v = sWsum[i];
        __nv_bfloat16 h = __float2bfloat16(v);
        uint32_t off = (uint32_t)r * ASTR + (uint32_t)d * 2;
        *(__nv_bfloat16*)(smc + BY_AHI + off) = h;
        *(__nv_bfloat16*)(smc + BY_ALO + off) = __float2bfloat16(v - __bfloat162float(h));
    }
    for (int i = tid; i < 2176; i += NT) {
        ((uint4*)(smc + BY_BHI))[i] = ((const uint4*)gWvpHi)[i];
        ((uint4*)(smc + BY_BLO))[i] = ((const uint4*)gWvpLo)[i];
    }
    __syncthreads();

    // ---- attn_vec = tanh(wsum @ WvProj + projB) via HMMA (warps 0-3) ----
    if (wid < 4) {
        float c[2][4][4];
        #pragma unroll
        for (int mi = 0; mi < 2; mi++)
        #pragma unroll
        for (int ni = 0; ni < 4; ni++)
        #pragma unroll
        for (int j = 0; j < 4; j++) c[mi][ni][j] = 0.f;

        #pragma unroll
        for (int kk = 0; kk < 8; kk++) {
            const uint32_t ko = kk * 32;
            uint32_t ah[2][4], al[2][4], bh[2][4], bl[2][4];
            LDSM_X4(ah[0][0], ah[0][1], ah[0][2], ah[0][3], aBase0 + ko);
            LDSM_X4(ah[1][0], ah[1][1], ah[1][2], ah[1][3], aBase1 + ko);
            LDSM_X4(al[0][0], al[0][1], al[0][2], al[0][3], alBase0 + ko);
            LDSM_X4(al[1][0], al[1][1], al[1][2], al[1][3], alBase1 + ko);
            LDSM_X4(bh[0][0], bh[0][1], bh[0][2], bh[0][3], bBase0 + ko);
            LDSM_X4(bh[1][0], bh[1][1], bh[1][2], bh[1][3], bBase1 + ko);
            LDSM_X4(bl[0][0], bl[0][1], bl[0][2], bl[0][3], blBase0 + ko);
            LDSM_X4(bl[1][0], bl[1][1], bl[1][2], bl[1][3], blBase1 + ko);
            #pragma unroll
            for (int mi = 0; mi < 2; mi++)
            #pragma unroll
            for (int ni = 0; ni < 4; ni++) {
                const uint32_t* bfh = &bh[ni >> 1][(ni & 1) * 2];
                const uint32_t* bfl = &bl[ni >> 1][(ni & 1) * 2];
                mma_bf16(c[mi][ni], ah[mi], bfh);
                mma_bf16(c[mi][ni], al[mi], bfh);
                mma_bf16(c[mi][ni], ah[mi], bfl);
            }
        }
        #pragma unroll
        for (int mi = 0; mi < 2; mi++)
        #pragma unroll
        for (int ci = 0; ci < 2; ci++) {
            int row = 16 * mi + 8 * ci + (lane >> 2);
            size_t base = (size_t)(b0 + row) * 256 + 128;
            #pragma unroll
            for (int ni = 0; ni < 4; ni++) {
                int col = 32 * wc + 8 * ni + 2 * (lane & 3);
                float t0 = tanhf(c[mi][ni][2 * ci]     + projB[col]);
                float t1 = tanhf(c[mi][ni][2 * ci + 1] + projB[col + 1]);
                __nv_bfloat16 h0 = __float2bfloat16(t0);
                __nv_bfloat16 h1 = __float2bfloat16(t1);
                g_xh[base + col]     = h0;
                g_xl[base + col]     = __float2bfloat16(t0 - __bfloat162float(h0));
                g_xh[base + col + 1] = h1;
                g_xl[base + col + 1] = __float2bfloat16(t1 - __bfloat162float(h1));
            }
        }
    }
}

// =====================================================================
// Kernel 2: MLP (unchanged from R11)
// =====================================================================
__global__ void __launch_bounds__(NT, 1)
k_mlp(const float* __restrict__ b1, const float* __restrict__ b2,
      const float* __restrict__ Wo, const float* __restrict__ bo,
      float* __restrict__ out)
{
    extern __shared__ float sm[];
    char* smc = (char*)sm;
    const uint32_t smb = smem_u32(sm);

    const int tid  = threadIdx.x;
    const int wid  = tid >> 5;
    const int lane = tid & 31;
    const int b0   = blockIdx.x * R2;
    const int wr = wid >> 3, wc = wid & 7;
    const int lt = lane >> 3, lw = lane & 7;

    for (int i = tid; i < 128 * 32; i += NT) {
        int row = i >> 5, q = i & 31;
        int ch = q >> 3, qq = q & 7;
        size_t src = (size_t)(b0 + row) * 32 + q;
        uint32_t dst = (uint32_t)(ch * XCH + row * XSTRB + qq * 16);
        *(uint4*)(smc + M_XH + dst) = ((const uint4*)g_xh)[src];
        *(uint4*)(smc + M_XL + dst) = ((const uint4*)g_xl)[src];
    }

    const uint32_t aoff = (uint32_t)(((lt & 1) * 8 + lw) * XSTRB + (lt >> 1) * 16);
    const uint32_t boff = (uint32_t)((32 * wc + (lt >> 1) * 8 + lw) * XSTRB + (lt & 1) * 16);
    const uint32_t bB0 = smb + M_WH + boff;
    const uint32_t bB1 = bB0 + 16 * XSTRB;
    const uint32_t bL0 = bB0 + (M_WL - M_WH);
    const uint32_t bL1 = bB1 + (M_WL - M_WH);

    for (int layer = 0; layer < 2; layer++) {
        const float* bias = layer ? b2 : b1;

        float c[4][4][4];
        #pragma unroll
        for (int mi = 0; mi < 4; mi++)
        #pragma unroll
        for (int ni = 0; ni < 4; ni++)
        #pragma unroll
        for (int j = 0; j < 4; j++) c[mi][ni][j] = 0.f;

        for (int kk = 0; kk < 4; kk++) {
            {
                const uint4* WH = (const uint4*)(layer ? gW2Hi[kk] : gW1Hi[kk]);
                const uint4* WL = (const uint4*)(layer ? gW2Lo[kk] : gW1Lo[kk]);
                for (int i = tid; i < 2304; i += NT) {
                    ((uint4*)(smc + M_WH))[i] = WH[i];
                    ((uint4*)(smc + M_WL))[i] = WL[i];
                }
            }
            __syncthreads();

            const uint32_t aChunk = smb + M_XH + (uint32_t)(kk * XCH)
                                  + (uint32_t)(64 * wr) * XSTRB + aoff;
            #pragma unroll
            for (int ks = 0; ks < 4; ks++) {
                const uint32_t ko = ks * 32;
                uint32_t af[4][4], bh[2][4], bl[2][4];
                #pragma unroll
                for (int m = 0; m < 4; m++)
                    LDSM_X4(af[m][0], af[m][1], af[m][2], af[m][3],
                            aChunk + (uint32_t)(16 * m) * XSTRB + ko);
                LDSM_X4(bh[0][0], bh[0][1], bh[0][2], bh[0][3], bB0 + ko);
                LDSM_X4(bh[1][0], bh[1][1], bh[1][2], bh[1][3], bB1 + ko);
                LDSM_X4(bl[0][0], bl[0][1], bl[0][2], bl[0][3], bL0 + ko);
                LDSM_X4(bl[1][0], bl[1][1], bl[1][2], bl[1][3], bL1 + ko);

                #pragma unroll
                for (int mi = 0; mi < 4; mi++)
                #pragma unroll
                for (int ni = 0; ni < 4; ni++) {
                    const uint32_t* bfh = &bh[ni >> 1][(ni & 1) * 2];
                    const uint32_t* bfl = &bl[ni >> 1][(ni & 1) * 2];
                    mma_bf16(c[mi][ni], af[mi], bfh);
                    mma_bf16(c[mi][ni], af[mi], bfl);
                }
                #pragma unroll
                for (int m = 0; m < 4; m++)
                    LDSM_X4(af[m][0], af[m][1], af[m][2], af[m][3],
                            aChunk + (M_XL - M_XH) + (uint32_t)(16 * m) * XSTRB + ko);
                #pragma unroll
                for (int mi = 0; mi < 4; mi++)
                #pragma unroll
                for (int ni = 0; ni < 4; ni++) {
                    const uint32_t* bfh = &bh[ni >> 1][(ni & 1) * 2];
                    mma_bf16(c[mi][ni], af[mi], bfh);
                }
            }
            __syncthreads();
        }

        const int chn = wc >> 1;
        #pragma unroll
        for (int mi = 0; mi < 4; mi++)
        #pragma unroll
        for (int ci = 0; ci < 2; ci++) {
            int row = 64 * wr + 16 * mi + 8 * ci + (lane >> 2);
            #pragma unroll
            for (int ni = 0; ni < 4; ni++) {
                int col = 32 * wc + 8 * ni + 2 * (lane & 3);
                int colin = (wc & 1) * 32 + 8 * ni + 2 * (lane & 3);
                float x0 = lrelu(c[mi][ni][2 * ci]     + bias[col]);
                float x1 = lrelu(c[mi][ni][2 * ci + 1] + bias[col + 1]);
                float h0 = __bfloat162float(__float2bfloat16(x0));
                float h1 = __bfloat162float(__float2bfloat16(x1));
                uint32_t off = (uint32_t)(chn * XCH + row * XSTRB + colin * 2);
                *(uint32_t*)(smc + M_XH + off) = bf16pair(h0, h1);
                *(uint32_t*)(smc + M_XL + off) = bf16pair(x0 - h0, x1 - h1);
            }
        }
        __syncthreads();
    }

    {
        float bo0 = bo[0], bo1 = bo[1];
        const int chn = lane >> 3;
        const int colin0 = (lane & 7) * 8;
        #pragma unroll
        for (int rr = 0; rr < 8; rr++) {
            int r = wid * 8 + rr;
            uint32_t off = (uint32_t)(chn * XCH + r * XSTRB + colin0 * 2);
            float a0 = 0.f, a1 = 0.f;
            #pragma unroll
            for (int kp = 0; kp < 4; kp++) {
                uint32_t uh = *(const uint32_t*)(smc + M_XH + off + kp * 4);
                uint32_t ul = *(const uint32_t*)(smc + M_XL + off + kp * 4);
                __nv_bfloat162 vh = *(__nv_bfloat162*)&uh;
                __nv_bfloat162 vl = *(__nv_bfloat162*)&ul;
                float x0 = __bfloat162float(vh.x) + __bfloat162float(vl.x);
                float x1 = __bfloat162float(vh.y) + __bfloat162float(vl.y);
                int col = lane * 8 + 2 * kp;
                float2 w0 = ((const float2*)Wo)[col];
                float2 w1 = ((const float2*)Wo)[col + 1];
                a0 += x0 * w0.x + x1 * w1.x;
                a1 += x0 * w0.y + x1 * w1.y;
            }
            #pragma unroll
            for (int o = 16; o > 0; o >>= 1) {
                a0 += __shfl_xor_sync(0xffffffffu, a0, o);
                a1 += __shfl_xor_sync(0xffffffffu, a1, o);
            }
            if (lane == 0) {
                out[(size_t)(b0 + r) * 2 + 0] = a0 + bo0;
                out[(size_t)(b0 + r) * 2 + 1] = a1 + bo1;
            }
        }
    }
}

extern "C" void kernel_launch(void* const* d_in, const int* in_sizes, int n_in,
                              void* d_out, int out_size)
{
    const float* obs   = (const float*)d_in[0];
    const float* ownW  = (const float*)d_in[1];
    const float* ownB  = (const float*)d_in[2];
    const float* intW  = (const float*)d_in[3];
    const float* intB  = (const float*)d_in[4];
    const float* Wq    = (const float*)d_in[5];
    const float* Wk    = (const float*)d_in[6];
    const float* Wv    = (const float*)d_in[7];
    const float* vatt  = (const float*)d_in[8];
    const float* projW = (const float*)d_in[9];
    const float* projB = (const float*)d_in[10];
    const float* W1    = (const float*)d_in[11];
    const float* b1    = (const float*)d_in[12];
    const float* W2    = (const float*)d_in[13];
    const float* b2    = (const float*)d_in[14];
    const float* Wo    = (const float*)d_in[15];
    const float* bo    = (const float*)d_in[16];
    float* out = (float*)d_out;

    cudaFuncSetAttribute(k_attn, cudaFuncAttributeMaxDynamicSharedMemorySize, SMEM1_BYTES);
    cudaFuncSetAttribute(k_mlp,  cudaFuncAttributeMaxDynamicSharedMemorySize, SMEM2_BYTES);

    k_prep<<<320, 256>>>(Wk, W1, W2, Wq);
    k_prep2<<<32, 256>>>(Wv, projW);
    k_attn<<<B_TOT / R1, NT, SMEM1_BYTES>>>(obs, ownW, ownB, intW, intB, vatt, projB);
    k_mlp<<<B_TOT / R2, NT, SMEM2_BYTES>>>(b1, b2, Wo, bo, out);
}

// round 13
// speedup vs baseline: 5.0743x; 1.0133x over previous
#include <cuda_runtime.h>
#include <cuda_bf16.h>
#include <math.h>
#include <stdint.h>

#define B_TOT   32768
#define OWN_DIM 3
#define N_INTR  32
#define INT_DIM 7
#define D       128
#define OBS_DIM 227
#define HID     256

#define R1      32
#define R2      128
#define X_STR   260
#define NT1     1024     // k_attn threads
#define NT2     512      // k_mlp threads

#define ASTR    272
#define TILE_BYTES (128 * ASTR)

#define BY_AHI    1024
#define BY_ALO    (BY_AHI + TILE_BYTES)
#define BY_BHI    (BY_ALO + TILE_BYTES)
#define BY_BLO    (BY_BHI + TILE_BYTES)
#define BY_F32    (BY_BLO + TILE_BYTES)
#define F_OBS   (BY_F32 / 4)
#define F_OWNE  (F_OBS  + R1 * OBS_DIM)
#define F_Q     (F_OWNE + R1 * D)
#define F_SC    (F_Q    + R1 * D)
#define F_AL    (F_SC   + R1 * N_INTR)
#define F_INTW  (F_AL   + R1 * N_INTR)
#define F_OWNW  (F_INTW + INT_DIM * D)
#define F_INTB  (F_OWNW + OWN_DIM * D)
#define F_VATT  (F_INTB + D)
#define F_MAP   (F_VATT + D)
#define F_WS    (F_MAP + R1 * N_INTR)
#define F_NC    (F_WS + 32)
#define SMEM1_BYTES ((F_NC + 1) * 4)

#define XSTRB   144
#define XCH     (R2 * XSTRB)
#define M_XH    0
#define M_XL    (4 * XCH)
#define M_WH    (8 * XCH)
#define M_WL    (M_WH + 256 * XSTRB)
#define SMEM2_BYTES (M_WL + 256 * XSTRB)

__device__ uint32_t gWkHi[8704], gWkLo[8704];
__device__ uint32_t gWqHi[8704], gWqLo[8704];
__device__ uint32_t gWvpHi[8704], gWvpLo[8704];
__device__ uint32_t gW1Hi[4][9216], gW1Lo[4][9216];
__device__ uint32_t gW2Hi[4][9216], gW2Lo[4][9216];
__device__ __nv_bfloat16 g_xh[(size_t)B_TOT * 256];
__device__ __nv_bfloat16 g_xl[(size_t)B_TOT * 256];

typedef unsigned long long u64;

__device__ __forceinline__ float lrelu(float x) { return fmaxf(x, 0.2f * x); }
__device__ __forceinline__ float tanh_ap(float x) {
    float y; asm("tanh.approx.f32 %0, %1;" : "=f"(y) : "f"(x)); return y;
}
__device__ __forceinline__ uint32_t smem_u32(const void* p) {
    uint32_t a;
    asm("{ .reg .u64 t; cvta.to.shared.u64 t, %1; cvt.u32.u64 %0, t; }" : "=r"(a) : "l"(p));
    return a;
}
__device__ __forceinline__ uint32_t bf16pair(float a, float b) {
    __nv_bfloat162 t = __floats2bfloat162_rn(a, b);
    return *(uint32_t*)&t;
}

#define LDSM_X4(r0, r1, r2, r3, addr) \
    asm volatile("ldmatrix.sync.aligned.m8n8.x4.shared.b16 {%0,%1,%2,%3}, [%4];" \
                 : "=r"(r0), "=r"(r1), "=r"(r2), "=r"(r3) : "r"(addr))

__device__ __forceinline__ void mma_bf16(float* c, const uint32_t* a, const uint32_t* b) {
    asm volatile(
        "mma.sync.aligned.m16n8k16.row.col.f32.bf16.bf16.f32 "
        "{%0,%1,%2,%3}, {%4,%5,%6,%7}, {%8,%9}, {%0,%1,%2,%3};"
        : "+f"(c[0]), "+f"(c[1]), "+f"(c[2]), "+f"(c[3])
        : "r"(a[0]), "r"(a[1]), "r"(a[2]), "r"(a[3]), "r"(b[0]), "r"(b[1]));
}

#define GROUP_BAR256(id) \
    asm volatile("bar.sync %0, 256;" :: "r"(id) : "memory")

// =====================================================================
// Prep kernels (unchanged from R12)
// =====================================================================
__global__ void __launch_bounds__(256, 4)
k_prep(const float* __restrict__ Wk, const float* __restrict__ W1,
       const float* __restrict__ W2, const float* __restrict__ Wq)
{
    int idx = blockIdx.x * 256 + threadIdx.x;
    if (idx < 2 * 8192) {
        const float* W = (idx < 8192) ? Wk : Wq;
        uint32_t* IH = (idx < 8192) ? gWkHi : gWqHi;
        uint32_t* IL = (idx < 8192) ? gWkLo : gWqLo;
        int j = idx & 8191;
        int ep = j >> 7, n = j & 127;
        int e0 = 2 * ep;
        float w0 = W[e0 * D + n], w1 = W[(e0 + 1) * D + n];
        float h0 = __bfloat162float(__float2bfloat16(w0));
        float h1 = __bfloat162float(__float2bfloat16(w1));
        int o = n * 68 + ep;
        IH[o] = bf16pair(h0, h1);
        IL[o] = bf16pair(w0 - h0, w1 - h1);
    } else if (idx < 2 * 8192 + 2 * 32768) {
        int j = idx - 2 * 8192;
        const float* W = (j < 32768) ? W1 : W2;
        uint32_t* WH = (j < 32768) ? &gW1Hi[0][0] : &gW2Hi[0][0];
        uint32_t* WL = (j < 32768) ? &gW1Lo[0][0] : &gW2Lo[0][0];
        j &= 32767;
        int kk = j >> 13, r = j & 8191;
        int n = r & 255, kp = r >> 8;
        int k0 = kk * 64 + 2 * kp;
        float w0 = W[(size_t)k0 * HID + n], w1 = W[(size_t)(k0 + 1) * HID + n];
        float h0 = __bfloat162float(__float2bfloat16(w0));
        float h1 = __bfloat162float(__float2bfloat16(w1));
        int o = kk * 9216 + n * 36 + kp;
        WH[o] = bf16pair(h0, h1);
        WL[o] = bf16pair(w0 - h0, w1 - h1);
    }
}

__global__ void __launch_bounds__(256, 4)
k_prep2(const float* __restrict__ Wv, const float* __restrict__ projW)
{
    int idx = blockIdx.x * 256 + threadIdx.x;
    int n = idx & 127, f0 = 2 * (idx >> 7);
    float s0 = 0.f, s1 = 0.f;
    #pragma unroll 4
    for (int e = 0; e < D; e++) {
        float pc = projW[e * D + n];
        s0 += Wv[f0 * D + e] * pc;
        s1 += Wv[(f0 + 1) * D + e] * pc;
    }
    float h0 = __bfloat162float(__float2bfloat16(s0));
    float h1 = __bfloat162float(__float2bfloat16(s1));
    int o = n * 68 + (f0 >> 1);
    gWvpHi[o] = bf16pair(h0, h1);
    gWvpLo[o] = bf16pair(s0 - h0, s1 - h1);
}

// =====================================================================
// Kernel 1: attention, 1024 threads, 32x16 warp tiles, 8-warp groups
// =====================================================================
__global__ void __launch_bounds__(NT1, 1)
k_attn(const float* __restrict__ obs,
       const float* __restrict__ ownW, const float* __restrict__ ownB,
       const float* __restrict__ intW, const float* __restrict__ intB,
       const float* __restrict__ vatt, const float* __restrict__ projB)
{
    extern __shared__ float sm[];
    char* smc = (char*)sm;
    const uint32_t smb = smem_u32(sm);

    float* sObs  = sm + F_OBS;
    float* sWsum = sm + F_OWNE;
    float* sQ    = sm + F_Q;
    float* sSc   = sm + F_SC;
    float* sAl   = sm + F_AL;
    float* sIntW = sm + F_INTW;
    float* sOwnW = sm + F_OWNW;
    float* sIntB = sm + F_INTB;
    float* sVatt = sm + F_VATT;
    int*   sMap  = (int*)(sm + F_MAP);
    int*   sWs   = (int*)(sm + F_WS);
    int*   sNC   = (int*)(sm + F_NC);

    const int tid  = threadIdx.x;
    const int wid  = tid >> 5;
    const int lane = tid & 31;
    const int b0   = blockIdx.x * R1;
    const float NEG_INF = __int_as_float(0xff800000u);

    // warp layout: 4 row-groups (wr) x 8 col-warps (wc); tile 32 rows x 16 cols
    const int wr = wid >> 3, wc = wid & 7;
    const int lt = lane >> 3, lw = lane & 7;
    const uint32_t aoff = (uint32_t)(((lt & 1) * 8 + lw) * ASTR + (lt >> 1) * 16);
    const uint32_t boff = (uint32_t)((((lt >> 1) * 8 + lw) + 16 * wc) * ASTR + (lt & 1) * 16);
    const uint32_t aBase0 = smb + BY_AHI + (uint32_t)(32 * wr) * ASTR + aoff;
    const uint32_t aBase1 = aBase0 + 16 * ASTR;
    const uint32_t alBase0 = aBase0 + TILE_BYTES;
    const uint32_t alBase1 = aBase1 + TILE_BYTES;
    const uint32_t bBase0  = smb + BY_BHI + boff;
    const uint32_t blBase0 = bBase0 + TILE_BYTES;
    // q/attn_vec GEMM bases (rows 0-31)
    const uint32_t aQ0 = smb + BY_AHI + aoff;
    const uint32_t aQ1 = aQ0 + 16 * ASTR;
    const uint32_t aQl0 = aQ0 + TILE_BYTES;
    const uint32_t aQl1 = aQ1 + TILE_BYTES;

    // ---- phase 1: stage obs + small weights + Wq image ----
    for (int i = tid; i < R1 * OBS_DIM; i += NT1) sObs[i] = obs[(size_t)b0 * OBS_DIM + i];
    for (int i = tid; i < INT_DIM * D; i += NT1)  sIntW[i] = intW[i];
    if (tid < OWN_DIM * D) sOwnW[tid] = ownW[tid];
    if (tid < D) { sIntB[tid] = intB[tid]; sVatt[tid] = vatt[tid]; }
    for (int i = tid; i < 2176; i += NT1) {
        ((uint4*)(smc + BY_BHI))[i] = ((const uint4*)gWqHi)[i];
        ((uint4*)(smc + BY_BLO))[i] = ((const uint4*)gWqLo)[i];
    }
    __syncthreads();

    // ---- phase 2: own_e -> A image + g_x; pad mask ----
    for (int i = tid; i < R1 * D; i += NT1) {
        int r = i >> 7, d = i & 127;
        const float* o = &sObs[r * OBS_DIM];
        float a = ownB[d] + o[0] * sOwnW[d] + o[1] * sOwnW[D + d] + o[2] * sOwnW[2 * D + d];
        a = lrelu(a);
        __nv_bfloat16 h = __float2bfloat16(a);
        float hf = __bfloat162float(h);
        uint32_t off = (uint32_t)r * ASTR + (uint32_t)d * 2;
        *(__nv_bfloat16*)(smc + BY_AHI + off) = h;
        *(__nv_bfloat16*)(smc + BY_ALO + off) = __float2bfloat16(a - hf);
        size_t gi = (size_t)(b0 + r) * 256 + d;
        g_xh[gi] = h;
        g_xl[gi] = __float2bfloat16(a - hf);
    }
    {   // 1024 pairs, 1 per thread
        int r = tid >> 5, n = tid & 31;
        const float* p = &sObs[r * OBS_DIM + OWN_DIM + n * INT_DIM];
        float s = 0.f;
        #pragma unroll
        for (int j = 0; j < INT_DIM; j++) s += fabsf(p[j]);
        sSc[tid] = (s < 1e-6f) ? NEG_INF : 0.f;
    }
    __syncthreads();

    // ---- phase 3: q = own_e @ Wq via HMMA (warps 0-7) ----
    if (wid < 8) {
        float c[2][2][4];
        #pragma unroll
        for (int mi = 0; mi < 2; mi++)
        #pragma unroll
        for (int ni = 0; ni < 2; ni++)
        #pragma unroll
        for (int j = 0; j < 4; j++) c[mi][ni][j] = 0.f;

        #pragma unroll
        for (int kk = 0; kk < 8; kk++) {
            const uint32_t ko = kk * 32;
            uint32_t ah[2][4], al[2][4], bh[4], bl[4];
            LDSM_X4(ah[0][0], ah[0][1], ah[0][2], ah[0][3], aQ0 + ko);
            LDSM_X4(ah[1][0], ah[1][1], ah[1][2], ah[1][3], aQ1 + ko);
            LDSM_X4(al[0][0], al[0][1], al[0][2], al[0][3], aQl0 + ko);
            LDSM_X4(al[1][0], al[1][1], al[1][2], al[1][3], aQl1 + ko);
            LDSM_X4(bh[0], bh[1], bh[2], bh[3], bBase0 + ko);
            LDSM_X4(bl[0], bl[1], bl[2], bl[3], blBase0 + ko);
            #pragma unroll
            for (int mi = 0; mi < 2; mi++)
            #pragma unroll
            for (int ni = 0; ni < 2; ni++) {
                mma_bf16(c[mi][ni], ah[mi], &bh[ni * 2]);
                mma_bf16(c[mi][ni], al[mi], &bh[ni * 2]);
                mma_bf16(c[mi][ni], ah[mi], &bl[ni * 2]);
            }
        }
        #pragma unroll
        for (int mi = 0; mi < 2; mi++)
        #pragma unroll
        for (int ci = 0; ci < 2; ci++) {
            int row = 16 * mi + 8 * ci + (lane >> 2);
            #pragma unroll
            for (int ni = 0; ni < 2; ni++) {
                int col = 16 * wc + 8 * ni + 2 * (lane & 3);
                sQ[row * D + col]     = c[mi][ni][2 * ci];
                sQ[row * D + col + 1] = c[mi][ni][2 * ci + 1];
            }
        }
    }
    __syncthreads();

    // ---- phase 4: compaction (1 pair per thread) ----
    {
        int flag = (sSc[tid] == 0.f) ? 1 : 0;
        unsigned bal = __ballot_sync(0xffffffffu, flag);
        int wpos = __popc(bal & ((1u << lane) - 1));
        if (lane == 0) sWs[wid] = __popc(bal);
        __syncthreads();
        if (tid == 0) {
            int acc = 0;
            for (int w = 0; w < 32; w++) { int t = sWs[w]; sWs[w] = acc; acc += t; }
            *sNC = acc;
        }
        __syncthreads();
        if (flag) sMap[sWs[wid] + wpos] = tid;
    }

    // ---- phase 5: Wk image into B ----
    for (int i = tid; i < 2176; i += NT1) {
        ((uint4*)(smc + BY_BHI))[i] = ((const uint4*)gWkHi)[i];
        ((uint4*)(smc + BY_BLO))[i] = ((const uint4*)gWkLo)[i];
    }
    __syncthreads();

    const int n_comp = *sNC;
    const int nch = (n_comp + 127) >> 7;

    const int gt = tid & 255;          // index within 8-warp group
    const int qd = 4 * (gt & 31);      // d quad per thread

    // ================= chunk loop =================
    for (int cc = 0; cc < nch; cc++) {
        // build: 32 rows x 32 quads per 256-thread group (4 iters)
        for (int it = gt; it < 32 * 32; it += 256) {
            int row = 32 * wr + (it >> 5);
            int g = cc * 128 + row;
            uint32_t off = (uint32_t)row * ASTR + (uint32_t)qd * 2;
            if (g < n_comp) {
                int pr = sMap[g];
                const float* p = &sObs[(pr >> 5) * OBS_DIM + OWN_DIM + (pr & 31) * INT_DIM];
                float4 acc = *(const float4*)&sIntB[qd];
                #pragma unroll
                for (int j = 0; j < INT_DIM; j++) {
                    float4 w = *(const float4*)&sIntW[j * D + qd];
                    float pj = p[j];
                    acc.x += pj * w.x; acc.y += pj * w.y;
                    acc.z += pj * w.z; acc.w += pj * w.w;
                }
                float v0 = lrelu(acc.x), v1 = lrelu(acc.y);
                float v2 = lrelu(acc.z), v3 = lrelu(acc.w);
                float h0 = __bfloat162float(__float2bfloat16(v0));
                float h1 = __bfloat162float(__float2bfloat16(v1));
                float h2 = __bfloat162float(__float2bfloat16(v2));
                float h3 = __bfloat162float(__float2bfloat16(v3));
                *(uint2*)(smc + BY_AHI + off) =
                    make_uint2(bf16pair(h0, h1), bf16pair(h2, h3));
                *(uint2*)(smc + BY_ALO + off) =
                    make_uint2(bf16pair(v0 - h0, v1 - h1), bf16pair(v2 - h2, v3 - h3));
            } else {
                *(uint2*)(smc + BY_AHI + off) = make_uint2(0u, 0u);
                *(uint2*)(smc + BY_ALO + off) = make_uint2(0u, 0u);
            }
        }
        GROUP_BAR256(wr + 1);

        if (cc * 128 + 32 * wr < n_comp) {
            float c[2][2][4];
            #pragma unroll
            for (int mi = 0; mi < 2; mi++)
            #pragma unroll
            for (int ni = 0; ni < 2; ni++)
            #pragma unroll
            for (int j = 0; j < 4; j++) c[mi][ni][j] = 0.f;

            #pragma unroll
            for (int kk = 0; kk < 8; kk++) {
                const uint32_t ko = kk * 32;
                uint32_t ah[2][4], al[2][4], bh[4], bl[4];
                LDSM_X4(ah[0][0], ah[0][1], ah[0][2], ah[0][3], aBase0 + ko);
                LDSM_X4(ah[1][0], ah[1][1], ah[1][2], ah[1][3], aBase1 + ko);
                LDSM_X4(al[0][0], al[0][1], al[0][2], al[0][3], alBase0 + ko);
                LDSM_X4(al[1][0], al[1][1], al[1][2], al[1][3], alBase1 + ko);
                LDSM_X4(bh[0], bh[1], bh[2], bh[3], bBase0 + ko);
                LDSM_X4(bl[0], bl[1], bl[2], bl[3], blBase0 + ko);
                #pragma unroll
                for (int mi = 0; mi < 2; mi++)
                #pragma unroll
                for (int ni = 0; ni < 2; ni++) {
                    mma_bf16(c[mi][ni], ah[mi], &bh[ni * 2]);
                    mma_bf16(c[mi][ni], al[mi], &bh[ni * 2]);
                    mma_bf16(c[mi][ni], ah[mi], &bl[ni * 2]);
                }
            }

            // epilogue
            float2 vv[2];
            #pragma unroll
            for (int ni = 0; ni < 2; ni++)
                vv[ni] = ((const float2*)sVatt)[8 * wc + 4 * ni + (lane & 3)];
            #pragma unroll
            for (int mi = 0; mi < 2; mi++)
            #pragma unroll
            for (int ci = 0; ci < 2; ci++) {
                int crow = 32 * wr + 16 * mi + 8 * ci + (lane >> 2);
                int g = cc * 128 + crow;
                bool ok = (g < n_comp);
                int pr = ok ? sMap[g] : 0;
                const float2* qr2 = (const float2*)&sQ[(pr >> 5) * D];
                float s = 0.f;
                #pragma unroll
                for (int ni = 0; ni < 2; ni++) {
                    float2 qv = qr2[8 * wc + 4 * ni + (lane & 3)];
                    s += tanh_ap(qv.x + c[mi][ni][2 * ci])     * vv[ni].x;
                    s += tanh_ap(qv.y + c[mi][ni][2 * ci + 1]) * vv[ni].y;
                }
                s += __shfl_xor_sync(0xffffffffu, s, 1);
                s += __shfl_xor_sync(0xffffffffu, s, 2);
                if (ok && (lane & 3) == 0) atomicAdd(&sSc[pr], s);
            }
        }
        GROUP_BAR256(wr + 1);
    }
    __syncthreads();

    // ---- softmax: 32 rows, one per warp ----
    {
        int r = wid;
        float s = sSc[r * N_INTR + lane];
        float m = s;
        #pragma unroll
        for (int o = 16; o > 0; o >>= 1) m = fmaxf(m, __shfl_xor_sync(0xffffffffu, m, o));
        float e = (m == NEG_INF) ? 0.f : __expf(s - m);
        float sum = e;
        #pragma unroll
        for (int o = 16; o > 0; o >>= 1) sum += __shfl_xor_sync(0xffffffffu, sum, o);
        sAl[r * N_INTR + lane] = (sum > 0.f) ? (e / sum) : 0.f;
    }
    __syncthreads();

    // ---- wsum = alpha @ int_e: one row per warp, 4 cols per lane ----
    {
        int r = wid;
        float wIW[INT_DIM][4];
        float wB[4];
        #pragma unroll
        for (int cq = 0; cq < 4; cq++) {
            wB[cq] = sIntB[4 * lane + cq];
            #pragma unroll
            for (int j = 0; j < INT_DIM; j++) wIW[j][cq] = sIntW[j * D + 4 * lane + cq];
        }
        float ws[4] = {0.f,0.f,0.f,0.f};
        for (int n = 0; n < N_INTR; n++) {
            float al = sAl[r * N_INTR + n];
            if (al != 0.f) {
                const float* p = &sObs[r * OBS_DIM + OWN_DIM + n * INT_DIM];
                float pj[INT_DIM];
                #pragma unroll
                for (int j = 0; j < INT_DIM; j++) pj[j] = p[j];
                #pragma unroll
                for (int cq = 0; cq < 4; cq++) {
                    float pre = wB[cq];
                    #pragma unroll
                    for (int j = 0; j < INT_DIM; j++) pre += pj[j] * wIW[j][cq];
                    ws[cq] += al * lrelu(pre);
                }
            }
        }
        #pragma unroll
        for (int cq = 0; cq < 4; cq++) sWsum[r * D + 4 * lane + cq] = ws[cq];
    }
    __syncthreads();

    // ---- split wsum into A image; WvProj image into B ----
    for (int i = tid; i < R1 * D; i += NT1) {
        int r = i >> 7, d = i & 127;
        float v = sWsum[i];
        __nv_bfloat16 h = __float2bfloat16(v);
        uint32_t off = (uint32_t)r * ASTR + (uint32_t)d * 2;
        *(__nv_bfloat16*)(smc + BY_AHI + off) = h;
        *(__nv_bfloat16*)(smc + BY_ALO + off) = __float2bfloat16(v - __bfloat162float(h));
    }
    for (int i = tid; i < 2176; i += NT1) {
        ((uint4*)(smc + BY_BHI))[i] = ((const uint4*)gWvpHi)[i];
        ((uint4*)(smc + BY_BLO))[i] = ((const uint4*)gWvpLo)[i];
    }
    __syncthreads();

    // ---- attn_vec = tanh(wsum @ WvProj + projB) via HMMA (warps 0-7) ----
    if (wid < 8) {
        float c[2][2][4];
        #pragma unroll
        for (int mi = 0; mi < 2; mi++)
        #pragma unroll
        for (int ni = 0; ni < 2; ni++)
        #pragma unroll
        for (int j = 0; j < 4; j++) c[mi][ni][j] = 0.f;

        #pragma unroll
        for (int kk = 0; kk < 8; kk++) {
            const uint32_t ko = kk * 32;
            uint32_t ah[2][4], al[2][4], bh[4], bl[4];
            LDSM_X4(ah[0][0], ah[0][1], ah[0][2], ah[0][3], aQ0 + ko);
            LDSM_X4(ah[1][0], ah[1][1], ah[1][2], ah[1][3], aQ1 + ko);
            LDSM_X4(al[0][0], al[0][1], al[0][2], al[0][3], aQl0 + ko);
            LDSM_X4(al[1][0], al[1][1], al[1][2], al[1][3], aQl1 + ko);
            LDSM_X4(bh[0], bh[1], bh[2], bh[3], bBase0 + ko);
            LDSM_X4(bl[0], bl[1], bl[2], bl[3], blBase0 + ko);
            #pragma unroll
            for (int mi = 0; mi < 2; mi++)
            #pragma unroll
            for (int ni = 0; ni < 2; ni++) {
                mma_bf16(c[mi][ni], ah[mi], &bh[ni * 2]);
                mma_bf16(c[mi][ni], al[mi], &bh[ni * 2]);
                mma_bf16(c[mi][ni], ah[mi], &bl[ni * 2]);
            }
        }
        #pragma unroll
        for (int mi = 0; mi < 2; mi++)
        #pragma unroll
        for (int ci = 0; ci < 2; ci++) {
            int row = 16 * mi + 8 * ci + (lane >> 2);
            size_t base = (size_t)(b0 + row) * 256 + 128;
            #pragma unroll
            for (int ni = 0; ni < 2; ni++) {
                int col = 16 * wc + 8 * ni + 2 * (lane & 3);
                float t0 = tanhf(c[mi][ni][2 * ci]     + projB[col]);
                float t1 = tanhf(c[mi][ni][2 * ci + 1] + projB[col + 1]);
                __nv_bfloat16 h0 = __float2bfloat16(t0);
                __nv_bfloat16 h1 = __float2bfloat16(t1);
                g_xh[base + col]     = h0;
                g_xl[base + col]     = __float2bfloat16(t0 - __bfloat162float(h0));
                g_xh[base + col + 1] = h1;
                g_xl[base + col + 1] = __float2bfloat16(t1 - __bfloat162float(h1));
            }
        }
    }
}

// =====================================================================
// Kernel 2: MLP (unchanged from R12, NT2=512)
// =====================================================================
__global__ void __launch_bounds__(NT2, 1)
k_mlp(const float* __restrict__ b1, const float* __restrict__ b2,
      const float* __restrict__ Wo, const float* __restrict__ bo,
      float* __restrict__ out)
{
    extern __shared__ float sm[];
    char* smc = (char*)sm;
    const uint32_t smb = smem_u32(sm);

    const int tid  = threadIdx.x;
    const int wid  = tid >> 5;
    const int lane = tid & 31;
    const int b0   = blockIdx.x * R2;
    const int wr = wid >> 3, wc = wid & 7;
    const int lt = lane >> 3, lw = lane & 7;

    for (int i = tid; i < 128 * 32; i += NT2) {
        int row = i >> 5, q = i & 31;
        int ch = q >> 3, qq = q & 7;
        size_t src = (size_t)(b0 + row) * 32 + q;
        uint32_t dst = (uint32_t)(ch * XCH + row * XSTRB + qq * 16);
        *(uint4*)(smc + M_XH + dst) = ((const uint4*)g_xh)[src];
        *(uint4*)(smc + M_XL + dst) = ((const uint4*)g_xl)[src];
    }

    const uint32_t aoff = (uint32_t)(((lt & 1) * 8 + lw) * XSTRB + (lt >> 1) * 16);
    const uint32_t boff = (uint32_t)((32 * wc + (lt >> 1) * 8 + lw) * XSTRB + (lt & 1) * 16);
    const uint32_t bB0 = smb + M_WH + boff;
    const uint32_t bB1 = bB0 + 16 * XSTRB;
    const uint32_t bL0 = bB0 + (M_WL - M_WH);
    const uint32_t bL1 = bB1 + (M_WL - M_WH);

    for (int layer = 0; layer < 2; layer++) {
        const float* bias = layer ? b2 : b1;

        float c[4][4][4];
        #pragma unroll
        for (int mi = 0; mi < 4; mi++)
        #pragma unroll
        for (int ni = 0; ni < 4; ni++)
        #pragma unroll
        for (int j = 0; j < 4; j++) c[mi][ni][j] = 0.f;

        for (int kk = 0; kk < 4; kk++) {
            {
                const uint4* WH = (const uint4*)(layer ? gW2Hi[kk] : gW1Hi[kk]);
                const uint4* WL = (const uint4*)(layer ? gW2Lo[kk] : gW1Lo[kk]);
                for (int i = tid; i < 2304; i += NT2) {
                    ((uint4*)(smc + M_WH))[i] = WH[i];
                    ((uint4*)(smc + M_WL))[i] = WL[i];
                }
            }
            __syncthreads();

            const uint32_t aChunk = smb + M_XH + (uint32_t)(kk * XCH)
                                  + (uint32_t)(64 * wr) * XSTRB + aoff;
            #pragma unroll
            for (int ks = 0; ks < 4; ks++) {
                const uint32_t ko = ks * 32;
                uint32_t af[4][4], bh[2][4], bl[2][4];
                #pragma unroll
                for (int m = 0; m < 4; m++)
                    LDSM_X4(af[m][0], af[m][1], af[m][2], af[m][3],
                            aChunk + (uint32_t)(16 * m) * XSTRB + ko);
                LDSM_X4(bh[0][0], bh[0][1], bh[0][2], bh[0][3], bB0 + ko);
                LDSM_X4(bh[1][0], bh[1][1], bh[1][2], bh[1][3], bB1 + ko);
                LDSM_X4(bl[0][0], bl[0][1], bl[0][2], bl[0][3], bL0 + ko);
                LDSM_X4(bl[1][0], bl[1][1], bl[1][2], bl[1][3], bL1 + ko);

                #pragma unroll
                for (int mi = 0; mi < 4; mi++)
                #pragma unroll
                for (int ni = 0; ni < 4; ni++) {
                    const uint32_t* bfh = &bh[ni >> 1][(ni & 1) * 2];
                    const uint32_t* bfl = &bl[ni >> 1][(ni & 1) * 2];
                    mma_bf16(c[mi][ni], af[mi], bfh);
                    mma_bf16(c[mi][ni], af[mi], bfl);
                }
                #pragma unroll
                for (int m = 0; m < 4; m++)
                    LDSM_X4(af[m][0], af[m][1], af[m][2], af[m][3],
                            aChunk + (M_XL - M_XH) + (uint32_t)(16 * m) * XSTRB + ko);
                #pragma unroll
                for (int mi = 0; mi < 4; mi++)
                #pragma unroll
                for (int ni = 0; ni < 4; ni++) {
                    const uint32_t* bfh = &bh[ni >> 1][(ni & 1) * 2];
                    mma_bf16(c[mi][ni], af[mi], bfh);
                }
            }
            __syncthreads();
        }

        const int chn = wc >> 1;
        #pragma unroll
        for (int mi = 0; mi < 4; mi++)
        #pragma unroll
        for (int ci = 0; ci < 2; ci++) {
            int row = 64 * wr + 16 * mi + 8 * ci + (lane >> 2);
            #pragma unroll
            for (int ni = 0; ni < 4; ni++) {
                int col = 32 * wc + 8 * ni + 2 * (lane & 3);
                int colin = (wc & 1) * 32 + 8 * ni + 2 * (lane & 3);
                float x0 = lrelu(c[mi][ni][2 * ci]     + bias[col]);
                float x1 = lrelu(c[mi][ni][2 * ci + 1] + bias[col + 1]);
                float h0 = __bfloat162float(__float2bfloat16(x0));
                float h1 = __bfloat162float(__float2bfloat16(x1));
                uint32_t off = (uint32_t)(chn * XCH + row * XSTRB + colin * 2);
                *(uint32_t*)(smc + M_XH + off) = bf16pair(h0, h1);
                *(uint32_t*)(smc + M_XL + off) = bf16pair(x0 - h0, x1 - h1);
            }
        }
        __syncthreads();
    }

    {
        float bo0 = bo[0], bo1 = bo[1];
        const int chn = lane >> 3;
        const int colin0 = (lane & 7) * 8;
        #pragma unroll
        for (int rr = 0; rr < 8; rr++) {
            int r = wid * 8 + rr;
            uint32_t off = (uint32_t)(chn * XCH + r * XSTRB + colin0 * 2);
            float a0 = 0.f, a1 = 0.f;
            #pragma unroll
            for (int kp = 0; kp < 4; kp++) {
                uint32_t uh = *(const uint32_t*)(smc + M_XH + off + kp * 4);
                uint32_t ul = *(const uint32_t*)(smc + M_XL + off + kp * 4);
                __nv_bfloat162 vh = *(__nv_bfloat162*)&uh;
                __nv_bfloat162 vl = *(__nv_bfloat162*)&ul;
                float x0 = __bfloat162float(vh.x) + __bfloat162float(vl.x);
                float x1 = __bfloat162float(vh.y) + __bfloat162float(vl.y);
                int col = lane * 8 + 2 * kp;
                float2 w0 = ((const float2*)Wo)[col];
                float2 w1 = ((const float2*)Wo)[col + 1];
                a0 += x0 * w0.x + x1 * w1.x;
                a1 += x0 * w0.y + x1 * w1.y;
            }
            #pragma unroll
            for (int o = 16; o > 0; o >>= 1) {
                a0 += __shfl_xor_sync(0xffffffffu, a0, o);
                a1 += __shfl_xor_sync(0xffffffffu, a1, o);
            }
            if (lane == 0) {
                out[(size_t)(b0 + r) * 2 + 0] = a0 + bo0;
                out[(size_t)(b0 + r) * 2 + 1] = a1 + bo1;
            }
        }
    }
}

extern "C" void kernel_launch(void* const* d_in, const int* in_sizes, int n_in,
                              void* d_out, int out_size)
{
    const float* obs   = (const float*)d_in[0];
    const float* ownW  = (const float*)d_in[1];
    const float* ownB  = (const float*)d_in[2];
    const float* intW  = (const float*)d_in[3];
    const float* intB  = (const float*)d_in[4];
    const float* Wq    = (const float*)d_in[5];
    const float* Wk    = (const float*)d_in[6];
    const float* Wv    = (const float*)d_in[7];
    const float* vatt  = (const float*)d_in[8];
    const float* projW = (const float*)d_in[9];
    const float* projB = (const float*)d_in[10];
    const float* W1    = (const float*)d_in[11];
    const float* b1    = (const float*)d_in[12];
    const float* W2    = (const float*)d_in[13];
    const float* b2    = (const float*)d_in[14];
    const float* Wo    = (const float*)d_in[15];
    const float* bo    = (const float*)d_in[16];
    float* out = (float*)d_out;

    cudaFuncSetAttribute(k_attn, cudaFuncAttributeMaxDynamicSharedMemorySize, SMEM1_BYTES);
    cudaFuncSetAttribute(k_mlp,  cudaFuncAttributeMaxDynamicSharedMemorySize, SMEM2_BYTES);

    k_prep<<<320, 256>>>(Wk, W1, W2, Wq);
    k_prep2<<<32, 256>>>(Wv, projW);
    k_attn<<<B_TOT / R1, NT1, SMEM1_BYTES>>>(obs, ownW, ownB, intW, intB, vatt, projB);
    k_mlp<<<B_TOT / R2, NT2, SMEM2_BYTES>>>(b1, b2, Wo, bo, out);
}

// round 14
// speedup vs baseline: 5.3017x; 1.0448x over previous
#include <cuda_runtime.h>
#include <cuda_bf16.h>
#include <cuda_fp16.h>
#include <math.h>
#include <stdint.h>

#define B_TOT   32768
#define OWN_DIM 3
#define N_INTR  32
#define INT_DIM 7
#define D       128
#define OBS_DIM 227
#define HID     256

#define R1      32
#define R2      128
#define X_STR   260
#define NT1     1024
#define NT2     512

#define ASTR    272
#define TILE_BYTES (128 * ASTR)

#define BY_AHI    1024
#define BY_ALO    (BY_AHI + TILE_BYTES)
#define BY_BHI    (BY_ALO + TILE_BYTES)
#define BY_BLO    (BY_BHI + TILE_BYTES)
#define BY_F32    (BY_BLO + TILE_BYTES)
#define F_OBS   (BY_F32 / 4)
#define F_OWNE  (F_OBS  + R1 * OBS_DIM)
#define F_Q     (F_OWNE + R1 * D)
#define F_SC    (F_Q    + R1 * D)
#define F_AL    (F_SC   + R1 * N_INTR)
#define F_INTW  (F_AL   + R1 * N_INTR)
#define F_OWNW  (F_INTW + INT_DIM * D)
#define F_INTB  (F_OWNW + OWN_DIM * D)
#define F_VATT  (F_INTB + D)
#define F_MAP   (F_VATT + D)
#define F_WS    (F_MAP + R1 * N_INTR)
#define F_NC    (F_WS + 32)
#define SMEM1_BYTES ((F_NC + 1) * 4)

#define XSTRB   144
#define XCH     (R2 * XSTRB)
#define M_XH    0
#define M_XL    (4 * XCH)
#define M_WH    (8 * XCH)
#define M_WL    (M_WH + 256 * XSTRB)
#define SMEM2_BYTES (M_WL + 256 * XSTRB)

__device__ uint32_t gWkHi[8704];                 // Wk fp16 image (single precision part)
__device__ uint32_t gWqHi[8704], gWqLo[8704];    // Wq bf16 hi/lo
__device__ uint32_t gWvpHi[8704], gWvpLo[8704];  // WvProj bf16 hi/lo
__device__ uint32_t gW1Hi[4][9216], gW1Lo[4][9216];
__device__ uint32_t gW2Hi[4][9216], gW2Lo[4][9216];
__device__ __nv_bfloat16 g_xh[(size_t)B_TOT * 256];
__device__ __nv_bfloat16 g_xl[(size_t)B_TOT * 256];

typedef unsigned long long u64;

__device__ __forceinline__ float lrelu(float x) { return fmaxf(x, 0.2f * x); }
__device__ __forceinline__ float tanh_ap(float x) {
    float y; asm("tanh.approx.f32 %0, %1;" : "=f"(y) : "f"(x)); return y;
}
__device__ __forceinline__ uint32_t smem_u32(const void* p) {
    uint32_t a;
    asm("{ .reg .u64 t; cvta.to.shared.u64 t, %1; cvt.u32.u64 %0, t; }" : "=r"(a) : "l"(p));
    return a;
}
__device__ __forceinline__ uint32_t bf16pair(float a, float b) {
    __nv_bfloat162 t = __floats2bfloat162_rn(a, b);
    return *(uint32_t*)&t;
}
__device__ __forceinline__ uint32_t f16pair(float a, float b) {
    __half2 t = __floats2half2_rn(a, b);
    return *(uint32_t*)&t;
}

#define LDSM_X4(r0, r1, r2, r3, addr) \
    asm volatile("ldmatrix.sync.aligned.m8n8.x4.shared.b16 {%0,%1,%2,%3}, [%4];" \
                 : "=r"(r0), "=r"(r1), "=r"(r2), "=r"(r3) : "r"(addr))

__device__ __forceinline__ void mma_bf16(float* c, const uint32_t* a, const uint32_t* b) {
    asm volatile(
        "mma.sync.aligned.m16n8k16.row.col.f32.bf16.bf16.f32 "
        "{%0,%1,%2,%3}, {%4,%5,%6,%7}, {%8,%9}, {%0,%1,%2,%3};"
        : "+f"(c[0]), "+f"(c[1]), "+f"(c[2]), "+f"(c[3])
        : "r"(a[0]), "r"(a[1]), "r"(a[2]), "r"(a[3]), "r"(b[0]), "r"(b[1]));
}
__device__ __forceinline__ void mma_f16(float* c, const uint32_t* a, const uint32_t* b) {
    asm volatile(
        "mma.sync.aligned.m16n8k16.row.col.f32.f16.f16.f32 "
        "{%0,%1,%2,%3}, {%4,%5,%6,%7}, {%8,%9}, {%0,%1,%2,%3};"
        : "+f"(c[0]), "+f"(c[1]), "+f"(c[2]), "+f"(c[3])
        : "r"(a[0]), "r"(a[1]), "r"(a[2]), "r"(a[3]), "r"(b[0]), "r"(b[1]));
}

#define GROUP_BAR256(id) \
    asm volatile("bar.sync %0, 256;" :: "r"(id) : "memory")

// =====================================================================
// Prep: Wk (fp16), Wq (bf16 hi/lo), W1/W2 (bf16 hi/lo), WvProj (bf16 hi/lo)
// =====================================================================
__global__ void __launch_bounds__(256, 4)
k_prep(const float* __restrict__ Wk, const float* __restrict__ W1,
       const float* __restrict__ W2, const float* __restrict__ Wq,
       const float* __restrict__ Wv, const float* __restrict__ projW)
{
    int idx = blockIdx.x * 256 + threadIdx.x;
    if (idx < 8192) {                       // Wk: fp16 single image
        int ep = idx >> 7, n = idx & 127;
        int e0 = 2 * ep;
        float w0 = Wk[e0 * D + n], w1 = Wk[(e0 + 1) * D + n];
        gWkHi[n * 68 + ep] = f16pair(w0, w1);
    } else if (idx < 2 * 8192) {            // Wq: bf16 hi/lo
        int j = idx & 8191;
        int ep = j >> 7, n = j & 127;
        int e0 = 2 * ep;
        float w0 = Wq[e0 * D + n], w1 = Wq[(e0 + 1) * D + n];
        float h0 = __bfloat162float(__float2bfloat16(w0));
        float h1 = __bfloat162float(__float2bfloat16(w1));
        int o = n * 68 + ep;
        gWqHi[o] = bf16pair(h0, h1);
        gWqLo[o] = bf16pair(w0 - h0, w1 - h1);
    } else if (idx < 2 * 8192 + 2 * 32768) {
        int j = idx - 2 * 8192;
        const float* W = (j < 32768) ? W1 : W2;
        uint32_t* WH = (j < 32768) ? &gW1Hi[0][0] : &gW2Hi[0][0];
        uint32_t* WL = (j < 32768) ? &gW1Lo[0][0] : &gW2Lo[0][0];
        j &= 32767;
        int kk = j >> 13, r = j & 8191;
        int n = r & 255, kp = r >> 8;
        int k0 = kk * 64 + 2 * kp;
        float w0 = W[(size_t)k0 * HID + n], w1 = W[(size_t)(k0 + 1) * HID + n];
        float h0 = __bfloat162float(__float2bfloat16(w0));
        float h1 = __bfloat162float(__float2bfloat16(w1));
        int o = kk * 9216 + n * 36 + kp;
        WH[o] = bf16pair(h0, h1);
        WL[o] = bf16pair(w0 - h0, w1 - h1);
    } else if (idx < 2 * 8192 + 2 * 32768 + 8192) {   // WvProj fused
        int j = idx - (2 * 8192 + 2 * 32768);
        int n = j & 127, f0 = 2 * (j >> 7);
        float s0 = 0.f, s1 = 0.f;
        #pragma unroll 4
        for (int e = 0; e < D; e++) {
            float pc = projW[e * D + n];
            s0 += Wv[f0 * D + e] * pc;
            s1 += Wv[(f0 + 1) * D + e] * pc;
        }
        float h0 = __bfloat162float(__float2bfloat16(s0));
        float h1 = __bfloat162float(__float2bfloat16(s1));
        int o = n * 68 + (f0 >> 1);
        gWvpHi[o] = bf16pair(h0, h1);
        gWvpLo[o] = bf16pair(s0 - h0, s1 - h1);
    }
}

// =====================================================================
// Kernel 1: attention; scores GEMM = fp16 2-pass, small GEMMs bf16 3-pass
// =====================================================================
__global__ void __launch_bounds__(NT1, 1)
k_attn(const float* __restrict__ obs,
       const float* __restrict__ ownW, const float* __restrict__ ownB,
       const float* __restrict__ intW, const float* __restrict__ intB,
       const float* __restrict__ vatt, const float* __restrict__ projB)
{
    extern __shared__ float sm[];
    char* smc = (char*)sm;
    const uint32_t smb = smem_u32(sm);

    float* sObs  = sm + F_OBS;
    float* sWsum = sm + F_OWNE;
    float* sQ    = sm + F_Q;
    float* sSc   = sm + F_SC;
    float* sAl   = sm + F_AL;
    float* sIntW = sm + F_INTW;
    float* sOwnW = sm + F_OWNW;
    float* sIntB = sm + F_INTB;
    float* sVatt = sm + F_VATT;
    int*   sMap  = (int*)(sm + F_MAP);
    int*   sWs   = (int*)(sm + F_WS);
    int*   sNC   = (int*)(sm + F_NC);

    const int tid  = threadIdx.x;
    const int wid  = tid >> 5;
    const int lane = tid & 31;
    const int b0   = blockIdx.x * R1;
    const float NEG_INF = __int_as_float(0xff800000u);

    const int wr = wid >> 3, wc = wid & 7;
    const int lt = lane >> 3, lw = lane & 7;
    const uint32_t aoff = (uint32_t)(((lt & 1) * 8 + lw) * ASTR + (lt >> 1) * 16);
    const uint32_t boff = (uint32_t)((((lt >> 1) * 8 + lw) + 16 * wc) * ASTR + (lt & 1) * 16);
    const uint32_t aBase0 = smb + BY_AHI + (uint32_t)(32 * wr) * ASTR + aoff;
    const uint32_t aBase1 = aBase0 + 16 * ASTR;
    const uint32_t alBase0 = aBase0 + TILE_BYTES;
    const uint32_t alBase1 = aBase1 + TILE_BYTES;
    const uint32_t bBase0  = smb + BY_BHI + boff;
    const uint32_t blBase0 = bBase0 + TILE_BYTES;
    const uint32_t aQ0 = smb + BY_AHI + aoff;
    const uint32_t aQ1 = aQ0 + 16 * ASTR;
    const uint32_t aQl0 = aQ0 + TILE_BYTES;
    const uint32_t aQl1 = aQ1 + TILE_BYTES;

    // ---- phase 1: stage obs + small weights + Wq image (bf16 hi/lo) ----
    for (int i = tid; i < R1 * OBS_DIM; i += NT1) sObs[i] = obs[(size_t)b0 * OBS_DIM + i];
    for (int i = tid; i < INT_DIM * D; i += NT1)  sIntW[i] = intW[i];
    if (tid < OWN_DIM * D) sOwnW[tid] = ownW[tid];
    if (tid < D) { sIntB[tid] = intB[tid]; sVatt[tid] = vatt[tid]; }
    for (int i = tid; i < 2176; i += NT1) {
        ((uint4*)(smc + BY_BHI))[i] = ((const uint4*)gWqHi)[i];
        ((uint4*)(smc + BY_BLO))[i] = ((const uint4*)gWqLo)[i];
    }
    __syncthreads();

    // ---- phase 2: own_e -> A image (bf16 hi/lo) + g_x; pad mask ----
    for (int i = tid; i < R1 * D; i += NT1) {
        int r = i >> 7, d = i & 127;
        const float* o = &sObs[r * OBS_DIM];
        float a = ownB[d] + o[0] * sOwnW[d] + o[1] * sOwnW[D + d] + o[2] * sOwnW[2 * D + d];
        a = lrelu(a);
        __nv_bfloat16 h = __float2bfloat16(a);
        float hf = __bfloat162float(h);
        uint32_t off = (uint32_t)r * ASTR + (uint32_t)d * 2;
        *(__nv_bfloat16*)(smc + BY_AHI + off) = h;
        *(__nv_bfloat16*)(smc + BY_ALO + off) = __float2bfloat16(a - hf);
        size_t gi = (size_t)(b0 + r) * 256 + d;
        g_xh[gi] = h;
        g_xl[gi] = __float2bfloat16(a - hf);
    }
    {
        int r = tid >> 5, n = tid & 31;
        const float* p = &sObs[r * OBS_DIM + OWN_DIM + n * INT_DIM];
        float s = 0.f;
        #pragma unroll
        for (int j = 0; j < INT_DIM; j++) s += fabsf(p[j]);
        sSc[tid] = (s < 1e-6f) ? NEG_INF : 0.f;
    }
    __syncthreads();

    // ---- phase 3: q = own_e @ Wq via bf16 HMMA (warps 0-7) ----
    if (wid < 8) {
        float c[2][2][4];
        #pragma unroll
        for (int mi = 0; mi < 2; mi++)
        #pragma unroll
        for (int ni = 0; ni < 2; ni++)
        #pragma unroll
        for (int j = 0; j < 4; j++) c[mi][ni][j] = 0.f;

        #pragma unroll
        for (int kk = 0; kk < 8; kk++) {
            const uint32_t ko = kk * 32;
            uint32_t ah[2][4], al[2][4], bh[4], bl[4];
            LDSM_X4(ah[0][0], ah[0][1], ah[0][2], ah[0][3], aQ0 + ko);
            LDSM_X4(ah[1][0], ah[1][1], ah[1][2], ah[1][3], aQ1 + ko);
            LDSM_X4(al[0][0], al[0][1], al[0][2], al[0][3], aQl0 + ko);
            LDSM_X4(al[1][0], al[1][1], al[1][2], al[1][3], aQl1 + ko);
            LDSM_X4(bh[0], bh[1], bh[2], bh[3], bBase0 + ko);
            LDSM_X4(bl[0], bl[1], bl[2], bl[3], blBase0 + ko);
            #pragma unroll
            for (int mi = 0; mi < 2; mi++)
            #pragma unroll
            for (int ni = 0; ni < 2; ni++) {
                mma_bf16(c[mi][ni], ah[mi], &bh[ni * 2]);
                mma_bf16(c[mi][ni], al[mi], &bh[ni * 2]);
                mma_bf16(c[mi][ni], ah[mi], &bl[ni * 2]);
            }
        }
        #pragma unroll
        for (int mi = 0; mi < 2; mi++)
        #pragma unroll
        for (int ci = 0; ci < 2; ci++) {
            int row = 16 * mi + 8 * ci + (lane >> 2);
            #pragma unroll
            for (int ni = 0; ni < 2; ni++) {
                int col = 16 * wc + 8 * ni + 2 * (lane & 3);
                sQ[row * D + col]     = c[mi][ni][2 * ci];
                sQ[row * D + col + 1] = c[mi][ni][2 * ci + 1];
            }
        }
    }
    __syncthreads();

    // ---- phase 4: compaction ----
    {
        int flag = (sSc[tid] == 0.f) ? 1 : 0;
        unsigned bal = __ballot_sync(0xffffffffu, flag);
        int wpos = __popc(bal & ((1u << lane) - 1));
        if (lane == 0) sWs[wid] = __popc(bal);
        __syncthreads();
        if (tid == 0) {
            int acc = 0;
            for (int w = 0; w < 32; w++) { int t = sWs[w]; sWs[w] = acc; acc += t; }
            *sNC = acc;
        }
        __syncthreads();
        if (flag) sMap[sWs[wid] + wpos] = tid;
    }

    // ---- phase 5: Wk fp16 image into B-hi only ----
    for (int i = tid; i < 2176; i += NT1)
        ((uint4*)(smc + BY_BHI))[i] = ((const uint4*)gWkHi)[i];
    __syncthreads();

    const int n_comp = *sNC;
    const int nch = (n_comp + 127) >> 7;

    const int gt = tid & 255;
    const int qd = 4 * (gt & 31);

    // ================= chunk loop: fp16 2-pass =================
    for (int cc = 0; cc < nch; cc++) {
        for (int it = gt; it < 32 * 32; it += 256) {
            int row = 32 * wr + (it >> 5);
            int g = cc * 128 + row;
            uint32_t off = (uint32_t)row * ASTR + (uint32_t)qd * 2;
            if (g < n_comp) {
                int pr = sMap[g];
                const float* p = &sObs[(pr >> 5) * OBS_DIM + OWN_DIM + (pr & 31) * INT_DIM];
                float4 acc = *(const float4*)&sIntB[qd];
                #pragma unroll
                for (int j = 0; j < INT_DIM; j++) {
                    float4 w = *(const float4*)&sIntW[j * D + qd];
                    float pj = p[j];
                    acc.x += pj * w.x; acc.y += pj * w.y;
                    acc.z += pj * w.z; acc.w += pj * w.w;
                }
                float v0 = lrelu(acc.x), v1 = lrelu(acc.y);
                float v2 = lrelu(acc.z), v3 = lrelu(acc.w);
                // fp16 split: hi + lo (residual ~2^-24)
                float h0 = __half2float(__float2half_rn(v0));
                float h1 = __half2float(__float2half_rn(v1));
                float h2 = __half2float(__float2half_rn(v2));
                float h3 = __half2float(__float2half_rn(v3));
                *(uint2*)(smc + BY_AHI + off) =
                    make_uint2(f16pair(h0, h1), f16pair(h2, h3));
                *(uint2*)(smc + BY_ALO + off) =
                    make_uint2(f16pair(v0 - h0, v1 - h1), f16pair(v2 - h2, v3 - h3));
            } else {
                *(uint2*)(smc + BY_AHI + off) = make_uint2(0u, 0u);
                *(uint2*)(smc + BY_ALO + off) = make_uint2(0u, 0u);
            }
        }
        GROUP_BAR256(wr + 1);

        if (cc * 128 + 32 * wr < n_comp) {
            float c[2][2][4];
            #pragma unroll
            for (int mi = 0; mi < 2; mi++)
            #pragma unroll
            for (int ni = 0; ni < 2; ni++)
            #pragma unroll
            for (int j = 0; j < 4; j++) c[mi][ni][j] = 0.f;

            #pragma unroll
            for (int kk = 0; kk < 8; kk++) {
                const uint32_t ko = kk * 32;
                uint32_t ah[2][4], al[2][4], bh[4];
                LDSM_X4(ah[0][0], ah[0][1], ah[0][2], ah[0][3], aBase0 + ko);
                LDSM_X4(ah[1][0], ah[1][1], ah[1][2], ah[1][3], aBase1 + ko);
                LDSM_X4(al[0][0], al[0][1], al[0][2], al[0][3], alBase0 + ko);
                LDSM_X4(al[1][0], al[1][1], al[1][2], al[1][3], alBase1 + ko);
                LDSM_X4(bh[0], bh[1], bh[2], bh[3], bBase0 + ko);
                #pragma unroll
                for (int mi = 0; mi < 2; mi++)
                #pragma unroll
                for (int ni = 0; ni < 2; ni++) {
                    mma_f16(c[mi][ni], ah[mi], &bh[ni * 2]);
                    mma_f16(c[mi][ni], al[mi], &bh[ni * 2]);
                }
            }

            float2 vv[2];
            #pragma unroll
            for (int ni = 0; ni < 2; ni++)
                vv[ni] = ((const float2*)sVatt)[8 * wc + 4 * ni + (lane & 3)];
            #pragma unroll
            for (int mi = 0; mi < 2; mi++)
            #pragma unroll
            for (int ci = 0; ci < 2; ci++) {
                int crow = 32 * wr + 16 * mi + 8 * ci + (lane >> 2);
                int g = cc * 128 + crow;
                bool ok = (g < n_comp);
                int pr = ok ? sMap[g] : 0;
                const float2* qr2 = (const float2*)&sQ[(pr >> 5) * D];
                float s = 0.f;
                #pragma unroll
                for (int ni = 0; ni < 2; ni++) {
                    float2 qv = qr2[8 * wc + 4 * ni + (lane & 3)];
                    s += tanh_ap(qv.x + c[mi][ni][2 * ci])     * vv[ni].x;
                    s += tanh_ap(qv.y + c[mi][ni][2 * ci + 1]) * vv[ni].y;
                }
                s += __shfl_xor_sync(0xffffffffu, s, 1);
                s += __shfl_xor_sync(0xffffffffu, s, 2);
                if (ok && (lane & 3) == 0) atomicAdd(&sSc[pr], s);
            }
        }
        GROUP_BAR256(wr + 1);
    }
    __syncthreads();

    // ---- softmax ----
    {
        int r = wid;
        float s = sSc[r * N_INTR + lane];
        float m = s;
        #pragma unroll
        for (int o = 16; o > 0; o >>= 1) m = fmaxf(m, __shfl_xor_sync(0xffffffffu, m, o));
        float e = (m == NEG_INF) ? 0.f : __expf(s - m);
        float sum = e;
        #pragma unroll
        for (int o = 16; o > 0; o >>= 1) sum += __shfl_xor_sync(0xffffffffu, sum, o);
        sAl[r * N_INTR + lane] = (sum > 0.f) ? (e / sum) : 0.f;
    }
    __syncthreads();

    // ---- wsum = alpha @ int_e ----
    {
        int r = wid;
        float wIW[INT_DIM][4];
        float wB[4];
        #pragma unroll
        for (int cq = 0; cq < 4; cq++) {
            wB[cq] = sIntB[4 * lane + cq];
            #pragma unroll
            for (int j = 0; j < INT_DIM; j++) wIW[j][cq] = sIntW[j * D + 4 * lane + cq];
        }
        float ws[4] = {0.f,0.f,0.f,0.f};
        for (int n = 0; n < N_INTR; n++) {
            float al = sAl[r * N_INTR + n];
            if (al != 0.f) {
                const float* p = &sObs[r * OBS_DIM + OWN_DIM + n * INT_DIM];
                float pj[INT_DIM];
                #pragma unroll
                for (int j = 0; j < INT_DIM; j++) pj[j] = p[j];
                #pragma unroll
                for (int cq = 0; cq < 4; cq++) {
                    float pre = wB[cq];
                    #pragma unroll
                    for (int j = 0; j < INT_DIM; j++) pre += pj[j] * wIW[j][cq];
                    ws[cq] += al * lrelu(pre);
                }
            }
        }
        #pragma unroll
        for (int cq = 0; cq < 4; cq++) sWsum[r * D + 4 * lane + cq] = ws[cq];
    }
    __syncthreads();

    // ---- split wsum (bf16) into A image; WvProj bf16 image into B ----
    for (int i = tid; i < R1 * D; i += NT1) {
        int r = i >> 7, d = i & 127;
        float v = sWsum[i];
        __nv_bfloat16 h = __float2bfloat16(v);
        uint32_t off = (uint32_t)r * ASTR + (uint32_t)d * 2;
        *(__nv_bfloat16*)(smc + BY_AHI + off) = h;
        *(__nv_bfloat16*)(smc + BY_ALO + off) = __float2bfloat16(v - __bfloat162float(h));
    }
    for (int i = tid; i < 2176; i += NT1) {
        ((uint4*)(smc + BY_BHI))[i] = ((const uint4*)gWvpHi)[i];
        ((uint4*)(smc + BY_BLO))[i] = ((const uint4*)gWvpLo)[i];
    }
    __syncthreads();

    // ---- attn_vec = tanh(wsum @ WvProj + projB) via bf16 HMMA ----
    if (wid < 8) {
        float c[2][2][4];
        #pragma unroll
        for (int mi = 0; mi < 2; mi++)
        #pragma unroll
        for (int ni = 0; ni < 2; ni++)
        #pragma unroll
        for (int j = 0; j < 4; j++) c[mi][ni][j] = 0.f;

        #pragma unroll
        for (int kk = 0; kk < 8; kk++) {
            const uint32_t ko = kk * 32;
            uint32_t ah[2][4], al[2][4], bh[4], bl[4];
            LDSM_X4(ah[0][0], ah[0][1], ah[0][2], ah[0][3], aQ0 + ko);
            LDSM_X4(ah[1][0], ah[1][1], ah[1][2], ah[1][3], aQ1 + ko);
            LDSM_X4(al[0][0], al[0][1], al[0][2], al[0][3], aQl0 + ko);
            LDSM_X4(al[1][0], al[1][1], al[1][2], al[1][3], aQl1 + ko);
            LDSM_X4(bh[0], bh[1], bh[2], bh[3], bBase0 + ko);
            LDSM_X4(bl[0], bl[1], bl[2], bl[3], blBase0 + ko);
            #pragma unroll
            for (int mi = 0; mi < 2; mi++)
            #pragma unroll
            for (int ni = 0; ni < 2; ni++) {
                mma_bf16(c[mi][ni], ah[mi], &bh[ni * 2]);
                mma_bf16(c[mi][ni], al[mi], &bh[ni * 2]);
                mma_bf16(c[mi][ni], ah[mi], &bl[ni * 2]);
            }
        }
        #pragma unroll
        for (int mi = 0; mi < 2; mi++)
        #pragma unroll
        for (int ci = 0; ci < 2; ci++) {
            int row = 16 * mi + 8 * ci + (lane >> 2);
            size_t base = (size_t)(b0 + row) * 256 + 128;
            #pragma unroll
            for (int ni = 0; ni < 2; ni++) {
                int col = 16 * wc + 8 * ni + 2 * (lane & 3);
                float t0 = tanhf(c[mi][ni][2 * ci]     + projB[col]);
                float t1 = tanhf(c[mi][ni][2 * ci + 1] + projB[col + 1]);
                __nv_bfloat16 h0 = __float2bfloat16(t0);
                __nv_bfloat16 h1 = __float2bfloat16(t1);
                g_xh[base + col]     = h0;
                g_xl[base + col]     = __float2bfloat16(t0 - __bfloat162float(h0));
                g_xh[base + col + 1] = h1;
                g_xl[base + col + 1] = __float2bfloat16(t1 - __bfloat162float(h1));
            }
        }
    }
}

// =====================================================================
// Kernel 2: MLP (unchanged)
// =====================================================================
__global__ void __launch_bounds__(NT2, 1)
k_mlp(const float* __restrict__ b1, const float* __restrict__ b2,
      const float* __restrict__ Wo, const float* __restrict__ bo,
      float* __restrict__ out)
{
    extern __shared__ float sm[];
    char* smc = (char*)sm;
    const uint32_t smb = smem_u32(sm);

    const int tid  = threadIdx.x;
    const int wid  = tid >> 5;
    const int lane = tid & 31;
    const int b0   = blockIdx.x * R2;
    const int wr = wid >> 3, wc = wid & 7;
    const int lt = lane >> 3, lw = lane & 7;

    for (int i = tid; i < 128 * 32; i += NT2) {
        int row = i >> 5, q = i & 31;
        int ch = q >> 3, qq = q & 7;
        size_t src = (size_t)(b0 + row) * 32 + q;
        uint32_t dst = (uint32_t)(ch * XCH + row * XSTRB + qq * 16);
        *(uint4*)(smc + M_XH + dst) = ((const uint4*)g_xh)[src];
        *(uint4*)(smc + M_XL + dst) = ((const uint4*)g_xl)[src];
    }

    const uint32_t aoff = (uint32_t)(((lt & 1) * 8 + lw) * XSTRB + (lt >> 1) * 16);
    const uint32_t boff = (uint32_t)((32 * wc + (lt >> 1) * 8 + lw) * XSTRB + (lt & 1) * 16);
    const uint32_t bB0 = smb + M_WH + boff;
    const uint32_t bB1 = bB0 + 16 * XSTRB;
    const uint32_t bL0 = bB0 + (M_WL - M_WH);
    const uint32_t bL1 = bB1 + (M_WL - M_WH);

    for (int layer = 0; layer < 2; layer++) {
        const float* bias = layer ? b2 : b1;

        float c[4][4][4];
        #pragma unroll
        for (int mi = 0; mi < 4; mi++)
        #pragma unroll
        for (int ni = 0; ni < 4; ni++)
        #pragma unroll
        for (int j = 0; j < 4; j++) c[mi][ni][j] = 0.f;

        for (int kk = 0; kk < 4; kk++) {
            {
                const uint4* WH = (const uint4*)(layer ? gW2Hi[kk] : gW1Hi[kk]);
                const uint4* WL = (const uint4*)(layer ? gW2Lo[kk] : gW1Lo[kk]);
                for (int i = tid; i < 2304; i += NT2) {
                    ((uint4*)(smc + M_WH))[i] = WH[i];
                    ((uint4*)(smc + M_WL))[i] = WL[i];
                }
            }
            __syncthreads();

            const uint32_t aChunk = smb + M_XH + (uint32_t)(kk * XCH)
                                  + (uint32_t)(64 * wr) * XSTRB + aoff;
            #pragma unroll
            for (int ks = 0; ks < 4; ks++) {
                const uint32_t ko = ks * 32;
                uint32_t af[4][4], bh[2][4], bl[2][4];
                #pragma unroll
                for (int m = 0; m < 4; m++)
                    LDSM_X4(af[m][0], af[m][1], af[m][2], af[m][3],
                            aChunk + (uint32_t)(16 * m) * XSTRB + ko);
                LDSM_X4(bh[0][0], bh[0][1], bh[0][2], bh[0][3], bB0 + ko);
                LDSM_X4(bh[1][0], bh[1][1], bh[1][2], bh[1][3], bB1 + ko);
                LDSM_X4(bl[0][0], bl[0][1], bl[0][2], bl[0][3], bL0 + ko);
                LDSM_X4(bl[1][0], bl[1][1], bl[1][2], bl[1][3], bL1 + ko);

                #pragma unroll
                for (int mi = 0; mi < 4; mi++)
                #pragma unroll
                for (int ni = 0; ni < 4; ni++) {
                    const uint32_t* bfh = &bh[ni >> 1][(ni & 1) * 2];
                    const uint32_t* bfl = &bl[ni >> 1][(ni & 1) * 2];
                    mma_bf16(c[mi][ni], af[mi], bfh);
                    mma_bf16(c[mi][ni], af[mi], bfl);
                }
                #pragma unroll
                for (int m = 0; m < 4; m++)
                    LDSM_X4(af[m][0], af[m][1], af[m][2], af[m][3],
                            aChunk + (M_XL - M_XH) + (uint32_t)(16 * m) * XSTRB + ko);
                #pragma unroll
                for (int mi = 0; mi < 4; mi++)
                #pragma unroll
                for (int ni = 0; ni < 4; ni++) {
                    const uint32_t* bfh = &bh[ni >> 1][(ni & 1) * 2];
                    mma_bf16(c[mi][ni], af[mi], bfh);
                }
            }
            __syncthreads();
        }

        const int chn = wc >> 1;
        #pragma unroll
        for (int mi = 0; mi < 4; mi++)
        #pragma unroll
        for (int ci = 0; ci < 2; ci++) {
            int row = 64 * wr + 16 * mi + 8 * ci + (lane >> 2);
            #pragma unroll
            for (int ni = 0; ni < 4; ni++) {
                int col = 32 * wc + 8 * ni + 2 * (lane & 3);
                int colin = (wc & 1) * 32 + 8 * ni + 2 * (lane & 3);
                float x0 = lrelu(c[mi][ni][2 * ci]     + bias[col]);
                float x1 = lrelu(c[mi][ni][2 * ci + 1] + bias[col + 1]);
                float h0 = __bfloat162float(__float2bfloat16(x0));
                float h1 = __bfloat162float(__float2bfloat16(x1));
                uint32_t off = (uint32_t)(chn * XCH + row * XSTRB + colin * 2);
                *(uint32_t*)(smc + M_XH + off) = bf16pair(h0, h1);
                *(uint32_t*)(smc + M_XL + off) = bf16pair(x0 - h0, x1 - h1);
            }
        }
        __syncthreads();
    }

    {
        float bo0 = bo[0], bo1 = bo[1];
        const int chn = lane >> 3;
        const int colin0 = (lane & 7) * 8;
        #pragma unroll
        for (int rr = 0; rr < 8; rr++) {
            int r = wid * 8 + rr;
            uint32_t off = (uint32_t)(chn * XCH + r * XSTRB + colin0 * 2);
            float a0 = 0.f, a1 = 0.f;
            #pragma unroll
            for (int kp = 0; kp < 4; kp++) {
                uint32_t uh = *(const uint32_t*)(smc + M_XH + off + kp * 4);
                uint32_t ul = *(const uint32_t*)(smc + M_XL + off + kp * 4);
                __nv_bfloat162 vh = *(__nv_bfloat162*)&uh;
                __nv_bfloat162 vl = *(__nv_bfloat162*)&ul;
                float x0 = __bfloat162float(vh.x) + __bfloat162float(vl.x);
                float x1 = __bfloat162float(vh.y) + __bfloat162float(vl.y);
                int col = lane * 8 + 2 * kp;
                float2 w0 = ((const float2*)Wo)[col];
                float2 w1 = ((const float2*)Wo)[col + 1];
                a0 += x0 * w0.x + x1 * w1.x;
                a1 += x0 * w0.y + x1 * w1.y;
            }
            #pragma unroll
            for (int o = 16; o > 0; o >>= 1) {
                a0 += __shfl_xor_sync(0xffffffffu, a0, o);
                a1 += __shfl_xor_sync(0xffffffffu, a1, o);
            }
            if (lane == 0) {
                out[(size_t)(b0 + r) * 2 + 0] = a0 + bo0;
                out[(size_t)(b0 + r) * 2 + 1] = a1 + bo1;
            }
        }
    }
}

extern "C" void kernel_launch(void* const* d_in, const int* in_sizes, int n_in,
                              void* d_out, int out_size)
{
    const float* obs   = (const float*)d_in[0];
    const float* ownW  = (const float*)d_in[1];
    const float* ownB  = (const float*)d_in[2];
    const float* intW  = (const float*)d_in[3];
    const float* intB  = (const float*)d_in[4];
    const float* Wq    = (const float*)d_in[5];
    const float* Wk    = (const float*)d_in[6];
    const float* Wv    = (const float*)d_in[7];
    const float* vatt  = (const float*)d_in[8];
    const float* projW = (const float*)d_in[9];
    const float* projB = (const float*)d_in[10];
    const float* W1    = (const float*)d_in[11];
    const float* b1    = (const float*)d_in[12];
    const float* W2    = (const float*)d_in[13];
    const float* b2    = (const float*)d_in[14];
    const float* Wo    = (const float*)d_in[15];
    const float* bo    = (const float*)d_in[16];
    float* out = (float*)d_out;

    cudaFuncSetAttribute(k_attn, cudaFuncAttributeMaxDynamicSharedMemorySize, SMEM1_BYTES);
    cudaFuncSetAttribute(k_mlp,  cudaFuncAttributeMaxDynamicSharedMemorySize, SMEM2_BYTES);

    k_prep<<<352, 256>>>(Wk, W1, W2, Wq, Wv, projW);
    k_attn<<<B_TOT / R1, NT1, SMEM1_BYTES>>>(obs, ownW, ownB, intW, intB, vatt, projB);
    k_mlp<<<B_TOT / R2, NT2, SMEM2_BYTES>>>(b1, b2, Wo, bo, out);
}

// round 15
// speedup vs baseline: 5.5849x; 1.0534x over previous
#include <cuda_runtime.h>
#include <cuda_bf16.h>
#include <cuda_fp16.h>
#include <math.h>
#include <stdint.h>

#define B_TOT   32768
#define OWN_DIM 3
#define N_INTR  32
#define INT_DIM 7
#define D       128
#define OBS_DIM 227
#define HID     256

#define R1      32
#define R2      128
#define X_STR   260
#define NT1     1024
#define NT2     512

#define ASTR    272
#define TILE_BYTES (128 * ASTR)

#define BY_AHI    1024
#define BY_ALO    (BY_AHI + TILE_BYTES)
#define BY_BHI    (BY_ALO + TILE_BYTES)
#define BY_BLO    (BY_BHI + TILE_BYTES)
#define BY_F32    (BY_BLO + TILE_BYTES)
#define F_OBS   (BY_F32 / 4)
#define F_OWNE  (F_OBS  + R1 * OBS_DIM)
#define F_Q     (F_OWNE + R1 * D)
#define F_SC    (F_Q    + R1 * D)
#define F_AL    (F_SC   + R1 * N_INTR)
#define F_INTW  (F_AL   + R1 * N_INTR)
#define F_OWNW  (F_INTW + INT_DIM * D)
#define F_INTB  (F_OWNW + OWN_DIM * D)
#define F_VATT  (F_INTB + D)
#define F_MAP   (F_VATT + D)
#define F_WS    (F_MAP + R1 * N_INTR)
#define F_NC    (F_WS + 32)
#define SMEM1_BYTES ((F_NC + 1) * 4)

#define XSTRB   144
#define XCH     (R2 * XSTRB)
#define M_XH    0
#define M_XL    (4 * XCH)
#define M_WH    (8 * XCH)
#define SMEM2_BYTES (M_WH + 256 * XSTRB)

__device__ uint32_t gWkF[8704];              // Wk fp16
__device__ uint32_t gWqF[8704];              // Wq fp16
__device__ uint32_t gWvpF[8704];             // WvProj fp16
__device__ uint32_t gW1F[4][9216];           // W1 fp16, per-kk images
__device__ uint32_t gW2F[4][9216];           // W2 fp16
__device__ __half g_xh[(size_t)B_TOT * 256];
__device__ __half g_xl[(size_t)B_TOT * 256];

typedef unsigned long long u64;

__device__ __forceinline__ float lrelu(float x) { return fmaxf(x, 0.2f * x); }
__device__ __forceinline__ float tanh_ap(float x) {
    float y; asm("tanh.approx.f32 %0, %1;" : "=f"(y) : "f"(x)); return y;
}
__device__ __forceinline__ uint32_t smem_u32(const void* p) {
    uint32_t a;
    asm("{ .reg .u64 t; cvta.to.shared.u64 t, %1; cvt.u32.u64 %0, t; }" : "=r"(a) : "l"(p));
    return a;
}
__device__ __forceinline__ uint32_t f16pair(float a, float b) {
    __half2 t = __floats2half2_rn(a, b);
    return *(uint32_t*)&t;
}

#define LDSM_X4(r0, r1, r2, r3, addr) \
    asm volatile("ldmatrix.sync.aligned.m8n8.x4.shared.b16 {%0,%1,%2,%3}, [%4];" \
                 : "=r"(r0), "=r"(r1), "=r"(r2), "=r"(r3) : "r"(addr))

__device__ __forceinline__ void mma_f16(float* c, const uint32_t* a, const uint32_t* b) {
    asm volatile(
        "mma.sync.aligned.m16n8k16.row.col.f32.f16.f16.f32 "
        "{%0,%1,%2,%3}, {%4,%5,%6,%7}, {%8,%9}, {%0,%1,%2,%3};"
        : "+f"(c[0]), "+f"(c[1]), "+f"(c[2]), "+f"(c[3])
        : "r"(a[0]), "r"(a[1]), "r"(a[2]), "r"(a[3]), "r"(b[0]), "r"(b[1]));
}

#define GROUP_BAR256(id) \
    asm volatile("bar.sync %0, 256;" :: "r"(id) : "memory")

// =====================================================================
// Prep: ALL weight images single fp16
// =====================================================================
__global__ void __launch_bounds__(256, 4)
k_prep(const float* __restrict__ Wk, const float* __restrict__ W1,
       const float* __restrict__ W2, const float* __restrict__ Wq,
       const float* __restrict__ Wv, const float* __restrict__ projW)
{
    int idx = blockIdx.x * 256 + threadIdx.x;
    if (idx < 2 * 8192) {                       // Wk, Wq: Bn[n][e] fp16 images
        const float* W = (idx < 8192) ? Wk : Wq;
        uint32_t* IF = (idx < 8192) ? gWkF : gWqF;
        int j = idx & 8191;
        int ep = j >> 7, n = j & 127;
        int e0 = 2 * ep;
        IF[n * 68 + ep] = f16pair(W[e0 * D + n], W[(e0 + 1) * D + n]);
    } else if (idx < 2 * 8192 + 2 * 32768) {    // W1, W2 fp16
        int j = idx - 2 * 8192;
        const float* W = (j < 32768) ? W1 : W2;
        uint32_t* WF = (j < 32768) ? &gW1F[0][0] : &gW2F[0][0];
        j &= 32767;
        int kk = j >> 13, r = j & 8191;
        int n = r & 255, kp = r >> 8;
        int k0 = kk * 64 + 2 * kp;
        WF[kk * 9216 + n * 36 + kp] =
            f16pair(W[(size_t)k0 * HID + n], W[(size_t)(k0 + 1) * HID + n]);
    } else if (idx < 2 * 8192 + 2 * 32768 + 8192) {   // WvProj fused, fp16
        int j = idx - (2 * 8192 + 2 * 32768);
        int n = j & 127, f0 = 2 * (j >> 7);
        float s0 = 0.f, s1 = 0.f;
        #pragma unroll 4
        for (int e = 0; e < D; e++) {
            float pc = projW[e * D + n];
            s0 += Wv[f0 * D + e] * pc;
            s1 += Wv[(f0 + 1) * D + e] * pc;
        }
        gWvpF[n * 68 + (f0 >> 1)] = f16pair(s0, s1);
    }
}

// =====================================================================
// Kernel 1: attention, all GEMMs fp16 2-pass (A split hi/lo, B single)
// =====================================================================
__global__ void __launch_bounds__(NT1, 1)
k_attn(const float* __restrict__ obs,
       const float* __restrict__ ownW, const float* __restrict__ ownB,
       const float* __restrict__ intW, const float* __restrict__ intB,
       const float* __restrict__ vatt, const float* __restrict__ projB)
{
    extern __shared__ float sm[];
    char* smc = (char*)sm;
    const uint32_t smb = smem_u32(sm);

    float* sObs  = sm + F_OBS;
    float* sWsum = sm + F_OWNE;
    float* sQ    = sm + F_Q;
    float* sSc   = sm + F_SC;
    float* sAl   = sm + F_AL;
    float* sIntW = sm + F_INTW;
    float* sOwnW = sm + F_OWNW;
    float* sIntB = sm + F_INTB;
    float* sVatt = sm + F_VATT;
    int*   sMap  = (int*)(sm + F_MAP);
    int*   sWs   = (int*)(sm + F_WS);
    int*   sNC   = (int*)(sm + F_NC);

    const int tid  = threadIdx.x;
    const int wid  = tid >> 5;
    const int lane = tid & 31;
    const int b0   = blockIdx.x * R1;
    const float NEG_INF = __int_as_float(0xff800000u);

    const int wr = wid >> 3, wc = wid & 7;
    const int lt = lane >> 3, lw = lane & 7;
    const uint32_t aoff = (uint32_t)(((lt & 1) * 8 + lw) * ASTR + (lt >> 1) * 16);
    const uint32_t boff = (uint32_t)((((lt >> 1) * 8 + lw) + 16 * wc) * ASTR + (lt & 1) * 16);
    const uint32_t aBase0 = smb + BY_AHI + (uint32_t)(32 * wr) * ASTR + aoff;
    const uint32_t aBase1 = aBase0 + 16 * ASTR;
    const uint32_t alBase0 = aBase0 + TILE_BYTES;
    const uint32_t alBase1 = aBase1 + TILE_BYTES;
    const uint32_t bBase0  = smb + BY_BHI + boff;
    const uint32_t aQ0 = smb + BY_AHI + aoff;
    const uint32_t aQ1 = aQ0 + 16 * ASTR;
    const uint32_t aQl0 = aQ0 + TILE_BYTES;
    const uint32_t aQl1 = aQ1 + TILE_BYTES;

    // ---- phase 1: stage obs + small weights + Wq fp16 image ----
    for (int i = tid; i < R1 * OBS_DIM; i += NT1) sObs[i] = obs[(size_t)b0 * OBS_DIM + i];
    for (int i = tid; i < INT_DIM * D; i += NT1)  sIntW[i] = intW[i];
    if (tid < OWN_DIM * D) sOwnW[tid] = ownW[tid];
    if (tid < D) { sIntB[tid] = intB[tid]; sVatt[tid] = vatt[tid]; }
    for (int i = tid; i < 2176; i += NT1)
        ((uint4*)(smc + BY_BHI))[i] = ((const uint4*)gWqF)[i];
    __syncthreads();

    // ---- phase 2: own_e -> A image (fp16 hi/lo) + g_x; pad mask ----
    for (int i = tid; i < R1 * D; i += NT1) {
        int r = i >> 7, d = i & 127;
        const float* o = &sObs[r * OBS_DIM];
        float a = ownB[d] + o[0] * sOwnW[d] + o[1] * sOwnW[D + d] + o[2] * sOwnW[2 * D + d];
        a = lrelu(a);
        __half h = __float2half_rn(a);
        float hf = __half2float(h);
        __half l = __float2half_rn(a - hf);
        uint32_t off = (uint32_t)r * ASTR + (uint32_t)d * 2;
        *(__half*)(smc + BY_AHI + off) = h;
        *(__half*)(smc + BY_ALO + off) = l;
        size_t gi = (size_t)(b0 + r) * 256 + d;
        g_xh[gi] = h;
        g_xl[gi] = l;
    }
    {
        int r = tid >> 5, n = tid & 31;
        const float* p = &sObs[r * OBS_DIM + OWN_DIM + n * INT_DIM];
        float s = 0.f;
        #pragma unroll
        for (int j = 0; j < INT_DIM; j++) s += fabsf(p[j]);
        sSc[tid] = (s < 1e-6f) ? NEG_INF : 0.f;
    }
    __syncthreads();

    // ---- phase 3: q = own_e @ Wq via fp16 2-pass (warps 0-7) ----
    if (wid < 8) {
        float c[2][2][4];
        #pragma unroll
        for (int mi = 0; mi < 2; mi++)
        #pragma unroll
        for (int ni = 0; ni < 2; ni++)
        #pragma unroll
        for (int j = 0; j < 4; j++) c[mi][ni][j] = 0.f;

        #pragma unroll
        for (int kk = 0; kk < 8; kk++) {
            const uint32_t ko = kk * 32;
            uint32_t ah[2][4], al[2][4], bh[4];
            LDSM_X4(ah[0][0], ah[0][1], ah[0][2], ah[0][3], aQ0 + ko);
            LDSM_X4(ah[1][0], ah[1][1], ah[1][2], ah[1][3], aQ1 + ko);
            LDSM_X4(al[0][0], al[0][1], al[0][2], al[0][3], aQl0 + ko);
            LDSM_X4(al[1][0], al[1][1], al[1][2], al[1][3], aQl1 + ko);
            LDSM_X4(bh[0], bh[1], bh[2], bh[3], bBase0 + ko);
            #pragma unroll
            for (int mi = 0; mi < 2; mi++)
            #pragma unroll
            for (int ni = 0; ni < 2; ni++) {
                mma_f16(c[mi][ni], ah[mi], &bh[ni * 2]);
                mma_f16(c[mi][ni], al[mi], &bh[ni * 2]);
            }
        }
        #pragma unroll
        for (int mi = 0; mi < 2; mi++)
        #pragma unroll
        for (int ci = 0; ci < 2; ci++) {
            int row = 16 * mi + 8 * ci + (lane >> 2);
            #pragma unroll
            for (int ni = 0; ni < 2; ni++) {
                int col = 16 * wc + 8 * ni + 2 * (lane & 3);
                sQ[row * D + col]     = c[mi][ni][2 * ci];
                sQ[row * D + col + 1] = c[mi][ni][2 * ci + 1];
            }
        }
    }
    __syncthreads();

    // ---- phase 4: compaction ----
    {
        int flag = (sSc[tid] == 0.f) ? 1 : 0;
        unsigned bal = __ballot_sync(0xffffffffu, flag);
        int wpos = __popc(bal & ((1u << lane) - 1));
        if (lane == 0) sWs[wid] = __popc(bal);
        __syncthreads();
        if (tid == 0) {
            int acc = 0;
            for (int w = 0; w < 32; w++) { int t = sWs[w]; sWs[w] = acc; acc += t; }
            *sNC = acc;
        }
        __syncthreads();
        if (flag) sMap[sWs[wid] + wpos] = tid;
    }

    // ---- phase 5: Wk fp16 image into B ----
    for (int i = tid; i < 2176; i += NT1)
        ((uint4*)(smc + BY_BHI))[i] = ((const uint4*)gWkF)[i];
    __syncthreads();

    const int n_comp = *sNC;
    const int nch = (n_comp + 127) >> 7;

    const int gt = tid & 255;
    const int qd = 4 * (gt & 31);

    // ================= chunk loop: fp16 2-pass =================
    for (int cc = 0; cc < nch; cc++) {
        for (int it = gt; it < 32 * 32; it += 256) {
            int row = 32 * wr + (it >> 5);
            int g = cc * 128 + row;
            uint32_t off = (uint32_t)row * ASTR + (uint32_t)qd * 2;
            if (g < n_comp) {
                int pr = sMap[g];
                const float* p = &sObs[(pr >> 5) * OBS_DIM + OWN_DIM + (pr & 31) * INT_DIM];
                float4 acc = *(const float4*)&sIntB[qd];
                #pragma unroll
                for (int j = 0; j < INT_DIM; j++) {
                    float4 w = *(const float4*)&sIntW[j * D + qd];
                    float pj = p[j];
                    acc.x += pj * w.x; acc.y += pj * w.y;
                    acc.z += pj * w.z; acc.w += pj * w.w;
                }
                float v0 = lrelu(acc.x), v1 = lrelu(acc.y);
                float v2 = lrelu(acc.z), v3 = lrelu(acc.w);
                float h0 = __half2float(__float2half_rn(v0));
                float h1 = __half2float(__float2half_rn(v1));
                float h2 = __half2float(__float2half_rn(v2));
                float h3 = __half2float(__float2half_rn(v3));
                *(uint2*)(smc + BY_AHI + off) =
                    make_uint2(f16pair(h0, h1), f16pair(h2, h3));
                *(uint2*)(smc + BY_ALO + off) =
                    make_uint2(f16pair(v0 - h0, v1 - h1), f16pair(v2 - h2, v3 - h3));
            } else {
                *(uint2*)(smc + BY_AHI + off) = make_uint2(0u, 0u);
                *(uint2*)(smc + BY_ALO + off) = make_uint2(0u, 0u);
            }
        }
        GROUP_BAR256(wr + 1);

        if (cc * 128 + 32 * wr < n_comp) {
            float c[2][2][4];
            #pragma unroll
            for (int mi = 0; mi < 2; mi++)
            #pragma unroll
            for (int ni = 0; ni < 2; ni++)
            #pragma unroll
            for (int j = 0; j < 4; j++) c[mi][ni][j] = 0.f;

            #pragma unroll
            for (int kk = 0; kk < 8; kk++) {
                const uint32_t ko = kk * 32;
                uint32_t ah[2][4], al[2][4], bh[4];
                LDSM_X4(ah[0][0], ah[0][1], ah[0][2], ah[0][3], aBase0 + ko);
                LDSM_X4(ah[1][0], ah[1][1], ah[1][2], ah[1][3], aBase1 + ko);
                LDSM_X4(al[0][0], al[0][1], al[0][2], al[0][3], alBase0 + ko);
                LDSM_X4(al[1][0], al[1][1], al[1][2], al[1][3], alBase1 + ko);
                LDSM_X4(bh[0], bh[1], bh[2], bh[3], bBase0 + ko);
                #pragma unroll
                for (int mi = 0; mi < 2; mi++)
                #pragma unroll
                for (int ni = 0; ni < 2; ni++) {
                    mma_f16(c[mi][ni], ah[mi], &bh[ni * 2]);
                    mma_f16(c[mi][ni], al[mi], &bh[ni * 2]);
                }
            }

            float2 vv[2];
            #pragma unroll
            for (int ni = 0; ni < 2; ni++)
                vv[ni] = ((const float2*)sVatt)[8 * wc + 4 * ni + (lane & 3)];
            #pragma unroll
            for (int mi = 0; mi < 2; mi++)
            #pragma unroll
            for (int ci = 0; ci < 2; ci++) {
                int crow = 32 * wr + 16 * mi + 8 * ci + (lane >> 2);
                int g = cc * 128 + crow;
                bool ok = (g < n_comp);
                int pr = ok ? sMap[g] : 0;
                const float2* qr2 = (const float2*)&sQ[(pr >> 5) * D];
                float s = 0.f;
                #pragma unroll
                for (int ni = 0; ni < 2; ni++) {
                    float2 qv = qr2[8 * wc + 4 * ni + (lane & 3)];
                    s += tanh_ap(qv.x + c[mi][ni][2 * ci])     * vv[ni].x;
                    s += tanh_ap(qv.y + c[mi][ni][2 * ci + 1]) * vv[ni].y;
                }
                s += __shfl_xor_sync(0xffffffffu, s, 1);
                s += __shfl_xor_sync(0xffffffffu, s, 2);
                if (ok && (lane & 3) == 0) atomicAdd(&sSc[pr], s);
            }
        }
        GROUP_BAR256(wr + 1);
    }
    __syncthreads();

    // ---- softmax ----
    {
        int r = wid;
        float s = sSc[r * N_INTR + lane];
        float m = s;
        #pragma unroll
        for (int o = 16; o > 0; o >>= 1) m = fmaxf(m, __shfl_xor_sync(0xffffffffu, m, o));
        float e = (m == NEG_INF) ? 0.f : __expf(s - m);
        float sum = e;
        #pragma unroll
        for (int o = 16; o > 0; o >>= 1) sum += __shfl_xor_sync(0xffffffffu, sum, o);
        sAl[r * N_INTR + lane] = (sum > 0.f) ? (e / sum) : 0.f;
    }
    __syncthreads();

    // ---- wsum = alpha @ int_e ----
    {
        int r = wid;
        float wIW[INT_DIM][4];
        float wB[4];
        #pragma unroll
        for (int cq = 0; cq < 4; cq++) {
            wB[cq] = sIntB[4 * lane + cq];
            #pragma unroll
            for (int j = 0; j < INT_DIM; j++) wIW[j][cq] = sIntW[j * D + 4 * lane + cq];
        }
        float ws[4] = {0.f,0.f,0.f,0.f};
        for (int n = 0; n < N_INTR; n++) {
            float al = sAl[r * N_INTR + n];
            if (al != 0.f) {
                const float* p = &sObs[r * OBS_DIM + OWN_DIM + n * INT_DIM];
                float pj[INT_DIM];
                #pragma unroll
                for (int j = 0; j < INT_DIM; j++) pj[j] = p[j];
                #pragma unroll
                for (int cq = 0; cq < 4; cq++) {
                    float pre = wB[cq];
                    #pragma unroll
                    for (int j = 0; j < INT_DIM; j++) pre += pj[j] * wIW[j][cq];
                    ws[cq] += al * lrelu(pre);
                }
            }
        }
        #pragma unroll
        for (int cq = 0; cq < 4; cq++) sWsum[r * D + 4 * lane + cq] = ws[cq];
    }
    __syncthreads();

    // ---- split wsum (fp16 hi/lo) into A image; WvProj fp16 into B ----
    for (int i = tid; i < R1 * D; i += NT1) {
        int r = i >> 7, d = i & 127;
        float v = sWsum[i];
        __half h = __float2half_rn(v);
        uint32_t off = (uint32_t)r * ASTR + (uint32_t)d * 2;
        *(__half*)(smc + BY_AHI + off) = h;
        *(__half*)(smc + BY_ALO + off) = __float2half_rn(v - __half2float(h));
    }
    for (int i = tid; i < 2176; i += NT1)
        ((uint4*)(smc + BY_BHI))[i] = ((const uint4*)gWvpF)[i];
    __syncthreads();

    // ---- attn_vec = tanh(wsum @ WvProj + projB) via fp16 2-pass ----
    if (wid < 8) {
        float c[2][2][4];
        #pragma unroll
        for (int mi = 0; mi < 2; mi++)
        #pragma unroll
        for (int ni = 0; ni < 2; ni++)
        #pragma unroll
        for (int j = 0; j < 4; j++) c[mi][ni][j] = 0.f;

        #pragma unroll
        for (int kk = 0; kk < 8; kk++) {
            const uint32_t ko = kk * 32;
            uint32_t ah[2][4], al[2][4], bh[4];
            LDSM_X4(ah[0][0], ah[0][1], ah[0][2], ah[0][3], aQ0 + ko);
            LDSM_X4(ah[1][0], ah[1][1], ah[1][2], ah[1][3], aQ1 + ko);
            LDSM_X4(al[0][0], al[0][1], al[0][2], al[0][3], aQl0 + ko);
            LDSM_X4(al[1][0], al[1][1], al[1][2], al[1][3], aQl1 + ko);
            LDSM_X4(bh[0], bh[1], bh[2], bh[3], bBase0 + ko);
            #pragma unroll
            for (int mi = 0; mi < 2; mi++)
            #pragma unroll
            for (int ni = 0; ni < 2; ni++) {
                mma_f16(c[mi][ni], ah[mi], &bh[ni * 2]);
                mma_f16(c[mi][ni], al[mi], &bh[ni * 2]);
            }
        }
        #pragma unroll
        for (int mi = 0; mi < 2; mi++)
        #pragma unroll
        for (int ci = 0; ci < 2; ci++) {
            int row = 16 * mi + 8 * ci + (lane >> 2);
            size_t base = (size_t)(b0 + row) * 256 + 128;
            #pragma unroll
            for (int ni = 0; ni < 2; ni++) {
                int col = 16 * wc + 8 * ni + 2 * (lane & 3);
                float t0 = tanhf(c[mi][ni][2 * ci]     + projB[col]);
                float t1 = tanhf(c[mi][ni][2 * ci + 1] + projB[col + 1]);
                __half h0 = __float2half_rn(t0);
                __half h1 = __float2half_rn(t1);
                g_xh[base + col]     = h0;
                g_xl[base + col]     = __float2half_rn(t0 - __half2float(h0));
                g_xh[base + col + 1] = h1;
                g_xl[base + col + 1] = __float2half_rn(t1 - __half2float(h1));
            }
        }
    }
}

// =====================================================================
// Kernel 2: MLP, fp16 2-pass (X split hi/lo, W single)
// =====================================================================
__global__ void __launch_bounds__(NT2, 1)
k_mlp(const float* __restrict__ b1, const float* __restrict__ b2,
      const float* __restrict__ Wo, const float* __restrict__ bo,
      float* __restrict__ out)
{
    extern __shared__ float sm[];
    char* smc = (char*)sm;
    const uint32_t smb = smem_u32(sm);

    const int tid  = threadIdx.x;
    const int wid  = tid >> 5;
    const int lane = tid & 31;
    const int b0   = blockIdx.x * R2;
    const int wr = wid >> 3, wc = wid & 7;
    const int lt = lane >> 3, lw = lane & 7;

    for (int i = tid; i < 128 * 32; i += NT2) {
        int row = i >> 5, q = i & 31;
        int ch = q >> 3, qq = q & 7;
        size_t src = (size_t)(b0 + row) * 32 + q;
        uint32_t dst = (uint32_t)(ch * XCH + row * XSTRB + qq * 16);
        *(uint4*)(smc + M_XH + dst) = ((const uint4*)g_xh)[src];
        *(uint4*)(smc + M_XL + dst) = ((const uint4*)g_xl)[src];
    }

    const uint32_t aoff = (uint32_t)(((lt & 1) * 8 + lw) * XSTRB + (lt >> 1) * 16);
    const uint32_t boff = (uint32_t)((32 * wc + (lt >> 1) * 8 + lw) * XSTRB + (lt & 1) * 16);
    const uint32_t bB0 = smb + M_WH + boff;
    const uint32_t bB1 = bB0 + 16 * XSTRB;

    for (int layer = 0; layer < 2; layer++) {
        const float* bias = layer ? b2 : b1;

        float c[4][4][4];
        #pragma unroll
        for (int mi = 0; mi < 4; mi++)
        #pragma unroll
        for (int ni = 0; ni < 4; ni++)
        #pragma unroll
        for (int j = 0; j < 4; j++) c[mi][ni][j] = 0.f;

        for (int kk = 0; kk < 4; kk++) {
            {
                const uint4* WF = (const uint4*)(layer ? gW2F[kk] : gW1F[kk]);
                for (int i = tid; i < 2304; i += NT2)
                    ((uint4*)(smc + M_WH))[i] = WF[i];
            }
            __syncthreads();

            const uint32_t aChunk = smb + M_XH + (uint32_t)(kk * XCH)
                                  + (uint32_t)(64 * wr) * XSTRB + aoff;
            #pragma unroll
            for (int ks = 0; ks < 4; ks++) {
                const uint32_t ko = ks * 32;
                uint32_t af[4][4], bh[2][4];
                #pragma unroll
                for (int m = 0; m < 4; m++)
                    LDSM_X4(af[m][0], af[m][1], af[m][2], af[m][3],
                            aChunk + (uint32_t)(16 * m) * XSTRB + ko);
                LDSM_X4(bh[0][0], bh[0][1], bh[0][2], bh[0][3], bB0 + ko);
                LDSM_X4(bh[1][0], bh[1][1], bh[1][2], bh[1][3], bB1 + ko);

                #pragma unroll
                for (int mi = 0; mi < 4; mi++)
                #pragma unroll
                for (int ni = 0; ni < 4; ni++)
                    mma_f16(c[mi][ni], af[mi], &bh[ni >> 1][(ni & 1) * 2]);

                #pragma unroll
                for (int m = 0; m < 4; m++)
                    LDSM_X4(af[m][0], af[m][1], af[m][2], af[m][3],
                            aChunk + (M_XL - M_XH) + (uint32_t)(16 * m) * XSTRB + ko);
                #pragma unroll
                for (int mi = 0; mi < 4; mi++)
                #pragma unroll
                for (int ni = 0; ni < 4; ni++)
                    mma_f16(c[mi][ni], af[mi], &bh[ni >> 1][(ni & 1) * 2]);
            }
            __syncthreads();
        }

        const int chn = wc >> 1;
        #pragma unroll
        for (int mi = 0; mi < 4; mi++)
        #pragma unroll
        for (int ci = 0; ci < 2; ci++) {
            int row = 64 * wr + 16 * mi + 8 * ci + (lane >> 2);
            #pragma unroll
            for (int ni = 0; ni < 4; ni++) {
                int col = 32 * wc + 8 * ni + 2 * (lane & 3);
                int colin = (wc & 1) * 32 + 8 * ni + 2 * (lane & 3);
                float x0 = lrelu(c[mi][ni][2 * ci]     + bias[col]);
                float x1 = lrelu(c[mi][ni][2 * ci + 1] + bias[col + 1]);
                float h0 = __half2float(__float2half_rn(x0));
                float h1 = __half2float(__float2half_rn(x1));
                uint32_t off = (uint32_t)(chn * XCH + row * XSTRB + colin * 2);
                *(uint32_t*)(smc + M_XH + off) = f16pair(h0, h1);
                *(uint32_t*)(smc + M_XL + off) = f16pair(x0 - h0, x1 - h1);
            }
        }
        __syncthreads();
    }

    {
        float bo0 = bo[0], bo1 = bo[1];
        const int chn = lane >> 3;
        const int colin0 = (lane & 7) * 8;
        #pragma unroll
        for (int rr = 0; rr < 8; rr++) {
            int r = wid * 8 + rr;
            uint32_t off = (uint32_t)(chn * XCH + r * XSTRB + colin0 * 2);
            float a0 = 0.f, a1 = 0.f;
            #pragma unroll
            for (int kp = 0; kp < 4; kp++) {
                uint32_t uh = *(const uint32_t*)(smc + M_XH + off + kp * 4);
                uint32_t ul = *(const uint32_t*)(smc + M_XL + off + kp * 4);
                __half2 vh = *(__half2*)&uh;
                __half2 vl = *(__half2*)&ul;
                float x0 = __half2float(vh.x) + __half2float(vl.x);
                float x1 = __half2float(vh.y) + __half2float(vl.y);
                int col = lane * 8 + 2 * kp;
                float2 w0 = ((const float2*)Wo)[col];
                float2 w1 = ((const float2*)Wo)[col + 1];
                a0 += x0 * w0.x + x1 * w1.x;
                a1 += x0 * w0.y + x1 * w1.y;
            }
            #pragma unroll
            for (int o = 16; o > 0; o >>= 1) {
                a0 += __shfl_xor_sync(0xffffffffu, a0, o);
                a1 += __shfl_xor_sync(0xffffffffu, a1, o);
            }
            if (lane == 0) {
                out[(size_t)(b0 + r) * 2 + 0] = a0 + bo0;
                out[(size_t)(b0 + r) * 2 + 1] = a1 + bo1;
            }
        }
    }
}

extern "C" void kernel_launch(void* const* d_in, const int* in_sizes, int n_in,
                              void* d_out, int out_size)
{
    const float* obs   = (const float*)d_in[0];
    const float* ownW  = (const float*)d_in[1];
    const float* ownB  = (const float*)d_in[2];
    const float* intW  = (const float*)d_in[3];
    const float* intB  = (const float*)d_in[4];
    const float* Wq    = (const float*)d_in[5];
    const float* Wk    = (const float*)d_in[6];
    const float* Wv    = (const float*)d_in[7];
    const float* vatt  = (const float*)d_in[8];
    const float* projW = (const float*)d_in[9];
    const float* projB = (const float*)d_in[10];
    const float* W1    = (const float*)d_in[11];
    const float* b1    = (const float*)d_in[12];
    const float* W2    = (const float*)d_in[13];
    const float* b2    = (const float*)d_in[14];
    const float* Wo    = (const float*)d_in[15];
    const float* bo    = (const float*)d_in[16];
    float* out = (float*)d_out;

    cudaFuncSetAttribute(k_attn, cudaFuncAttributeMaxDynamicSharedMemorySize, SMEM1_BYTES);
    cudaFuncSetAttribute(k_mlp,  cudaFuncAttributeMaxDynamicSharedMemorySize, SMEM2_BYTES);

    k_prep<<<352, 256>>>(Wk, W1, W2, Wq, Wv, projW);
    k_attn<<<B_TOT / R1, NT1, SMEM1_BYTES>>>(obs, ownW, ownB, intW, intB, vatt, projB);
    k_mlp<<<B_TOT / R2, NT2, SMEM2_BYTES>>>(b1, b2, Wo, bo, out);
}

// round 16
// speedup vs baseline: 6.2928x; 1.1268x over previous
#include <cuda_runtime.h>
#include <cuda_bf16.h>
#include <cuda_fp16.h>
#include <math.h>
#include <stdint.h>

#define B_TOT   32768
#define OWN_DIM 3
#define N_INTR  32
#define INT_DIM 7
#define D       128
#define OBS_DIM 227
#define HID     256

#define R1      32
#define R2      128
#define X_STR   260
#define NT1     1024
#define NT2     512

#define ASTR    272
#define TILE_BYTES (128 * ASTR)

#define BY_AHI    1024
#define BY_ALO    (BY_AHI + TILE_BYTES)
#define BY_BHI    (BY_ALO + TILE_BYTES)
#define BY_BLO    (BY_BHI + TILE_BYTES)
#define BY_F32    (BY_BLO + TILE_BYTES)
#define F_OBS   (BY_F32 / 4)
#define F_OWNE  (F_OBS  + R1 * OBS_DIM)
#define F_Q     (F_OWNE + R1 * D)
#define F_SC    (F_Q    + R1 * D)
#define F_AL    (F_SC   + R1 * N_INTR)
#define F_INTW  (F_AL   + R1 * N_INTR)
#define F_OWNW  (F_INTW + INT_DIM * D)
#define F_INTB  (F_OWNW + OWN_DIM * D)
#define F_VATT  (F_INTB + D)
#define F_MAP   (F_VATT + D)
#define F_WS    (F_MAP + R1 * N_INTR)
#define F_NC    (F_WS + 32)
#define SMEM1_BYTES ((F_NC + 1) * 4)

#define XSTRB   144
#define XCH     (R2 * XSTRB)
#define M_XH    0
#define M_XL    (4 * XCH)
#define M_W0    (8 * XCH)            // 147456
#define WBUF    36864                // one fp16 W chunk image
#define SMEM2_BYTES (M_W0 + 2 * WBUF) // 221184 (R11-proven size)

__device__ uint32_t gWkF[8704];
__device__ uint32_t gWqF[8704];
__device__ uint32_t gWvpF[8704];
__device__ uint32_t gW1F[4][9216];
__device__ uint32_t gW2F[4][9216];
__device__ __half g_xh[(size_t)B_TOT * 256];
__device__ __half g_xl[(size_t)B_TOT * 256];

typedef unsigned long long u64;

__device__ __forceinline__ float lrelu(float x) { return fmaxf(x, 0.2f * x); }
__device__ __forceinline__ float tanh_ap(float x) {
    float y; asm("tanh.approx.f32 %0, %1;" : "=f"(y) : "f"(x)); return y;
}
__device__ __forceinline__ uint32_t smem_u32(const void* p) {
    uint32_t a;
    asm("{ .reg .u64 t; cvta.to.shared.u64 t, %1; cvt.u32.u64 %0, t; }" : "=r"(a) : "l"(p));
    return a;
}
__device__ __forceinline__ uint32_t f16pair(float a, float b) {
    __half2 t = __floats2half2_rn(a, b);
    return *(uint32_t*)&t;
}

#define LDSM_X4(r0, r1, r2, r3, addr) \
    asm volatile("ldmatrix.sync.aligned.m8n8.x4.shared.b16 {%0,%1,%2,%3}, [%4];" \
                 : "=r"(r0), "=r"(r1), "=r"(r2), "=r"(r3) : "r"(addr))

__device__ __forceinline__ void mma_f16(float* c, const uint32_t* a, const uint32_t* b) {
    asm volatile(
        "mma.sync.aligned.m16n8k16.row.col.f32.f16.f16.f32 "
        "{%0,%1,%2,%3}, {%4,%5,%6,%7}, {%8,%9}, {%0,%1,%2,%3};"
        : "+f"(c[0]), "+f"(c[1]), "+f"(c[2]), "+f"(c[3])
        : "r"(a[0]), "r"(a[1]), "r"(a[2]), "r"(a[3]), "r"(b[0]), "r"(b[1]));
}

#define GROUP_BAR256(id) \
    asm volatile("bar.sync %0, 256;" :: "r"(id) : "memory")
#define CP_ASYNC16(dst, src) \
    asm volatile("cp.async.ca.shared.global [%0], [%1], 16;" :: "r"(dst), "l"(src))
#define CP_COMMIT() asm volatile("cp.async.commit_group;" ::: "memory")
#define CP_WAIT0()  asm volatile("cp.async.wait_group 0;" ::: "memory")

// =====================================================================
// Prep: ALL weight images single fp16 (unchanged from R15)
// =====================================================================
__global__ void __launch_bounds__(256, 4)
k_prep(const float* __restrict__ Wk, const float* __restrict__ W1,
       const float* __restrict__ W2, const float* __restrict__ Wq,
       const float* __restrict__ Wv, const float* __restrict__ projW)
{
    int idx = blockIdx.x * 256 + threadIdx.x;
    if (idx < 2 * 8192) {
        const float* W = (idx < 8192) ? Wk : Wq;
        uint32_t* IF = (idx < 8192) ? gWkF : gWqF;
        int j = idx & 8191;
        int ep = j >> 7, n = j & 127;
        int e0 = 2 * ep;
        IF[n * 68 + ep] = f16pair(W[e0 * D + n], W[(e0 + 1) * D + n]);
    } else if (idx < 2 * 8192 + 2 * 32768) {
        int j = idx - 2 * 8192;
        const float* W = (j < 32768) ? W1 : W2;
        uint32_t* WF = (j < 32768) ? &gW1F[0][0] : &gW2F[0][0];
        j &= 32767;
        int kk = j >> 13, r = j & 8191;
        int n = r & 255, kp = r >> 8;
        int k0 = kk * 64 + 2 * kp;
        WF[kk * 9216 + n * 36 + kp] =
            f16pair(W[(size_t)k0 * HID + n], W[(size_t)(k0 + 1) * HID + n]);
    } else if (idx < 2 * 8192 + 2 * 32768 + 8192) {
        int j = idx - (2 * 8192 + 2 * 32768);
        int n = j & 127, f0 = 2 * (j >> 7);
        float s0 = 0.f, s1 = 0.f;
        #pragma unroll 4
        for (int e = 0; e < D; e++) {
            float pc = projW[e * D + n];
            s0 += Wv[f0 * D + e] * pc;
            s1 += Wv[(f0 + 1) * D + e] * pc;
        }
        gWvpF[n * 68 + (f0 >> 1)] = f16pair(s0, s1);
    }
}

// =====================================================================
// Kernel 1: attention (R15 + per-chunk build-weight hoist)
// =====================================================================
__global__ void __launch_bounds__(NT1, 1)
k_attn(const float* __restrict__ obs,
       const float* __restrict__ ownW, const float* __restrict__ ownB,
       const float* __restrict__ intW, const float* __restrict__ intB,
       const float* __restrict__ vatt, const float* __restrict__ projB)
{
    extern __shared__ float sm[];
    char* smc = (char*)sm;
    const uint32_t smb = smem_u32(sm);

    float* sObs  = sm + F_OBS;
    float* sWsum = sm + F_OWNE;
    float* sQ    = sm + F_Q;
    float* sSc   = sm + F_SC;
    float* sAl   = sm + F_AL;
    float* sIntW = sm + F_INTW;
    float* sOwnW = sm + F_OWNW;
    float* sIntB = sm + F_INTB;
    float* sVatt = sm + F_VATT;
    int*   sMap  = (int*)(sm + F_MAP);
    int*   sWs   = (int*)(sm + F_WS);
    int*   sNC   = (int*)(sm + F_NC);

    const int tid  = threadIdx.x;
    const int wid  = tid >> 5;
    const int lane = tid & 31;
    const int b0   = blockIdx.x * R1;
    const float NEG_INF = __int_as_float(0xff800000u);

    const int wr = wid >> 3, wc = wid & 7;
    const int lt = lane >> 3, lw = lane & 7;
    const uint32_t aoff = (uint32_t)(((lt & 1) * 8 + lw) * ASTR + (lt >> 1) * 16);
    const uint32_t boff = (uint32_t)((((lt >> 1) * 8 + lw) + 16 * wc) * ASTR + (lt & 1) * 16);
    const uint32_t aBase0 = smb + BY_AHI + (uint32_t)(32 * wr) * ASTR + aoff;
    const uint32_t aBase1 = aBase0 + 16 * ASTR;
    const uint32_t alBase0 = aBase0 + TILE_BYTES;
    const uint32_t alBase1 = aBase1 + TILE_BYTES;
    const uint32_t bBase0  = smb + BY_BHI + boff;
    const uint32_t aQ0 = smb + BY_AHI + aoff;
    const uint32_t aQ1 = aQ0 + 16 * ASTR;
    const uint32_t aQl0 = aQ0 + TILE_BYTES;
    const uint32_t aQl1 = aQ1 + TILE_BYTES;

    // ---- phase 1 ----
    for (int i = tid; i < R1 * OBS_DIM; i += NT1) sObs[i] = obs[(size_t)b0 * OBS_DIM + i];
    for (int i = tid; i < INT_DIM * D; i += NT1)  sIntW[i] = intW[i];
    if (tid < OWN_DIM * D) sOwnW[tid] = ownW[tid];
    if (tid < D) { sIntB[tid] = intB[tid]; sVatt[tid] = vatt[tid]; }
    for (int i = tid; i < 2176; i += NT1)
        ((uint4*)(smc + BY_BHI))[i] = ((const uint4*)gWqF)[i];
    __syncthreads();

    // ---- phase 2 ----
    for (int i = tid; i < R1 * D; i += NT1) {
        int r = i >> 7, d = i & 127;
        const float* o = &sObs[r * OBS_DIM];
        float a = ownB[d] + o[0] * sOwnW[d] + o[1] * sOwnW[D + d] + o[2] * sOwnW[2 * D + d];
        a = lrelu(a);
        __half h = __float2half_rn(a);
        float hf = __half2float(h);
        __half l = __float2half_rn(a - hf);
        uint32_t off = (uint32_t)r * ASTR + (uint32_t)d * 2;
        *(__half*)(smc + BY_AHI + off) = h;
        *(__half*)(smc + BY_ALO + off) = l;
        size_t gi = (size_t)(b0 + r) * 256 + d;
        g_xh[gi] = h;
        g_xl[gi] = l;
    }
    {
        int r = tid >> 5, n = tid & 31;
        const float* p = &sObs[r * OBS_DIM + OWN_DIM + n * INT_DIM];
        float s = 0.f;
        #pragma unroll
        for (int j = 0; j < INT_DIM; j++) s += fabsf(p[j]);
        sSc[tid] = (s < 1e-6f) ? NEG_INF : 0.f;
    }
    __syncthreads();

    // ---- phase 3: q = own_e @ Wq ----
    if (wid < 8) {
        float c[2][2][4];
        #pragma unroll
        for (int mi = 0; mi < 2; mi++)
        #pragma unroll
        for (int ni = 0; ni < 2; ni++)
        #pragma unroll
        for (int j = 0; j < 4; j++) c[mi][ni][j] = 0.f;

        #pragma unroll
        for (int kk = 0; kk < 8; kk++) {
            const uint32_t ko = kk * 32;
            uint32_t ah[2][4], al[2][4], bh[4];
            LDSM_X4(ah[0][0], ah[0][1], ah[0][2], ah[0][3], aQ0 + ko);
            LDSM_X4(ah[1][0], ah[1][1], ah[1][2], ah[1][3], aQ1 + ko);
            LDSM_X4(al[0][0], al[0][1], al[0][2], al[0][3], aQl0 + ko);
            LDSM_X4(al[1][0], al[1][1], al[1][2], al[1][3], aQl1 + ko);
            LDSM_X4(bh[0], bh[1], bh[2], bh[3], bBase0 + ko);
            #pragma unroll
            for (int mi = 0; mi < 2; mi++)
            #pragma unroll
            for (int ni = 0; ni < 2; ni++) {
                mma_f16(c[mi][ni], ah[mi], &bh[ni * 2]);
                mma_f16(c[mi][ni], al[mi], &bh[ni * 2]);
            }
        }
        #pragma unroll
        for (int mi = 0; mi < 2; mi++)
        #pragma unroll
        for (int ci = 0; ci < 2; ci++) {
            int row = 16 * mi + 8 * ci + (lane >> 2);
            #pragma unroll
            for (int ni = 0; ni < 2; ni++) {
                int col = 16 * wc + 8 * ni + 2 * (lane & 3);
                sQ[row * D + col]     = c[mi][ni][2 * ci];
                sQ[row * D + col + 1] = c[mi][ni][2 * ci + 1];
            }
        }
    }
    __syncthreads();

    // ---- phase 4: compaction ----
    {
        int flag = (sSc[tid] == 0.f) ? 1 : 0;
        unsigned bal = __ballot_sync(0xffffffffu, flag);
        int wpos = __popc(bal & ((1u << lane) - 1));
        if (lane == 0) sWs[wid] = __popc(bal);
        __syncthreads();
        if (tid == 0) {
            int acc = 0;
            for (int w = 0; w < 32; w++) { int t = sWs[w]; sWs[w] = acc; acc += t; }
            *sNC = acc;
        }
        __syncthreads();
        if (flag) sMap[sWs[wid] + wpos] = tid;
    }

    // ---- phase 5: Wk fp16 image ----
    for (int i = tid; i < 2176; i += NT1)
        ((uint4*)(smc + BY_BHI))[i] = ((const uint4*)gWkF)[i];
    __syncthreads();

    const int n_comp = *sNC;
    const int nch = (n_comp + 127) >> 7;

    const int gt = tid & 255;
    const int qd = 4 * (gt & 31);

    // ================= chunk loop =================
    for (int cc = 0; cc < nch; cc++) {
        // hoist build weights once per chunk (regs freed at GROUP_BAR)
        float4 wjv[INT_DIM];
        #pragma unroll
        for (int j = 0; j < INT_DIM; j++) wjv[j] = *(const float4*)&sIntW[j * D + qd];
        const float4 bbv = *(const float4*)&sIntB[qd];

        for (int it = gt; it < 32 * 32; it += 256) {
            int row = 32 * wr + (it >> 5);
            int g = cc * 128 + row;
            uint32_t off = (uint32_t)row * ASTR + (uint32_t)qd * 2;
            if (g < n_comp) {
                int pr = sMap[g];
                const float* p = &sObs[(pr >> 5) * OBS_DIM + OWN_DIM + (pr & 31) * INT_DIM];
                float4 acc = bbv;
                #pragma unroll
                for (int j = 0; j < INT_DIM; j++) {
                    float pj = p[j];
                    acc.x += pj * wjv[j].x; acc.y += pj * wjv[j].y;
                    acc.z += pj * wjv[j].z; acc.w += pj * wjv[j].w;
                }
                float v0 = lrelu(acc.x), v1 = lrelu(acc.y);
                float v2 = lrelu(acc.z), v3 = lrelu(acc.w);
                float h0 = __half2float(__float2half_rn(v0));
                float h1 = __half2float(__float2half_rn(v1));
                float h2 = __half2float(__float2half_rn(v2));
                float h3 = __half2float(__float2half_rn(v3));
                *(uint2*)(smc + BY_AHI + off) =
                    make_uint2(f16pair(h0, h1), f16pair(h2, h3));
                *(uint2*)(smc + BY_ALO + off) =
                    make_uint2(f16pair(v0 - h0, v1 - h1), f16pair(v2 - h2, v3 - h3));
            } else {
                *(uint2*)(smc + BY_AHI + off) = make_uint2(0u, 0u);
                *(uint2*)(smc + BY_ALO + off) = make_uint2(0u, 0u);
            }
        }
        GROUP_BAR256(wr + 1);

        if (cc * 128 + 32 * wr < n_comp) {
            float c[2][2][4];
            #pragma unroll
            for (int mi = 0; mi < 2; mi++)
            #pragma unroll
            for (int ni = 0; ni < 2; ni++)
            #pragma unroll
            for (int j = 0; j < 4; j++) c[mi][ni][j] = 0.f;

            #pragma unroll
            for (int kk = 0; kk < 8; kk++) {
                const uint32_t ko = kk * 32;
                uint32_t ah[2][4], al[2][4], bh[4];
                LDSM_X4(ah[0][0], ah[0][1], ah[0][2], ah[0][3], aBase0 + ko);
                LDSM_X4(ah[1][0], ah[1][1], ah[1][2], ah[1][3], aBase1 + ko);
                LDSM_X4(al[0][0], al[0][1], al[0][2], al[0][3], alBase0 + ko);
                LDSM_X4(al[1][0], al[1][1], al[1][2], al[1][3], alBase1 + ko);
                LDSM_X4(bh[0], bh[1], bh[2], bh[3], bBase0 + ko);
                #pragma unroll
                for (int mi = 0; mi < 2; mi++)
                #pragma unroll
                for (int ni = 0; ni < 2; ni++) {
                    mma_f16(c[mi][ni], ah[mi], &bh[ni * 2]);
                    mma_f16(c[mi][ni], al[mi], &bh[ni * 2]);
                }
            }

            float2 vv[2];
            #pragma unroll
            for (int ni = 0; ni < 2; ni++)
                vv[ni] = ((const float2*)sVatt)[8 * wc + 4 * ni + (lane & 3)];
            #pragma unroll
            for (int mi = 0; mi < 2; mi++)
            #pragma unroll
            for (int ci = 0; ci < 2; ci++) {
                int crow = 32 * wr + 16 * mi + 8 * ci + (lane >> 2);
                int g = cc * 128 + crow;
                bool ok = (g < n_comp);
                int pr = ok ? sMap[g] : 0;
                const float2* qr2 = (const float2*)&sQ[(pr >> 5) * D];
                float s = 0.f;
                #pragma unroll
                for (int ni = 0; ni < 2; ni++) {
                    float2 qv = qr2[8 * wc + 4 * ni + (lane & 3)];
                    s += tanh_ap(qv.x + c[mi][ni][2 * ci])     * vv[ni].x;
                    s += tanh_ap(qv.y + c[mi][ni][2 * ci + 1]) * vv[ni].y;
                }
                s += __shfl_xor_sync(0xffffffffu, s, 1);
                s += __shfl_xor_sync(0xffffffffu, s, 2);
                if (ok && (lane & 3) == 0) atomicAdd(&sSc[pr], s);
            }
        }
        GROUP_BAR256(wr + 1);
    }
    __syncthreads();

    // ---- softmax ----
    {
        int r = wid;
        float s = sSc[r * N_INTR + lane];
        float m = s;
        #pragma unroll
        for (int o = 16; o > 0; o >>= 1) m = fmaxf(m, __shfl_xor_sync(0xffffffffu, m, o));
        float e = (m == NEG_INF) ? 0.f : __expf(s - m);
        float sum = e;
        #pragma unroll
        for (int o = 16; o > 0; o >>= 1) sum += __shfl_xor_sync(0xffffffffu, sum, o);
        sAl[r * N_INTR + lane] = (sum > 0.f) ? (e / sum) : 0.f;
    }
    __syncthreads();

    // ---- wsum = alpha @ int_e ----
    {
        int r = wid;
        float wIW[INT_DIM][4];
        float wB[4];
        #pragma unroll
        for (int cq = 0; cq < 4; cq++) {
            wB[cq] = sIntB[4 * lane + cq];
            #pragma unroll
            for (int j = 0; j < INT_DIM; j++) wIW[j][cq] = sIntW[j * D + 4 * lane + cq];
        }
        float ws[4] = {0.f,0.f,0.f,0.f};
        for (int n = 0; n < N_INTR; n++) {
            float al = sAl[r * N_INTR + n];
            if (al != 0.f) {
                const float* p = &sObs[r * OBS_DIM + OWN_DIM + n * INT_DIM];
                float pj[INT_DIM];
                #pragma unroll
                for (int j = 0; j < INT_DIM; j++) pj[j] = p[j];
                #pragma unroll
                for (int cq = 0; cq < 4; cq++) {
                    float pre = wB[cq];
                    #pragma unroll
                    for (int j = 0; j < INT_DIM; j++) pre += pj[j] * wIW[j][cq];
                    ws[cq] += al * lrelu(pre);
                }
            }
        }
        #pragma unroll
        for (int cq = 0; cq < 4; cq++) sWsum[r * D + 4 * lane + cq] = ws[cq];
    }
    __syncthreads();

    // ---- split wsum; WvProj image ----
    for (int i = tid; i < R1 * D; i += NT1) {
        int r = i >> 7, d = i & 127;
        float v = sWsum[i];
        __half h = __float2half_rn(v);
        uint32_t off = (uint32_t)r * ASTR + (uint32_t)d * 2;
        *(__half*)(smc + BY_AHI + off) = h;
        *(__half*)(smc + BY_ALO + off) = __float2half_rn(v - __half2float(h));
    }
    for (int i = tid; i < 2176; i += NT1)
        ((uint4*)(smc + BY_BHI))[i] = ((const uint4*)gWvpF)[i];
    __syncthreads();

    // ---- attn_vec ----
    if (wid < 8) {
        float c[2][2][4];
        #pragma unroll
        for (int mi = 0; mi < 2; mi++)
        #pragma unroll
        for (int ni = 0; ni < 2; ni++)
        #pragma unroll
        for (int j = 0; j < 4; j++) c[mi][ni][j] = 0.f;

        #pragma unroll
        for (int kk = 0; kk < 8; kk++) {
            const uint32_t ko = kk * 32;
            uint32_t ah[2][4], al[2][4], bh[4];
            LDSM_X4(ah[0][0], ah[0][1], ah[0][2], ah[0][3], aQ0 + ko);
            LDSM_X4(ah[1][0], ah[1][1], ah[1][2], ah[1][3], aQ1 + ko);
            LDSM_X4(al[0][0], al[0][1], al[0][2], al[0][3], aQl0 + ko);
            LDSM_X4(al[1][0], al[1][1], al[1][2], al[1][3], aQl1 + ko);
            LDSM_X4(bh[0], bh[1], bh[2], bh[3], bBase0 + ko);
            #pragma unroll
            for (int mi = 0; mi < 2; mi++)
            #pragma unroll
            for (int ni = 0; ni < 2; ni++) {
                mma_f16(c[mi][ni], ah[mi], &bh[ni * 2]);
                mma_f16(c[mi][ni], al[mi], &bh[ni * 2]);
            }
        }
        #pragma unroll
        for (int mi = 0; mi < 2; mi++)
        #pragma unroll
        for (int ci = 0; ci < 2; ci++) {
            int row = 16 * mi + 8 * ci + (lane >> 2);
            size_t base = (size_t)(b0 + row) * 256 + 128;
            #pragma unroll
            for (int ni = 0; ni < 2; ni++) {
                int col = 16 * wc + 8 * ni + 2 * (lane & 3);
                float t0 = tanhf(c[mi][ni][2 * ci]     + projB[col]);
                float t1 = tanhf(c[mi][ni][2 * ci + 1] + projB[col + 1]);
                __half h0 = __float2half_rn(t0);
                __half h1 = __float2half_rn(t1);
                g_xh[base + col]     = h0;
                g_xl[base + col]     = __float2half_rn(t0 - __half2float(h0));
                g_xh[base + col + 1] = h1;
                g_xl[base + col + 1] = __float2half_rn(t1 - __half2float(h1));
            }
        }
    }
}

// =====================================================================
// Kernel 2: MLP, fp16 2-pass + cp.async double-buffered W staging
// =====================================================================
__global__ void __launch_bounds__(NT2, 1)
k_mlp(const float* __restrict__ b1, const float* __restrict__ b2,
      const float* __restrict__ Wo, const float* __restrict__ bo,
      float* __restrict__ out)
{
    extern __shared__ float sm[];
    char* smc = (char*)sm;
    const uint32_t smb = smem_u32(sm);

    const int tid  = threadIdx.x;
    const int wid  = tid >> 5;
    const int lane = tid & 31;
    const int b0   = blockIdx.x * R2;
    const int wr = wid >> 3, wc = wid & 7;
    const int lt = lane >> 3, lw = lane & 7;

    // stage W chunk li (0..7: layer*4+kk) into buffer li&1 via cp.async
    auto stageW = [&](int li) {
        const uint4* WF = (const uint4*)((li >= 4) ? gW2F[li & 3] : gW1F[li & 3]);
        uint32_t dstb = smb + M_W0 + (uint32_t)(li & 1) * WBUF;
        for (int i = tid; i < 2304; i += NT2)
            CP_ASYNC16(dstb + (uint32_t)i * 16, (const void*)(WF + i));
        CP_COMMIT();
    };

    stageW(0);   // overlap with X staging below

    for (int i = tid; i < 128 * 32; i += NT2) {
        int row = i >> 5, q = i & 31;
        int ch = q >> 3, qq = q & 7;
        size_t src = (size_t)(b0 + row) * 32 + q;
        uint32_t dst = (uint32_t)(ch * XCH + row * XSTRB + qq * 16);
        *(uint4*)(smc + M_XH + dst) = ((const uint4*)g_xh)[src];
        *(uint4*)(smc + M_XL + dst) = ((const uint4*)g_xl)[src];
    }
    CP_WAIT0();
    __syncthreads();

    const uint32_t aoff = (uint32_t)(((lt & 1) * 8 + lw) * XSTRB + (lt >> 1) * 16);
    const uint32_t boff = (uint32_t)((32 * wc + (lt >> 1) * 8 + lw) * XSTRB + (lt & 1) * 16);

    for (int layer = 0; layer < 2; layer++) {
        const float* bias = layer ? b2 : b1;

        float c[4][4][4];
        #pragma unroll
        for (int mi = 0; mi < 4; mi++)
        #pragma unroll
        for (int ni = 0; ni < 4; ni++)
        #pragma unroll
        for (int j = 0; j < 4; j++) c[mi][ni][j] = 0.f;

        for (int kk = 0; kk < 4; kk++) {
            const int li = layer * 4 + kk;
            if (li < 7) stageW(li + 1);     // async prefetch into other buffer

            const uint32_t bB0 = smb + M_W0 + (uint32_t)(li & 1) * WBUF + boff;
            const uint32_t bB1 = bB0 + 16 * XSTRB;
            const uint32_t aChunk = smb + M_XH + (uint32_t)(kk * XCH)
                                  + (uint32_t)(64 * wr) * XSTRB + aoff;
            #pragma unroll
            for (int ks = 0; ks < 4; ks++) {
                const uint32_t ko = ks * 32;
                uint32_t af[4][4], bh[2][4];
                #pragma unroll
                for (int m = 0; m < 4; m++)
                    LDSM_X4(af[m][0], af[m][1], af[m][2], af[m][3],
                            aChunk + (uint32_t)(16 * m) * XSTRB + ko);
                LDSM_X4(bh[0][0], bh[0][1], bh[0][2], bh[0][3], bB0 + ko);
                LDSM_X4(bh[1][0], bh[1][1], bh[1][2], bh[1][3], bB1 + ko);

                #pragma unroll
                for (int mi = 0; mi < 4; mi++)
                #pragma unroll
                for (int ni = 0; ni < 4; ni++)
                    mma_f16(c[mi][ni], af[mi], &bh[ni >> 1][(ni & 1) * 2]);

                #pragma unroll
                for (int m = 0; m < 4; m++)
                    LDSM_X4(af[m][0], af[m][1], af[m][2], af[m][3],
                            aChunk + (M_XL - M_XH) + (uint32_t)(16 * m) * XSTRB + ko);
                #pragma unroll
                for (int mi = 0; mi < 4; mi++)
                #pragma unroll
                for (int ni = 0; ni < 4; ni++)
                    mma_f16(c[mi][ni], af[mi], &bh[ni >> 1][(ni & 1) * 2]);
            }
            CP_WAIT0();
            __syncthreads();
        }

        // epilogue: bias + lrelu -> split-fp16 back into X buffers
        const int chn = wc >> 1;
        #pragma unroll
        for (int mi = 0; mi < 4; mi++)
        #pragma unroll
        for (int ci = 0; ci < 2; ci++) {
            int row = 64 * wr + 16 * mi + 8 * ci + (lane >> 2);
            #pragma unroll
            for (int ni = 0; ni < 4; ni++) {
                int col = 32 * wc + 8 * ni + 2 * (lane & 3);
                int colin = (wc & 1) * 32 + 8 * ni + 2 * (lane & 3);
                float x0 = lrelu(c[mi][ni][2 * ci]     + bias[col]);
                float x1 = lrelu(c[mi][ni][2 * ci + 1] + bias[col + 1]);
                float h0 = __half2float(__float2half_rn(x0));
                float h1 = __half2float(__float2half_rn(x1));
                uint32_t off = (uint32_t)(chn * XCH + row * XSTRB + colin * 2);
                *(uint32_t*)(smc + M_XH + off) = f16pair(h0, h1);
                *(uint32_t*)(smc + M_XL + off) = f16pair(x0 - h0, x1 - h1);
            }
        }
        __syncthreads();
    }

    // out layer: 256 -> 2 from split-fp16 X
    {
        float bo0 = bo[0], bo1 = bo[1];
        const int chn = lane >> 3;
        const int colin0 = (lane & 7) * 8;
        #pragma unroll
        for (int rr = 0; rr < 8; rr++) {
            int r = wid * 8 + rr;
            uint32_t off = (uint32_t)(chn * XCH + r * XSTRB + colin0 * 2);
            float a0 = 0.f, a1 = 0.f;
            #pragma unroll
            for (int kp = 0; kp < 4; kp++) {
                uint32_t uh = *(const uint32_t*)(smc + M_XH + off + kp * 4);
                uint32_t ul = *(const uint32_t*)(smc + M_XL + off + kp * 4);
                __half2 vh = *(__half2*)&uh;
                __half2 vl = *(__half2*)&ul;
                float x0 = __half2float(vh.x) + __half2float(vl.x);
                float x1 = __half2float(vh.y) + __half2float(vl.y);
                int col = lane * 8 + 2 * kp;
                float2 w0 = ((const float2*)Wo)[col];
                float2 w1 = ((const float2*)Wo)[col + 1];
                a0 += x0 * w0.x + x1 * w1.x;
                a1 += x0 * w0.y + x1 * w1.y;
            }
            #pragma unroll
            for (int o = 16; o > 0; o >>= 1) {
                a0 += __shfl_xor_sync(0xffffffffu, a0, o);
                a1 += __shfl_xor_sync(0xffffffffu, a1, o);
            }
            if (lane == 0) {
                out[(size_t)(b0 + r) * 2 + 0] = a0 + bo0;
                out[(size_t)(b0 + r) * 2 + 1] = a1 + bo1;
            }
        }
    }
}

extern "C" void kernel_launch(void* const* d_in, const int* in_sizes, int n_in,
                              void* d_out, int out_size)
{
    const float* obs   = (const float*)d_in[0];
    const float* ownW  = (const float*)d_in[1];
    const float* ownB  = (const float*)d_in[2];
    const float* intW  = (const float*)d_in[3];
    const float* intB  = (const float*)d_in[4];
    const float* Wq    = (const float*)d_in[5];
    const float* Wk    = (const float*)d_in[6];
    const float* Wv    = (const float*)d_in[7];
    const float* vatt  = (const float*)d_in[8];
    const float* projW = (const float*)d_in[9];
    const float* projB = (const float*)d_in[10];
    const float* W1    = (const float*)d_in[11];
    const float* b1    = (const float*)d_in[12];
    const float* W2    = (const float*)d_in[13];
    const float* b2    = (const float*)d_in[14];
    const float* Wo    = (const float*)d_in[15];
    const float* bo    = (const float*)d_in[16];
    float* out = (float*)d_out;

    cudaFuncSetAttribute(k_attn, cudaFuncAttributeMaxDynamicSharedMemorySize, SMEM1_BYTES);
    cudaFuncSetAttribute(k_mlp,  cudaFuncAttributeMaxDynamicSharedMemorySize, SMEM2_BYTES);

    k_prep<<<352, 256>>>(Wk, W1, W2, Wq, Wv, projW);
    k_attn<<<B_TOT / R1, NT1, SMEM1_BYTES>>>(obs, ownW, ownB, intW, intB, vatt, projB);
    k_mlp<<<B_TOT / R2, NT2, SMEM2_BYTES>>>(b1, b2, Wo, bo, out);
}